// round 6
// baseline (speedup 1.0000x reference)
#include <cuda_runtime.h>
#include <cuda_bf16.h>
#include <math.h>
#include <stdint.h>

#define BATCH 2
#define SEQ   2048
#define DIMM  1024
#define HEADS 16
#define DHD   64
#define INNER_ (HEADS*DHD)      // 1024
#define ROWS  (BATCH*SEQ)       // 4096
#define KDIM  1024

// ---------------- scratch (no cudaMalloc allowed) ----------------
__device__ __align__(256) float g_kv[ROWS*2*DHD];                    // [row][k|v]
__device__ __align__(256) __nv_bfloat16 g_qh [ROWS*INNER_];
__device__ __align__(256) __nv_bfloat16 g_ql [ROWS*INNER_];
__device__ __align__(256) __nv_bfloat16 g_kh [BATCH*SEQ*DHD];
__device__ __align__(256) __nv_bfloat16 g_kl [BATCH*SEQ*DHD];
__device__ __align__(256) __nv_bfloat16 g_vth[BATCH*DHD*SEQ];        // transposed V
__device__ __align__(256) __nv_bfloat16 g_vtl[BATCH*DHD*SEQ];
__device__ __align__(256) __nv_bfloat16 g_aoh[ROWS*INNER_];
__device__ __align__(256) __nv_bfloat16 g_aol[ROWS*INNER_];
__device__ __align__(256) __nv_bfloat16 g_xh [ROWS*DIMM];
__device__ __align__(256) __nv_bfloat16 g_xl [ROWS*DIMM];
__device__ __align__(256) __nv_bfloat16 g_wcth[(INNER_+2*DHD)*DIMM]; // [Wq^T ; Wkv^T]
__device__ __align__(256) __nv_bfloat16 g_wctl[(INNER_+2*DHD)*DIMM];
__device__ __align__(256) __nv_bfloat16 g_woth[DIMM*INNER_];
__device__ __align__(256) __nv_bfloat16 g_wotl[DIMM*INNER_];

// ---------------- helpers ----------------
__device__ __forceinline__ uint32_t s2u(const void* p) {
    uint32_t a;
    asm("{ .reg .u64 t; cvta.to.shared.u64 t, %1; cvt.u32.u64 %0, t; }"
        : "=r"(a) : "l"(p));
    return a;
}
__device__ __forceinline__ void cp16(uint32_t dst, const void* src) {
    asm volatile("cp.async.cg.shared.global [%0], [%1], 16;" :: "r"(dst), "l"(src));
}
__device__ __forceinline__ void cp_commit() { asm volatile("cp.async.commit_group;" ::: "memory"); }

__device__ __forceinline__ void mma16816(float c[4], const uint32_t a[4], const uint32_t b[2]) {
    asm volatile("mma.sync.aligned.m16n8k16.row.col.f32.bf16.bf16.f32 "
        "{%0,%1,%2,%3}, {%4,%5,%6,%7}, {%8,%9}, {%0,%1,%2,%3};"
        : "+f"(c[0]), "+f"(c[1]), "+f"(c[2]), "+f"(c[3])
        : "r"(a[0]), "r"(a[1]), "r"(a[2]), "r"(a[3]), "r"(b[0]), "r"(b[1]));
}

// pack two floats into bf16x2 hi + bf16x2 lo (residual)
__device__ __forceinline__ void pack_hl(float a, float b, uint32_t& h, uint32_t& l) {
    __nv_bfloat16 ha = __float2bfloat16(a), hb = __float2bfloat16(b);
    __nv_bfloat16 la = __float2bfloat16(a - __bfloat162float(ha));
    __nv_bfloat16 lb = __float2bfloat16(b - __bfloat162float(hb));
    __nv_bfloat162 hh = __halves2bfloat162(ha, hb);
    __nv_bfloat162 ll = __halves2bfloat162(la, lb);
    h = *reinterpret_cast<uint32_t*>(&hh);
    l = *reinterpret_cast<uint32_t*>(&ll);
}

// l4 = lane>>2, c2 = (lane&3)*2 must be in scope.
#define LDA_FR(fr, arr, row0, kcol, STRIDE) do { \
    (fr)[0] = *(const uint32_t*)&(arr)[((row0) + l4    )*(STRIDE) + (kcol) + c2    ]; \
    (fr)[1] = *(const uint32_t*)&(arr)[((row0) + l4 + 8)*(STRIDE) + (kcol) + c2    ]; \
    (fr)[2] = *(const uint32_t*)&(arr)[((row0) + l4    )*(STRIDE) + (kcol) + c2 + 8]; \
    (fr)[3] = *(const uint32_t*)&(arr)[((row0) + l4 + 8)*(STRIDE) + (kcol) + c2 + 8]; \
} while(0)
#define LDB_FR(fr, arr, n0, kcol, STRIDE) do { \
    (fr)[0] = *(const uint32_t*)&(arr)[((n0) + l4)*(STRIDE) + (kcol) + c2    ]; \
    (fr)[1] = *(const uint32_t*)&(arr)[((n0) + l4)*(STRIDE) + (kcol) + c2 + 8]; \
} while(0)

// ---------------------------------------------------------------------------
// Prep kernels
// ---------------------------------------------------------------------------
__global__ __launch_bounds__(256) void split_kernel(
    const float* __restrict__ A, __nv_bfloat16* __restrict__ H,
    __nv_bfloat16* __restrict__ L, int n4)
{
    int i = blockIdx.x * blockDim.x + threadIdx.x;
    if (i >= n4) return;
    float4 a = ((const float4*)A)[i];
    uint32_t h01, l01, h23, l23;
    pack_hl(a.x, a.y, h01, l01);
    pack_hl(a.z, a.w, h23, l23);
    ((uint32_t*)H)[2*i]   = h01; ((uint32_t*)H)[2*i+1] = h23;
    ((uint32_t*)L)[2*i]   = l01; ((uint32_t*)L)[2*i+1] = l23;
}

__global__ __launch_bounds__(256) void transpose_split_kernel(
    const float* __restrict__ W, __nv_bfloat16* __restrict__ TH,
    __nv_bfloat16* __restrict__ TL, int K, int N, float scale)
{
    __shared__ float tile[32][33];
    const int tx = threadIdx.x, ty = threadIdx.y;     // block (32,8)
    const int n0 = blockIdx.x * 32, k0 = blockIdx.y * 32;
    #pragma unroll
    for (int i = 0; i < 4; i++)
        tile[ty + 8*i][tx] = W[(size_t)(k0 + ty + 8*i) * N + n0 + tx];
    __syncthreads();
    #pragma unroll
    for (int i = 0; i < 4; i++) {
        float a = tile[tx][ty + 8*i] * scale;
        __nv_bfloat16 h = __float2bfloat16(a);
        __nv_bfloat16 l = __float2bfloat16(a - __bfloat162float(h));
        size_t o = (size_t)(n0 + ty + 8*i) * K + k0 + tx;
        TH[o] = h; TL[o] = l;
    }
}

// split + transpose kv: g_kv [row][128] -> Kh/Kl [b][j][64], Vth/Vtl [b][d][SEQ]
__global__ __launch_bounds__(256) void kvsplit_kernel(
    const float* __restrict__ KVin,
    __nv_bfloat16* __restrict__ KH, __nv_bfloat16* __restrict__ KL,
    __nv_bfloat16* __restrict__ VTH, __nv_bfloat16* __restrict__ VTL)
{
    __shared__ float vt[64][65];
    const int b = blockIdx.y, j0 = blockIdx.x * 64;
    const int tid = threadIdx.x;
    const int j = tid >> 2, g = (tid & 3) * 16;
    const float* rp = KVin + (size_t)(b*SEQ + j0 + j) * (2*DHD);
    #pragma unroll
    for (int c = 0; c < 4; c++) {
        float4 kq = *(const float4*)(rp + g + c*4);
        uint32_t h01, l01, h23, l23;
        pack_hl(kq.x, kq.y, h01, l01);
        pack_hl(kq.z, kq.w, h23, l23);
        size_t ko = (size_t)(b*SEQ + j0 + j)*DHD + g + c*4;
        *(uint32_t*)(KH + ko) = h01; *(uint32_t*)(KH + ko + 2) = h23;
        *(uint32_t*)(KL + ko) = l01; *(uint32_t*)(KL + ko + 2) = l23;
        float4 vq = *(const float4*)(rp + DHD + g + c*4);
        vt[j][g + c*4 + 0] = vq.x; vt[j][g + c*4 + 1] = vq.y;
        vt[j][g + c*4 + 2] = vq.z; vt[j][g + c*4 + 3] = vq.w;
    }
    __syncthreads();
    const int d = tid >> 2, jg = (tid & 3) * 16;
    #pragma unroll
    for (int i = 0; i < 16; i += 2) {
        float a = vt[jg + i][d], bb = vt[jg + i + 1][d];
        uint32_t h, l; pack_hl(a, bb, h, l);
        size_t vo = (size_t)(b*DHD + d)*SEQ + j0 + jg + i;
        *(uint32_t*)(VTH + vo) = h;
        *(uint32_t*)(VTL + vo) = l;
    }
}

// ---------------------------------------------------------------------------
// HMMA GEMM: CTA 128x128, BK=32, 2-stage cp.async, 8 warps x 32x64.
// MODE 0: fp32 C + bias.  MODE 1: cols<1024 -> split bf16 (q), col>=1024 -> fp32 kv.
// ---------------------------------------------------------------------------
#define GBK 32
#define GNSTG (KDIM/GBK)
#define GSTRIDE 40
#define GMATB (128*GSTRIDE*2)
#define GSTGB (4*GMATB)
#define GEMM_SMEM (2*GSTGB)

template<int MODE>
__global__ __launch_bounds__(256, 2) void gemm_mma(
    const __nv_bfloat16* __restrict__ Ah, const __nv_bfloat16* __restrict__ Al,
    const __nv_bfloat16* __restrict__ Bh, const __nv_bfloat16* __restrict__ Bl,
    float* __restrict__ C, const float* __restrict__ bias, int Ncols,
    __nv_bfloat16* __restrict__ CH, __nv_bfloat16* __restrict__ CL,
    float* __restrict__ C2)
{
    extern __shared__ __align__(16) char smem[];
    const uint32_t sbuf = s2u(smem);
    const int tid = threadIdx.x, wid = tid >> 5, lane = tid & 31;
    const int l4 = lane >> 2, c2 = (lane & 3) * 2;
    const int wm = wid & 3, wn = wid >> 2;
    const int bn = blockIdx.x, bm = blockIdx.y;

    const __nv_bfloat16* pA[2] = { Ah + (size_t)(bm*128)*KDIM, Al + (size_t)(bm*128)*KDIM };
    const __nv_bfloat16* pB[2] = { Bh + (size_t)(bn*128)*KDIM, Bl + (size_t)(bn*128)*KDIM };

    const int r0 = tid >> 2, kc = tid & 3;
    const int r1 = r0 + 64;

    float acc[2][8][4];
    #pragma unroll
    for (int i = 0; i < 2; i++)
        #pragma unroll
        for (int j = 0; j < 8; j++)
            #pragma unroll
            for (int e = 0; e < 4; e++) acc[i][j][e] = 0.f;

    #define G_LOAD(S) do { \
        const int _k0 = (S) * GBK; \
        const uint32_t stb = sbuf + ((S) & 1) * GSTGB; \
        _Pragma("unroll") \
        for (int m = 0; m < 2; m++) { \
            cp16(stb + m*GMATB     + r0*80 + kc*16, pA[m] + (size_t)r0*KDIM + _k0 + kc*8); \
            cp16(stb + m*GMATB     + r1*80 + kc*16, pA[m] + (size_t)r1*KDIM + _k0 + kc*8); \
            cp16(stb + (m+2)*GMATB + r0*80 + kc*16, pB[m] + (size_t)r0*KDIM + _k0 + kc*8); \
            cp16(stb + (m+2)*GMATB + r1*80 + kc*16, pB[m] + (size_t)r1*KDIM + _k0 + kc*8); \
        } \
    } while (0)

    G_LOAD(0); cp_commit();

    for (int s = 0; s < GNSTG; s++) {
        if (s + 1 < GNSTG) {
            G_LOAD(s + 1); cp_commit();
            asm volatile("cp.async.wait_group 1;" ::: "memory");
        } else {
            asm volatile("cp.async.wait_group 0;" ::: "memory");
        }
        __syncthreads();

        const __nv_bfloat16* base = (const __nv_bfloat16*)(smem + (s & 1) * GSTGB);
        const __nv_bfloat16* As_h = base;
        const __nv_bfloat16* As_l = base + 128*GSTRIDE;
        const __nv_bfloat16* Bs_h = base + 2*128*GSTRIDE;
        const __nv_bfloat16* Bs_l = base + 3*128*GSTRIDE;
        const int arow = wm*32, bcol = wn*64;

        #pragma unroll
        for (int k16 = 0; k16 < 2; k16++) {
            const int kcol = k16 * 16;
            uint32_t af[2][4], bf_[8][2];
            #pragma unroll
            for (int mt = 0; mt < 2; mt++) LDA_FR(af[mt], As_h, arow + mt*16, kcol, GSTRIDE);
            #pragma unroll
            for (int nt = 0; nt < 8; nt++) LDB_FR(bf_[nt], Bs_h, bcol + nt*8, kcol, GSTRIDE);
            #pragma unroll
            for (int mt = 0; mt < 2; mt++)
                #pragma unroll
                for (int nt = 0; nt < 8; nt++) mma16816(acc[mt][nt], af[mt], bf_[nt]);
            #pragma unroll
            for (int nt = 0; nt < 8; nt++) LDB_FR(bf_[nt], Bs_l, bcol + nt*8, kcol, GSTRIDE);
            #pragma unroll
            for (int mt = 0; mt < 2; mt++)
                #pragma unroll
                for (int nt = 0; nt < 8; nt++) mma16816(acc[mt][nt], af[mt], bf_[nt]);
            #pragma unroll
            for (int mt = 0; mt < 2; mt++) LDA_FR(af[mt], As_l, arow + mt*16, kcol, GSTRIDE);
            #pragma unroll
            for (int nt = 0; nt < 8; nt++) LDB_FR(bf_[nt], Bs_h, bcol + nt*8, kcol, GSTRIDE);
            #pragma unroll
            for (int mt = 0; mt < 2; mt++)
                #pragma unroll
                for (int nt = 0; nt < 8; nt++) mma16816(acc[mt][nt], af[mt], bf_[nt]);
        }
        __syncthreads();
    }
    #undef G_LOAD

    #pragma unroll
    for (int mt = 0; mt < 2; mt++) {
        const int rg0 = bm*128 + wm*32 + mt*16 + l4;
        #pragma unroll
        for (int nt = 0; nt < 8; nt++) {
            const int cg = bn*128 + wn*64 + nt*8 + c2;
            if (MODE == 0) {
                float b0 = bias ? bias[cg] : 0.f;
                float b1 = bias ? bias[cg+1] : 0.f;
                float2 v0 = { acc[mt][nt][0] + b0, acc[mt][nt][1] + b1 };
                float2 v1 = { acc[mt][nt][2] + b0, acc[mt][nt][3] + b1 };
                *(float2*)(C + (size_t)rg0*Ncols + cg)     = v0;
                *(float2*)(C + (size_t)(rg0+8)*Ncols + cg) = v1;
            } else {
                if (bn < 8) {
                    uint32_t h0, l0v, h1, l1v;
                    pack_hl(acc[mt][nt][0], acc[mt][nt][1], h0, l0v);
                    pack_hl(acc[mt][nt][2], acc[mt][nt][3], h1, l1v);
                    *(uint32_t*)(CH + (size_t)rg0*INNER_ + cg)     = h0;
                    *(uint32_t*)(CL + (size_t)rg0*INNER_ + cg)     = l0v;
                    *(uint32_t*)(CH + (size_t)(rg0+8)*INNER_ + cg) = h1;
                    *(uint32_t*)(CL + (size_t)(rg0+8)*INNER_ + cg) = l1v;
                } else {
                    const int cc = cg - 1024;
                    float2 v0 = { acc[mt][nt][0], acc[mt][nt][1] };
                    float2 v1 = { acc[mt][nt][2], acc[mt][nt][3] };
                    *(float2*)(C2 + (size_t)rg0*(2*DHD) + cc)     = v0;
                    *(float2*)(C2 + (size_t)(rg0+8)*(2*DHD) + cc) = v1;
                }
            }
        }
    }
}

// ---------------------------------------------------------------------------
// T5 relative-position bucket (mirrors jax fp32 math)
// ---------------------------------------------------------------------------
__device__ __forceinline__ int rel_bucket(int nn) {
    if (nn < 16) return nn;
    float t = logf((float)nn * (1.0f/16.0f)) / 2.0794415416798357f * 16.0f;
    int v = 16 + (int)t;
    return v < 31 ? v : 31;
}

// ---------------------------------------------------------------------------
// Flash attention v2: q-tile 128, warp-local softmax, register P, double-buffered KV.
// Grid (SEQ/128, HEADS, BATCH), 256 threads = 8 warps (warp w -> 16 rows).
// ---------------------------------------------------------------------------
#define FSTRIDE 72
#define FTILE   (64*FSTRIDE*2)     // 9216 bytes per bf16 tile
#define FKHO 0
#define FKLO (1*FTILE)
#define FVHO (2*FTILE)
#define FVLO (3*FTILE)
#define FSTG (4*FTILE)             // 36864 per stage
#define FBIAS (2*FSTG)             // 73728
#define FLASH_SMEM (FBIAS + 2048*4)  // 81920

__global__ __launch_bounds__(256, 2) void flash2(
    const __nv_bfloat16* __restrict__ QH, const __nv_bfloat16* __restrict__ QL,
    const __nv_bfloat16* __restrict__ KH, const __nv_bfloat16* __restrict__ KL,
    const __nv_bfloat16* __restrict__ VTH, const __nv_bfloat16* __restrict__ VTL,
    const float* __restrict__ rel_emb,
    __nv_bfloat16* __restrict__ AOH, __nv_bfloat16* __restrict__ AOL)
{
    extern __shared__ __align__(16) char smem[];
    const uint32_t sb = s2u(smem);
    float* biasv = (float*)(smem + FBIAS);

    const int qtb = (SEQ/128 - 1) - blockIdx.x;     // heavy CTAs first
    const int h = blockIdx.y, b = blockIdx.z;
    const int tid = threadIdx.x, lane = tid & 31, w = tid >> 5;
    const int l4 = lane >> 2, c2 = (lane & 3) * 2;
    const int i0 = qtb * 128;
    const int wrow = i0 + w * 16;

    // bias table (once per CTA)
    for (int nn = tid; nn < 2048; nn += 256)
        biasv[nn] = rel_emb[rel_bucket(nn)*HEADS + h] * 8.0f;

    // Q fragments in registers (hi/lo), 16 rows x 64 dims per warp
    uint32_t qhf[4][4], qlf[4][4];
    {
        const size_t rb = (size_t)(b*SEQ + wrow + l4) * INNER_ + h*DHD;
        #pragma unroll
        for (int k16 = 0; k16 < 4; k16++) {
            const int c = k16*16 + c2;
            qhf[k16][0] = *(const uint32_t*)(QH + rb + c);
            qhf[k16][1] = *(const uint32_t*)(QH + rb + 8*INNER_ + c);
            qhf[k16][2] = *(const uint32_t*)(QH + rb + c + 8);
            qhf[k16][3] = *(const uint32_t*)(QH + rb + 8*INNER_ + c + 8);
            qlf[k16][0] = *(const uint32_t*)(QL + rb + c);
            qlf[k16][1] = *(const uint32_t*)(QL + rb + 8*INNER_ + c);
            qlf[k16][2] = *(const uint32_t*)(QL + rb + c + 8);
            qlf[k16][3] = *(const uint32_t*)(QL + rb + 8*INNER_ + c + 8);
        }
    }

    float o[8][4];
    #pragma unroll
    for (int nt = 0; nt < 8; nt++)
        #pragma unroll
        for (int e = 0; e < 4; e++) o[nt][e] = 0.f;
    float m0 = -INFINITY, m1 = -INFINITY, l0 = 0.f, l1 = 0.f;

    const int jmax = (i0 + 127) >> 6;
    const int iwmax = wrow + 15;

    // KV stage loader: 4 tiles x 64 rows x 8 chunks of 16B = 2048 cp16 / 256 thr
    #define LOADKV(JT, S) do { \
        const int _j0 = (JT) * 64; \
        const uint32_t _sb = sb + (uint32_t)(S) * FSTG; \
        _Pragma("unroll") \
        for (int q = 0; q < 2; q++) { \
            const int id = tid*2 + q; \
            const int r = id >> 3, cc = id & 7; \
            const uint32_t so = (uint32_t)(r*144 + cc*16); \
            const size_t ksrc = (size_t)(b*SEQ + _j0 + r)*DHD + cc*8; \
            const size_t vsrc = (size_t)(b*DHD + r)*SEQ + _j0 + cc*8; \
            cp16(_sb + FKHO + so, KH  + ksrc); \
            cp16(_sb + FKLO + so, KL  + ksrc); \
            cp16(_sb + FVHO + so, VTH + vsrc); \
            cp16(_sb + FVLO + so, VTL + vsrc); \
        } \
    } while (0)

    LOADKV(0, 0); cp_commit();

    for (int jt = 0; jt <= jmax; jt++) {
        if (jt < jmax) {
            LOADKV(jt + 1, (jt + 1) & 1); cp_commit();
            asm volatile("cp.async.wait_group 1;" ::: "memory");
        } else {
            asm volatile("cp.async.wait_group 0;" ::: "memory");
        }
        __syncthreads();

        const int j0 = jt * 64;
        if (j0 <= iwmax) {   // warp-uniform skip of fully-masked blocks
            const char* stg = smem + (jt & 1) * FSTG;
            const __nv_bfloat16* Khs = (const __nv_bfloat16*)(stg + FKHO);
            const __nv_bfloat16* Kls = (const __nv_bfloat16*)(stg + FKLO);
            const __nv_bfloat16* Vhs = (const __nv_bfloat16*)(stg + FVHO);
            const __nv_bfloat16* Vls = (const __nv_bfloat16*)(stg + FVLO);

            // ---- S = Q K^T ----
            float s[8][4];
            #pragma unroll
            for (int nt = 0; nt < 8; nt++)
                #pragma unroll
                for (int e = 0; e < 4; e++) s[nt][e] = 0.f;

            #pragma unroll
            for (int k16 = 0; k16 < 4; k16++) {
                const int kcol = k16 * 16;
                #pragma unroll
                for (int nt = 0; nt < 8; nt++) {
                    uint32_t bh[2], bl[2];
                    LDB_FR(bh, Khs, nt*8, kcol, FSTRIDE);
                    mma16816(s[nt], qhf[k16], bh);
                    LDB_FR(bl, Kls, nt*8, kcol, FSTRIDE);
                    mma16816(s[nt], qhf[k16], bl);
                    mma16816(s[nt], qlf[k16], bh);
                }
            }

            // ---- bias + causal mask ----
            const bool masked = (j0 + 63 > wrow);
            const int irow0 = wrow + l4;
            #pragma unroll
            for (int nt = 0; nt < 8; nt++) {
                #pragma unroll
                for (int e = 0; e < 4; e++) {
                    const int ri = irow0 + ((e >> 1) << 3);
                    const int cj = j0 + nt*8 + c2 + (e & 1);
                    const int nn = ri - cj;
                    if (masked && nn < 0) s[nt][e] = -INFINITY;
                    else                  s[nt][e] += biasv[nn];
                }
            }

            // ---- warp-local online softmax ----
            float mc0 = -INFINITY, mc1 = -INFINITY;
            #pragma unroll
            for (int nt = 0; nt < 8; nt++) {
                mc0 = fmaxf(mc0, fmaxf(s[nt][0], s[nt][1]));
                mc1 = fmaxf(mc1, fmaxf(s[nt][2], s[nt][3]));
            }
            mc0 = fmaxf(mc0, __shfl_xor_sync(0xffffffffu, mc0, 1));
            mc0 = fmaxf(mc0, __shfl_xor_sync(0xffffffffu, mc0, 2));
            mc1 = fmaxf(mc1, __shfl_xor_sync(0xffffffffu, mc1, 1));
            mc1 = fmaxf(mc1, __shfl_xor_sync(0xffffffffu, mc1, 2));
            const float mn0 = fmaxf(m0, mc0), mn1 = fmaxf(m1, mc1);
            const float sc0 = __expf(m0 - mn0), sc1 = __expf(m1 - mn1);
            m0 = mn0; m1 = mn1;

            float rs0 = 0.f, rs1 = 0.f;
            #pragma unroll
            for (int nt = 0; nt < 8; nt++) {
                s[nt][0] = __expf(s[nt][0] - mn0);
                s[nt][1] = __expf(s[nt][1] - mn0);
                s[nt][2] = __expf(s[nt][2] - mn1);
                s[nt][3] = __expf(s[nt][3] - mn1);
                rs0 += s[nt][0] + s[nt][1];
                rs1 += s[nt][2] + s[nt][3];
            }
            rs0 += __shfl_xor_sync(0xffffffffu, rs0, 1);
            rs0 += __shfl_xor_sync(0xffffffffu, rs0, 2);
            rs1 += __shfl_xor_sync(0xffffffffu, rs1, 1);
            rs1 += __shfl_xor_sync(0xffffffffu, rs1, 2);
            l0 = l0*sc0 + rs0;
            l1 = l1*sc1 + rs1;

            #pragma unroll
            for (int nt = 0; nt < 8; nt++) {
                o[nt][0] *= sc0; o[nt][1] *= sc0;
                o[nt][2] *= sc1; o[nt][3] *= sc1;
            }

            // ---- O += P V (P packed in registers, hi/lo) ----
            #pragma unroll
            for (int kk = 0; kk < 4; kk++) {
                uint32_t pah[4], pal[4];
                pack_hl(s[2*kk  ][0], s[2*kk  ][1], pah[0], pal[0]);
                pack_hl(s[2*kk  ][2], s[2*kk  ][3], pah[1], pal[1]);
                pack_hl(s[2*kk+1][0], s[2*kk+1][1], pah[2], pal[2]);
                pack_hl(s[2*kk+1][2], s[2*kk+1][3], pah[3], pal[3]);
                const int kcol = kk * 16;
                #pragma unroll
                for (int nt = 0; nt < 8; nt++) {
                    uint32_t bh[2], bl[2];
                    LDB_FR(bh, Vhs, nt*8, kcol, FSTRIDE);
                    mma16816(o[nt], pah, bh);
                    LDB_FR(bl, Vls, nt*8, kcol, FSTRIDE);
                    mma16816(o[nt], pah, bl);
                    mma16816(o[nt], pal, bh);
                }
            }
        }
        __syncthreads();
    }
    #undef LOADKV

    // ---- normalize + write split bf16 output ----
    {
        const float inv0 = 1.0f / l0, inv1 = 1.0f / l1;
        const size_t rb = (size_t)(b*SEQ + wrow + l4) * INNER_ + h*DHD;
        #pragma unroll
        for (int nt = 0; nt < 8; nt++) {
            const int col = nt*8 + c2;
            uint32_t ph, pl;
            pack_hl(o[nt][0]*inv0, o[nt][1]*inv0, ph, pl);
            *(uint32_t*)(AOH + rb + col) = ph;
            *(uint32_t*)(AOL + rb + col) = pl;
            pack_hl(o[nt][2]*inv1, o[nt][3]*inv1, ph, pl);
            *(uint32_t*)(AOH + rb + 8*INNER_ + col) = ph;
            *(uint32_t*)(AOL + rb + 8*INNER_ + col) = pl;
        }
    }
}

// ---------------------------------------------------------------------------
extern "C" void kernel_launch(void* const* d_in, const int* in_sizes, int n_in,
                              void* d_out, int out_size)
{
    const float* x       = (const float*)d_in[0];
    const float* Wq      = (const float*)d_in[1];
    const float* Wkv     = (const float*)d_in[2];
    const float* Wout    = (const float*)d_in[3];
    const float* bout    = (const float*)d_in[4];
    const float* rel_emb = (const float*)d_in[5];
    float* out = (float*)d_out;

    void* p;
    cudaGetSymbolAddress(&p, g_kv);   float* kvp = (float*)p;
    cudaGetSymbolAddress(&p, g_qh);   __nv_bfloat16* qh  = (__nv_bfloat16*)p;
    cudaGetSymbolAddress(&p, g_ql);   __nv_bfloat16* ql  = (__nv_bfloat16*)p;
    cudaGetSymbolAddress(&p, g_kh);   __nv_bfloat16* kh  = (__nv_bfloat16*)p;
    cudaGetSymbolAddress(&p, g_kl);   __nv_bfloat16* kl  = (__nv_bfloat16*)p;
    cudaGetSymbolAddress(&p, g_vth);  __nv_bfloat16* vth = (__nv_bfloat16*)p;
    cudaGetSymbolAddress(&p, g_vtl);  __nv_bfloat16* vtl = (__nv_bfloat16*)p;
    cudaGetSymbolAddress(&p, g_aoh);  __nv_bfloat16* aoh = (__nv_bfloat16*)p;
    cudaGetSymbolAddress(&p, g_aol);  __nv_bfloat16* aol = (__nv_bfloat16*)p;
    cudaGetSymbolAddress(&p, g_xh);   __nv_bfloat16* xh  = (__nv_bfloat16*)p;
    cudaGetSymbolAddress(&p, g_xl);   __nv_bfloat16* xl  = (__nv_bfloat16*)p;
    cudaGetSymbolAddress(&p, g_wcth); __nv_bfloat16* wch = (__nv_bfloat16*)p;
    cudaGetSymbolAddress(&p, g_wctl); __nv_bfloat16* wcl = (__nv_bfloat16*)p;
    cudaGetSymbolAddress(&p, g_woth); __nv_bfloat16* woh = (__nv_bfloat16*)p;
    cudaGetSymbolAddress(&p, g_wotl); __nv_bfloat16* wol = (__nv_bfloat16*)p;

    cudaFuncSetAttribute(gemm_mma<0>, cudaFuncAttributeMaxDynamicSharedMemorySize, GEMM_SMEM);
    cudaFuncSetAttribute(gemm_mma<1>, cudaFuncAttributeMaxDynamicSharedMemorySize, GEMM_SMEM);
    cudaFuncSetAttribute(flash2, cudaFuncAttributeMaxDynamicSharedMemorySize, FLASH_SMEM);

    dim3 tb(32, 8);
    // weight prep (Wq pre-scaled by dim_head^-0.5)
    transpose_split_kernel<<<dim3(INNER_/32, DIMM/32), tb>>>(Wq,  wch, wcl, DIMM, INNER_, 0.125f);
    transpose_split_kernel<<<dim3((2*DHD)/32, DIMM/32), tb>>>(Wkv, wch + (size_t)INNER_*DIMM,
                                                              wcl + (size_t)INNER_*DIMM, DIMM, 2*DHD, 1.0f);
    transpose_split_kernel<<<dim3(DIMM/32, INNER_/32), tb>>>(Wout, woh, wol, INNER_, DIMM, 1.0f);
    split_kernel<<<(ROWS*DIMM/4 + 255)/256, 256>>>(x, xh, xl, ROWS*DIMM/4);

    // fused q|kv projection: writes q as split bf16, kv as fp32
    gemm_mma<1><<<dim3(9, ROWS/128), 256, GEMM_SMEM>>>(xh, xl, wch, wcl,
                                                       nullptr, nullptr, 0, qh, ql, kvp);
    // kv -> split K + transposed split V
    kvsplit_kernel<<<dim3(SEQ/64, BATCH), 256>>>(kvp, kh, kl, vth, vtl);
    // attention (writes split bf16 output directly)
    flash2<<<dim3(SEQ/128, HEADS, BATCH), 256, FLASH_SMEM>>>(qh, ql, kh, kl, vth, vtl,
                                                             rel_emb, aoh, aol);
    // out = ao @ Wout + bout
    gemm_mma<0><<<dim3(DIMM/128, ROWS/128), 256, GEMM_SMEM>>>(aoh, aol, woh, wol,
                                                              out, bout, DIMM,
                                                              nullptr, nullptr, nullptr);
}

// round 7
// speedup vs baseline: 1.1072x; 1.1072x over previous
#include <cuda_runtime.h>
#include <cuda_bf16.h>
#include <math.h>
#include <stdint.h>

#define BATCH 2
#define SEQ   2048
#define DIMM  1024
#define HEADS 16
#define DHD   64
#define INNER_ (HEADS*DHD)      // 1024
#define ROWS  (BATCH*SEQ)       // 4096
#define KDIM  1024
#define LOG2E 1.4426950408889634f

// ---------------- scratch (no cudaMalloc allowed) ----------------
__device__ __align__(256) float g_kv[ROWS*2*DHD];
__device__ __align__(256) __nv_bfloat16 g_qh [ROWS*INNER_];
__device__ __align__(256) __nv_bfloat16 g_ql [ROWS*INNER_];
__device__ __align__(256) __nv_bfloat16 g_kh [BATCH*SEQ*DHD];
__device__ __align__(256) __nv_bfloat16 g_kl [BATCH*SEQ*DHD];
__device__ __align__(256) __nv_bfloat16 g_vth[BATCH*DHD*SEQ];
__device__ __align__(256) __nv_bfloat16 g_vtl[BATCH*DHD*SEQ];
__device__ __align__(256) __nv_bfloat16 g_aoh[ROWS*INNER_];
__device__ __align__(256) __nv_bfloat16 g_aol[ROWS*INNER_];
__device__ __align__(256) __nv_bfloat16 g_xh [ROWS*DIMM];
__device__ __align__(256) __nv_bfloat16 g_xl [ROWS*DIMM];
__device__ __align__(256) __nv_bfloat16 g_wcth[(INNER_+2*DHD)*DIMM];
__device__ __align__(256) __nv_bfloat16 g_wctl[(INNER_+2*DHD)*DIMM];
__device__ __align__(256) __nv_bfloat16 g_woth[DIMM*INNER_];
__device__ __align__(256) __nv_bfloat16 g_wotl[DIMM*INNER_];

// ---------------- helpers ----------------
__device__ __forceinline__ uint32_t s2u(const void* p) {
    uint32_t a;
    asm("{ .reg .u64 t; cvta.to.shared.u64 t, %1; cvt.u32.u64 %0, t; }"
        : "=r"(a) : "l"(p));
    return a;
}
__device__ __forceinline__ void cp16(uint32_t dst, const void* src) {
    asm volatile("cp.async.cg.shared.global [%0], [%1], 16;" :: "r"(dst), "l"(src));
}
__device__ __forceinline__ void cp_commit() { asm volatile("cp.async.commit_group;" ::: "memory"); }

__device__ __forceinline__ void mma16816(float c[4], const uint32_t a[4], const uint32_t b[2]) {
    asm volatile("mma.sync.aligned.m16n8k16.row.col.f32.bf16.bf16.f32 "
        "{%0,%1,%2,%3}, {%4,%5,%6,%7}, {%8,%9}, {%0,%1,%2,%3};"
        : "+f"(c[0]), "+f"(c[1]), "+f"(c[2]), "+f"(c[3])
        : "r"(a[0]), "r"(a[1]), "r"(a[2]), "r"(a[3]), "r"(b[0]), "r"(b[1]));
}

// ldmatrix x4: 4 8x8 b16 matrices; lane i supplies row addr for matrix i/8.
__device__ __forceinline__ void ldsm_x4(uint32_t r[4], uint32_t saddr) {
    asm volatile("ldmatrix.sync.aligned.m8n8.x4.shared.b16 {%0,%1,%2,%3}, [%4];"
        : "=r"(r[0]), "=r"(r[1]), "=r"(r[2]), "=r"(r[3]) : "r"(saddr));
}

// pack two floats into bf16x2 hi + bf16x2 lo (residual)
__device__ __forceinline__ void pack_hl(float a, float b, uint32_t& h, uint32_t& l) {
    __nv_bfloat16 ha = __float2bfloat16(a), hb = __float2bfloat16(b);
    __nv_bfloat16 la = __float2bfloat16(a - __bfloat162float(ha));
    __nv_bfloat16 lb = __float2bfloat16(b - __bfloat162float(hb));
    __nv_bfloat162 hh = __halves2bfloat162(ha, hb);
    __nv_bfloat162 ll = __halves2bfloat162(la, lb);
    h = *reinterpret_cast<uint32_t*>(&hh);
    l = *reinterpret_cast<uint32_t*>(&ll);
}

// ---------------------------------------------------------------------------
// Prep kernels
// ---------------------------------------------------------------------------
__global__ __launch_bounds__(256) void split_kernel(
    const float* __restrict__ A, __nv_bfloat16* __restrict__ H,
    __nv_bfloat16* __restrict__ L, int n4)
{
    int i = blockIdx.x * blockDim.x + threadIdx.x;
    if (i >= n4) return;
    float4 a = ((const float4*)A)[i];
    uint32_t h01, l01, h23, l23;
    pack_hl(a.x, a.y, h01, l01);
    pack_hl(a.z, a.w, h23, l23);
    ((uint32_t*)H)[2*i]   = h01; ((uint32_t*)H)[2*i+1] = h23;
    ((uint32_t*)L)[2*i]   = l01; ((uint32_t*)L)[2*i+1] = l23;
}

__global__ __launch_bounds__(256) void transpose_split_kernel(
    const float* __restrict__ W, __nv_bfloat16* __restrict__ TH,
    __nv_bfloat16* __restrict__ TL, int K, int N, float scale)
{
    __shared__ float tile[32][33];
    const int tx = threadIdx.x, ty = threadIdx.y;
    const int n0 = blockIdx.x * 32, k0 = blockIdx.y * 32;
    #pragma unroll
    for (int i = 0; i < 4; i++)
        tile[ty + 8*i][tx] = W[(size_t)(k0 + ty + 8*i) * N + n0 + tx];
    __syncthreads();
    #pragma unroll
    for (int i = 0; i < 4; i++) {
        float a = tile[tx][ty + 8*i] * scale;
        __nv_bfloat16 h = __float2bfloat16(a);
        __nv_bfloat16 l = __float2bfloat16(a - __bfloat162float(h));
        size_t o = (size_t)(n0 + ty + 8*i) * K + k0 + tx;
        TH[o] = h; TL[o] = l;
    }
}

__global__ __launch_bounds__(256) void kvsplit_kernel(
    const float* __restrict__ KVin,
    __nv_bfloat16* __restrict__ KH, __nv_bfloat16* __restrict__ KL,
    __nv_bfloat16* __restrict__ VTH, __nv_bfloat16* __restrict__ VTL)
{
    __shared__ float vt[64][65];
    const int b = blockIdx.y, j0 = blockIdx.x * 64;
    const int tid = threadIdx.x;
    const int j = tid >> 2, g = (tid & 3) * 16;
    const float* rp = KVin + (size_t)(b*SEQ + j0 + j) * (2*DHD);
    #pragma unroll
    for (int c = 0; c < 4; c++) {
        float4 kq = *(const float4*)(rp + g + c*4);
        uint32_t h01, l01, h23, l23;
        pack_hl(kq.x, kq.y, h01, l01);
        pack_hl(kq.z, kq.w, h23, l23);
        size_t ko = (size_t)(b*SEQ + j0 + j)*DHD + g + c*4;
        *(uint32_t*)(KH + ko) = h01; *(uint32_t*)(KH + ko + 2) = h23;
        *(uint32_t*)(KL + ko) = l01; *(uint32_t*)(KL + ko + 2) = l23;
        float4 vq = *(const float4*)(rp + DHD + g + c*4);
        vt[j][g + c*4 + 0] = vq.x; vt[j][g + c*4 + 1] = vq.y;
        vt[j][g + c*4 + 2] = vq.z; vt[j][g + c*4 + 3] = vq.w;
    }
    __syncthreads();
    const int d = tid >> 2, jg = (tid & 3) * 16;
    #pragma unroll
    for (int i = 0; i < 16; i += 2) {
        float a = vt[jg + i][d], bb = vt[jg + i + 1][d];
        uint32_t h, l; pack_hl(a, bb, h, l);
        size_t vo = (size_t)(b*DHD + d)*SEQ + j0 + jg + i;
        *(uint32_t*)(VTH + vo) = h;
        *(uint32_t*)(VTL + vo) = l;
    }
}

// ---------------------------------------------------------------------------
// HMMA GEMM: CTA 128x128, BK=32, 2-stage cp.async, 8 warps x 32x64.
// ldmatrix fragment loads + Bh-reuse pass order (Ah*Bh, Al*Bh, Ah*Bl).
// ---------------------------------------------------------------------------
#define GBK 32
#define GNSTG (KDIM/GBK)
#define GSTRIDE 40                  // elements; 80 bytes/row
#define GMATB (128*GSTRIDE*2)
#define GSTGB (4*GMATB)
#define GEMM_SMEM (2*GSTGB)

template<int MODE>
__global__ __launch_bounds__(256) void gemm_mma(
    const __nv_bfloat16* __restrict__ Ah, const __nv_bfloat16* __restrict__ Al,
    const __nv_bfloat16* __restrict__ Bh, const __nv_bfloat16* __restrict__ Bl,
    float* __restrict__ C, const float* __restrict__ bias, int Ncols,
    __nv_bfloat16* __restrict__ CH, __nv_bfloat16* __restrict__ CL,
    float* __restrict__ C2)
{
    extern __shared__ __align__(16) char smem[];
    const uint32_t sbuf = s2u(smem);
    const int tid = threadIdx.x, wid = tid >> 5, lane = tid & 31;
    const int l4 = lane >> 2, c2 = (lane & 3) * 2;
    const int wm = wid & 3, wn = wid >> 2;
    const int bn = blockIdx.x, bm = blockIdx.y;

    // ldmatrix lane address terms
    const uint32_t ltermB = ((lane & 7) + ((lane >> 4) << 3)) * (GSTRIDE*2)
                          + (((lane >> 3) & 1) << 4);            // +8 cols = 16B
    const uint32_t ltermA = ((lane & 7) + (((lane >> 3) & 1) << 3)) * (GSTRIDE*2)
                          + (((lane >> 4) & 1) << 4);

    const __nv_bfloat16* pA[2] = { Ah + (size_t)(bm*128)*KDIM, Al + (size_t)(bm*128)*KDIM };
    const __nv_bfloat16* pB[2] = { Bh + (size_t)(bn*128)*KDIM, Bl + (size_t)(bn*128)*KDIM };

    const int r0 = tid >> 2, kc = tid & 3;
    const int r1 = r0 + 64;

    float acc[2][8][4];
    #pragma unroll
    for (int i = 0; i < 2; i++)
        #pragma unroll
        for (int j = 0; j < 8; j++)
            #pragma unroll
            for (int e = 0; e < 4; e++) acc[i][j][e] = 0.f;

    #define G_LOAD(S) do { \
        const int _k0 = (S) * GBK; \
        const uint32_t stb = sbuf + ((S) & 1) * GSTGB; \
        _Pragma("unroll") \
        for (int m = 0; m < 2; m++) { \
            cp16(stb + m*GMATB     + r0*80 + kc*16, pA[m] + (size_t)r0*KDIM + _k0 + kc*8); \
            cp16(stb + m*GMATB     + r1*80 + kc*16, pA[m] + (size_t)r1*KDIM + _k0 + kc*8); \
            cp16(stb + (m+2)*GMATB + r0*80 + kc*16, pB[m] + (size_t)r0*KDIM + _k0 + kc*8); \
            cp16(stb + (m+2)*GMATB + r1*80 + kc*16, pB[m] + (size_t)r1*KDIM + _k0 + kc*8); \
        } \
    } while (0)

    G_LOAD(0); cp_commit();

    for (int s = 0; s < GNSTG; s++) {
        if (s + 1 < GNSTG) {
            G_LOAD(s + 1); cp_commit();
            asm volatile("cp.async.wait_group 1;" ::: "memory");
        } else {
            asm volatile("cp.async.wait_group 0;" ::: "memory");
        }
        __syncthreads();

        const uint32_t stb = sbuf + (s & 1) * GSTGB;
        // warp bases for ldmatrix
        const uint32_t aBaseH = stb            + (wm*32)*80 + ltermA;
        const uint32_t aBaseL = stb + GMATB    + (wm*32)*80 + ltermA;
        const uint32_t bBaseH = stb + 2*GMATB  + (wn*64)*80 + ltermB;
        const uint32_t bBaseL = stb + 3*GMATB  + (wn*64)*80 + ltermB;

        #pragma unroll
        for (int k16 = 0; k16 < 2; k16++) {
            const uint32_t kc2 = (uint32_t)k16 * 32;   // kcol*2 bytes
            uint32_t ah[2][4], al[2][4], bb[4][4];
            #pragma unroll
            for (int mt = 0; mt < 2; mt++) ldsm_x4(ah[mt], aBaseH + mt*(16*80) + kc2);
            #pragma unroll
            for (int np = 0; np < 4; np++) ldsm_x4(bb[np], bBaseH + np*(16*80) + kc2);
            #pragma unroll
            for (int mt = 0; mt < 2; mt++)
                #pragma unroll
                for (int np = 0; np < 4; np++) {
                    mma16816(acc[mt][2*np],   ah[mt], &bb[np][0]);
                    mma16816(acc[mt][2*np+1], ah[mt], &bb[np][2]);
                }
            #pragma unroll
            for (int mt = 0; mt < 2; mt++) ldsm_x4(al[mt], aBaseL + mt*(16*80) + kc2);
            #pragma unroll
            for (int mt = 0; mt < 2; mt++)
                #pragma unroll
                for (int np = 0; np < 4; np++) {
                    mma16816(acc[mt][2*np],   al[mt], &bb[np][0]);
                    mma16816(acc[mt][2*np+1], al[mt], &bb[np][2]);
                }
            #pragma unroll
            for (int np = 0; np < 4; np++) ldsm_x4(bb[np], bBaseL + np*(16*80) + kc2);
            #pragma unroll
            for (int mt = 0; mt < 2; mt++)
                #pragma unroll
                for (int np = 0; np < 4; np++) {
                    mma16816(acc[mt][2*np],   ah[mt], &bb[np][0]);
                    mma16816(acc[mt][2*np+1], ah[mt], &bb[np][2]);
                }
        }
        __syncthreads();
    }
    #undef G_LOAD

    #pragma unroll
    for (int mt = 0; mt < 2; mt++) {
        const int rg0 = bm*128 + wm*32 + mt*16 + l4;
        #pragma unroll
        for (int nt = 0; nt < 8; nt++) {
            const int cg = bn*128 + wn*64 + nt*8 + c2;
            if (MODE == 0) {
                float b0 = bias ? bias[cg] : 0.f;
                float b1 = bias ? bias[cg+1] : 0.f;
                float2 v0 = { acc[mt][nt][0] + b0, acc[mt][nt][1] + b1 };
                float2 v1 = { acc[mt][nt][2] + b0, acc[mt][nt][3] + b1 };
                *(float2*)(C + (size_t)rg0*Ncols + cg)     = v0;
                *(float2*)(C + (size_t)(rg0+8)*Ncols + cg) = v1;
            } else {
                if (bn < 8) {
                    uint32_t h0, l0v, h1, l1v;
                    pack_hl(acc[mt][nt][0], acc[mt][nt][1], h0, l0v);
                    pack_hl(acc[mt][nt][2], acc[mt][nt][3], h1, l1v);
                    *(uint32_t*)(CH + (size_t)rg0*INNER_ + cg)     = h0;
                    *(uint32_t*)(CL + (size_t)rg0*INNER_ + cg)     = l0v;
                    *(uint32_t*)(CH + (size_t)(rg0+8)*INNER_ + cg) = h1;
                    *(uint32_t*)(CL + (size_t)(rg0+8)*INNER_ + cg) = l1v;
                } else {
                    const int cc = cg - 1024;
                    float2 v0 = { acc[mt][nt][0], acc[mt][nt][1] };
                    float2 v1 = { acc[mt][nt][2], acc[mt][nt][3] };
                    *(float2*)(C2 + (size_t)rg0*(2*DHD) + cc)     = v0;
                    *(float2*)(C2 + (size_t)(rg0+8)*(2*DHD) + cc) = v1;
                }
            }
        }
    }
}

// ---------------------------------------------------------------------------
// T5 relative-position bucket (mirrors jax fp32 math)
// ---------------------------------------------------------------------------
__device__ __forceinline__ int rel_bucket(int nn) {
    if (nn < 16) return nn;
    float t = logf((float)nn * (1.0f/16.0f)) / 2.0794415416798357f * 16.0f;
    int v = 16 + (int)t;
    return v < 31 ? v : 31;
}

// ---------------------------------------------------------------------------
// Flash attention v3: 3-stage cp.async ring (ONE __syncthreads per KV tile),
// ldmatrix K/V fragment loads, exp2-domain softmax (log2e folded into q & bias).
// Grid (SEQ/128, HEADS, BATCH), 256 threads = 8 warps (warp w -> 16 rows).
// ---------------------------------------------------------------------------
#define FSTRIDE 72                  // elements; 144 bytes/row
#define FTILE   (64*FSTRIDE*2)      // 9216 bytes per tile
#define FKHO 0
#define FKLO (1*FTILE)
#define FVHO (2*FTILE)
#define FVLO (3*FTILE)
#define FSTG (4*FTILE)              // 36864 per stage
#define FBIAS (3*FSTG)              // 110592
#define FLASH_SMEM (FBIAS + 2048*4) // 118784

__global__ __launch_bounds__(256) void flash2(
    const __nv_bfloat16* __restrict__ QH, const __nv_bfloat16* __restrict__ QL,
    const __nv_bfloat16* __restrict__ KH, const __nv_bfloat16* __restrict__ KL,
    const __nv_bfloat16* __restrict__ VTH, const __nv_bfloat16* __restrict__ VTL,
    const float* __restrict__ rel_emb,
    __nv_bfloat16* __restrict__ AOH, __nv_bfloat16* __restrict__ AOL)
{
    extern __shared__ __align__(16) char smem[];
    const uint32_t sb = s2u(smem);
    float* biasv = (float*)(smem + FBIAS);

    const int qtb = (SEQ/128 - 1) - blockIdx.x;     // heavy CTAs first
    const int h = blockIdx.y, b = blockIdx.z;
    const int tid = threadIdx.x, lane = tid & 31, w = tid >> 5;
    const int l4 = lane >> 2, c2 = (lane & 3) * 2;
    const int i0 = qtb * 128;
    const int wrow = i0 + w * 16;

    // ldmatrix lane address term (B frags, stride 144B)
    const uint32_t ltermB = ((lane & 7) + ((lane >> 4) << 3)) * (FSTRIDE*2)
                          + (((lane >> 3) & 1) << 4);

    // bias table in log2 domain
    for (int nn = tid; nn < 2048; nn += 256)
        biasv[nn] = rel_emb[rel_bucket(nn)*HEADS + h] * (8.0f * LOG2E);

    // Q fragments in registers (hi/lo); q already pre-scaled by 0.125*log2e
    uint32_t qhf[4][4], qlf[4][4];
    {
        const size_t rb = (size_t)(b*SEQ + wrow + l4) * INNER_ + h*DHD;
        #pragma unroll
        for (int k16 = 0; k16 < 4; k16++) {
            const int c = k16*16 + c2;
            qhf[k16][0] = *(const uint32_t*)(QH + rb + c);
            qhf[k16][1] = *(const uint32_t*)(QH + rb + 8*INNER_ + c);
            qhf[k16][2] = *(const uint32_t*)(QH + rb + c + 8);
            qhf[k16][3] = *(const uint32_t*)(QH + rb + 8*INNER_ + c + 8);
            qlf[k16][0] = *(const uint32_t*)(QL + rb + c);
            qlf[k16][1] = *(const uint32_t*)(QL + rb + 8*INNER_ + c);
            qlf[k16][2] = *(const uint32_t*)(QL + rb + c + 8);
            qlf[k16][3] = *(const uint32_t*)(QL + rb + 8*INNER_ + c + 8);
        }
    }

    float o[8][4];
    #pragma unroll
    for (int nt = 0; nt < 8; nt++)
        #pragma unroll
        for (int e = 0; e < 4; e++) o[nt][e] = 0.f;
    float m0 = -INFINITY, m1 = -INFINITY, l0 = 0.f, l1 = 0.f;

    const int jmax = (i0 + 127) >> 6;     // >= 1 always
    const int iwmax = wrow + 15;

    #define LOADKV(JT, S) do { \
        const int _j0 = (JT) * 64; \
        const uint32_t _sb = sb + (uint32_t)(S) * FSTG; \
        _Pragma("unroll") \
        for (int q = 0; q < 2; q++) { \
            const int id = tid*2 + q; \
            const int r = id >> 3, cc = id & 7; \
            const uint32_t so = (uint32_t)(r*144 + cc*16); \
            const size_t ksrc = (size_t)(b*SEQ + _j0 + r)*DHD + cc*8; \
            const size_t vsrc = (size_t)(b*DHD + r)*SEQ + _j0 + cc*8; \
            cp16(_sb + FKHO + so, KH  + ksrc); \
            cp16(_sb + FKLO + so, KL  + ksrc); \
            cp16(_sb + FVHO + so, VTH + vsrc); \
            cp16(_sb + FVLO + so, VTL + vsrc); \
        } \
    } while (0)

    LOADKV(0, 0); cp_commit();
    LOADKV(1, 1); cp_commit();

    for (int jt = 0; jt <= jmax; jt++) {
        asm volatile("cp.async.wait_group 1;" ::: "memory");
        __syncthreads();                               // stage jt visible; stage jt-1 free
        if (jt + 2 <= jmax) LOADKV(jt + 2, (jt + 2) % 3);
        cp_commit();

        const int j0 = jt * 64;
        if (j0 <= iwmax) {
            const uint32_t stgb = sb + (uint32_t)(jt % 3) * FSTG;

            // ---- S = Q K^T (ldmatrix frags, Kh kept live for 3rd product) ----
            float s[8][4];
            #pragma unroll
            for (int nt = 0; nt < 8; nt++)
                #pragma unroll
                for (int e = 0; e < 4; e++) s[nt][e] = 0.f;

            #pragma unroll
            for (int k16 = 0; k16 < 4; k16++) {
                const uint32_t kc2 = (uint32_t)k16 * 32;
                #pragma unroll
                for (int np = 0; np < 4; np++) {
                    uint32_t kh4[4], kl4[4];
                    const uint32_t a0 = stgb + FKHO + np*(16*144) + kc2 + ltermB;
                    ldsm_x4(kh4, a0);
                    ldsm_x4(kl4, a0 + (FKLO - FKHO));
                    mma16816(s[2*np],   qhf[k16], &kh4[0]);
                    mma16816(s[2*np+1], qhf[k16], &kh4[2]);
                    mma16816(s[2*np],   qhf[k16], &kl4[0]);
                    mma16816(s[2*np+1], qhf[k16], &kl4[2]);
                    mma16816(s[2*np],   qlf[k16], &kh4[0]);
                    mma16816(s[2*np+1], qlf[k16], &kh4[2]);
                }
            }

            // ---- bias + causal mask (log2 domain) ----
            const bool masked = (j0 + 63 > wrow);
            const int irow0 = wrow + l4;
            #pragma unroll
            for (int nt = 0; nt < 8; nt++) {
                #pragma unroll
                for (int e = 0; e < 4; e++) {
                    const int ri = irow0 + ((e >> 1) << 3);
                    const int cj = j0 + nt*8 + c2 + (e & 1);
                    const int nn = ri - cj;
                    if (masked && nn < 0) s[nt][e] = -INFINITY;
                    else                  s[nt][e] += biasv[nn];
                }
            }

            // ---- warp-local online softmax (exp2 domain) ----
            float mc0 = -INFINITY, mc1 = -INFINITY;
            #pragma unroll
            for (int nt = 0; nt < 8; nt++) {
                mc0 = fmaxf(mc0, fmaxf(s[nt][0], s[nt][1]));
                mc1 = fmaxf(mc1, fmaxf(s[nt][2], s[nt][3]));
            }
            mc0 = fmaxf(mc0, __shfl_xor_sync(0xffffffffu, mc0, 1));
            mc0 = fmaxf(mc0, __shfl_xor_sync(0xffffffffu, mc0, 2));
            mc1 = fmaxf(mc1, __shfl_xor_sync(0xffffffffu, mc1, 1));
            mc1 = fmaxf(mc1, __shfl_xor_sync(0xffffffffu, mc1, 2));
            const float mn0 = fmaxf(m0, mc0), mn1 = fmaxf(m1, mc1);
            const float sc0 = exp2f(m0 - mn0), sc1 = exp2f(m1 - mn1);
            m0 = mn0; m1 = mn1;

            float rs0 = 0.f, rs1 = 0.f;
            #pragma unroll
            for (int nt = 0; nt < 8; nt++) {
                s[nt][0] = exp2f(s[nt][0] - mn0);
                s[nt][1] = exp2f(s[nt][1] - mn0);
                s[nt][2] = exp2f(s[nt][2] - mn1);
                s[nt][3] = exp2f(s[nt][3] - mn1);
                rs0 += s[nt][0] + s[nt][1];
                rs1 += s[nt][2] + s[nt][3];
            }
            rs0 += __shfl_xor_sync(0xffffffffu, rs0, 1);
            rs0 += __shfl_xor_sync(0xffffffffu, rs0, 2);
            rs1 += __shfl_xor_sync(0xffffffffu, rs1, 1);
            rs1 += __shfl_xor_sync(0xffffffffu, rs1, 2);
            l0 = l0*sc0 + rs0;
            l1 = l1*sc1 + rs1;

            #pragma unroll
            for (int nt = 0; nt < 8; nt++) {
                o[nt][0] *= sc0; o[nt][1] *= sc0;
                o[nt][2] *= sc1; o[nt][3] *= sc1;
            }

            // ---- O += P V ----
            #pragma unroll
            for (int kk = 0; kk < 4; kk++) {
                uint32_t pah[4], pal[4];
                pack_hl(s[2*kk  ][0], s[2*kk  ][1], pah[0], pal[0]);
                pack_hl(s[2*kk  ][2], s[2*kk  ][3], pah[1], pal[1]);
                pack_hl(s[2*kk+1][0], s[2*kk+1][1], pah[2], pal[2]);
                pack_hl(s[2*kk+1][2], s[2*kk+1][3], pah[3], pal[3]);
                const uint32_t kc2 = (uint32_t)kk * 32;
                #pragma unroll
                for (int np = 0; np < 4; np++) {
                    uint32_t vh4[4], vl4[4];
                    const uint32_t a0 = stgb + FVHO + np*(16*144) + kc2 + ltermB;
                    ldsm_x4(vh4, a0);
                    ldsm_x4(vl4, a0 + (FVLO - FVHO));
                    mma16816(o[2*np],   pah, &vh4[0]);
                    mma16816(o[2*np+1], pah, &vh4[2]);
                    mma16816(o[2*np],   pah, &vl4[0]);
                    mma16816(o[2*np+1], pah, &vl4[2]);
                    mma16816(o[2*np],   pal, &vh4[0]);
                    mma16816(o[2*np+1], pal, &vh4[2]);
                }
            }
        }
    }
    #undef LOADKV

    // ---- normalize + write split bf16 output ----
    {
        const float inv0 = 1.0f / l0, inv1 = 1.0f / l1;
        const size_t rb = (size_t)(b*SEQ + wrow + l4) * INNER_ + h*DHD;
        #pragma unroll
        for (int nt = 0; nt < 8; nt++) {
            const int col = nt*8 + c2;
            uint32_t ph, pl;
            pack_hl(o[nt][0]*inv0, o[nt][1]*inv0, ph, pl);
            *(uint32_t*)(AOH + rb + col) = ph;
            *(uint32_t*)(AOL + rb + col) = pl;
            pack_hl(o[nt][2]*inv1, o[nt][3]*inv1, ph, pl);
            *(uint32_t*)(AOH + rb + 8*INNER_ + col) = ph;
            *(uint32_t*)(AOL + rb + 8*INNER_ + col) = pl;
        }
    }
}

// ---------------------------------------------------------------------------
extern "C" void kernel_launch(void* const* d_in, const int* in_sizes, int n_in,
                              void* d_out, int out_size)
{
    const float* x       = (const float*)d_in[0];
    const float* Wq      = (const float*)d_in[1];
    const float* Wkv     = (const float*)d_in[2];
    const float* Wout    = (const float*)d_in[3];
    const float* bout    = (const float*)d_in[4];
    const float* rel_emb = (const float*)d_in[5];
    float* out = (float*)d_out;

    void* p;
    cudaGetSymbolAddress(&p, g_kv);   float* kvp = (float*)p;
    cudaGetSymbolAddress(&p, g_qh);   __nv_bfloat16* qh  = (__nv_bfloat16*)p;
    cudaGetSymbolAddress(&p, g_ql);   __nv_bfloat16* ql  = (__nv_bfloat16*)p;
    cudaGetSymbolAddress(&p, g_kh);   __nv_bfloat16* kh  = (__nv_bfloat16*)p;
    cudaGetSymbolAddress(&p, g_kl);   __nv_bfloat16* kl  = (__nv_bfloat16*)p;
    cudaGetSymbolAddress(&p, g_vth);  __nv_bfloat16* vth = (__nv_bfloat16*)p;
    cudaGetSymbolAddress(&p, g_vtl);  __nv_bfloat16* vtl = (__nv_bfloat16*)p;
    cudaGetSymbolAddress(&p, g_aoh);  __nv_bfloat16* aoh = (__nv_bfloat16*)p;
    cudaGetSymbolAddress(&p, g_aol);  __nv_bfloat16* aol = (__nv_bfloat16*)p;
    cudaGetSymbolAddress(&p, g_xh);   __nv_bfloat16* xh  = (__nv_bfloat16*)p;
    cudaGetSymbolAddress(&p, g_xl);   __nv_bfloat16* xl  = (__nv_bfloat16*)p;
    cudaGetSymbolAddress(&p, g_wcth); __nv_bfloat16* wch = (__nv_bfloat16*)p;
    cudaGetSymbolAddress(&p, g_wctl); __nv_bfloat16* wcl = (__nv_bfloat16*)p;
    cudaGetSymbolAddress(&p, g_woth); __nv_bfloat16* woh = (__nv_bfloat16*)p;
    cudaGetSymbolAddress(&p, g_wotl); __nv_bfloat16* wol = (__nv_bfloat16*)p;

    cudaFuncSetAttribute(gemm_mma<0>, cudaFuncAttributeMaxDynamicSharedMemorySize, GEMM_SMEM);
    cudaFuncSetAttribute(gemm_mma<1>, cudaFuncAttributeMaxDynamicSharedMemorySize, GEMM_SMEM);
    cudaFuncSetAttribute(flash2, cudaFuncAttributeMaxDynamicSharedMemorySize, FLASH_SMEM);

    dim3 tb(32, 8);
    // weight prep (Wq pre-scaled by dim_head^-0.5 * log2e for exp2-domain softmax)
    transpose_split_kernel<<<dim3(INNER_/32, DIMM/32), tb>>>(Wq,  wch, wcl, DIMM, INNER_, 0.125f * LOG2E);
    transpose_split_kernel<<<dim3((2*DHD)/32, DIMM/32), tb>>>(Wkv, wch + (size_t)INNER_*DIMM,
                                                              wcl + (size_t)INNER_*DIMM, DIMM, 2*DHD, 1.0f);
    transpose_split_kernel<<<dim3(DIMM/32, INNER_/32), tb>>>(Wout, woh, wol, INNER_, DIMM, 1.0f);
    split_kernel<<<(ROWS*DIMM/4 + 255)/256, 256>>>(x, xh, xl, ROWS*DIMM/4);

    // fused q|kv projection: writes q as split bf16, kv as fp32
    gemm_mma<1><<<dim3(9, ROWS/128), 256, GEMM_SMEM>>>(xh, xl, wch, wcl,
                                                       nullptr, nullptr, 0, qh, ql, kvp);
    // kv -> split K + transposed split V
    kvsplit_kernel<<<dim3(SEQ/64, BATCH), 256>>>(kvp, kh, kl, vth, vtl);
    // attention
    flash2<<<dim3(SEQ/128, HEADS, BATCH), 256, FLASH_SMEM>>>(qh, ql, kh, kl, vth, vtl,
                                                             rel_emb, aoh, aol);
    // out = ao @ Wout + bout
    gemm_mma<0><<<dim3(DIMM/128, ROWS/128), 256, GEMM_SMEM>>>(aoh, aol, woh, wol,
                                                              out, bout, DIMM,
                                                              nullptr, nullptr, nullptr);
}

// round 8
// speedup vs baseline: 1.1125x; 1.0048x over previous
#include <cuda_runtime.h>
#include <cuda_bf16.h>
#include <math.h>
#include <stdint.h>

#define BATCH 2
#define SEQ   2048
#define DIMM  1024
#define HEADS 16
#define DHD   64
#define INNER_ (HEADS*DHD)      // 1024
#define ROWS  (BATCH*SEQ)       // 4096
#define KDIM  1024
#define LOG2E 1.4426950408889634f

// ---------------- scratch (no cudaMalloc allowed) ----------------
__device__ __align__(256) float g_kv[ROWS*2*DHD];
__device__ __align__(256) __nv_bfloat16 g_qh [ROWS*INNER_];
__device__ __align__(256) __nv_bfloat16 g_ql [ROWS*INNER_];
__device__ __align__(256) __nv_bfloat16 g_kh [BATCH*SEQ*DHD];
__device__ __align__(256) __nv_bfloat16 g_kl [BATCH*SEQ*DHD];
__device__ __align__(256) __nv_bfloat16 g_vth[BATCH*DHD*SEQ];
__device__ __align__(256) __nv_bfloat16 g_vtl[BATCH*DHD*SEQ];
__device__ __align__(256) __nv_bfloat16 g_aoh[ROWS*INNER_];
__device__ __align__(256) __nv_bfloat16 g_aol[ROWS*INNER_];
__device__ __align__(256) __nv_bfloat16 g_xh [ROWS*DIMM];
__device__ __align__(256) __nv_bfloat16 g_xl [ROWS*DIMM];
__device__ __align__(256) __nv_bfloat16 g_wcth[(INNER_+2*DHD)*DIMM];
__device__ __align__(256) __nv_bfloat16 g_wctl[(INNER_+2*DHD)*DIMM];
__device__ __align__(256) __nv_bfloat16 g_woth[DIMM*INNER_];
__device__ __align__(256) __nv_bfloat16 g_wotl[DIMM*INNER_];

// ---------------- helpers ----------------
__device__ __forceinline__ uint32_t s2u(const void* p) {
    uint32_t a;
    asm("{ .reg .u64 t; cvta.to.shared.u64 t, %1; cvt.u32.u64 %0, t; }"
        : "=r"(a) : "l"(p));
    return a;
}
__device__ __forceinline__ void cp16(uint32_t dst, const void* src) {
    asm volatile("cp.async.cg.shared.global [%0], [%1], 16;" :: "r"(dst), "l"(src));
}
__device__ __forceinline__ void cp_commit() { asm volatile("cp.async.commit_group;" ::: "memory"); }

__device__ __forceinline__ void mma16816(float c[4], const uint32_t a[4], const uint32_t b[2]) {
    asm volatile("mma.sync.aligned.m16n8k16.row.col.f32.bf16.bf16.f32 "
        "{%0,%1,%2,%3}, {%4,%5,%6,%7}, {%8,%9}, {%0,%1,%2,%3};"
        : "+f"(c[0]), "+f"(c[1]), "+f"(c[2]), "+f"(c[3])
        : "r"(a[0]), "r"(a[1]), "r"(a[2]), "r"(a[3]), "r"(b[0]), "r"(b[1]));
}

// ldmatrix x4: 4 8x8 b16 matrices; lane i supplies row addr for matrix i/8.
__device__ __forceinline__ void ldsm_x4(uint32_t r[4], uint32_t saddr) {
    asm volatile("ldmatrix.sync.aligned.m8n8.x4.shared.b16 {%0,%1,%2,%3}, [%4];"
        : "=r"(r[0]), "=r"(r[1]), "=r"(r[2]), "=r"(r[3]) : "r"(saddr));
}

// pack two floats into bf16x2 hi + bf16x2 lo (residual)
__device__ __forceinline__ void pack_hl(float a, float b, uint32_t& h, uint32_t& l) {
    __nv_bfloat16 ha = __float2bfloat16(a), hb = __float2bfloat16(b);
    __nv_bfloat16 la = __float2bfloat16(a - __bfloat162float(ha));
    __nv_bfloat16 lb = __float2bfloat16(b - __bfloat162float(hb));
    __nv_bfloat162 hh = __halves2bfloat162(ha, hb);
    __nv_bfloat162 ll = __halves2bfloat162(la, lb);
    h = *reinterpret_cast<uint32_t*>(&hh);
    l = *reinterpret_cast<uint32_t*>(&ll);
}

// ---------------------------------------------------------------------------
// Prep kernels
// ---------------------------------------------------------------------------
__global__ __launch_bounds__(256) void split_kernel(
    const float* __restrict__ A, __nv_bfloat16* __restrict__ H,
    __nv_bfloat16* __restrict__ L, int n4)
{
    int i = blockIdx.x * blockDim.x + threadIdx.x;
    if (i >= n4) return;
    float4 a = ((const float4*)A)[i];
    uint32_t h01, l01, h23, l23;
    pack_hl(a.x, a.y, h01, l01);
    pack_hl(a.z, a.w, h23, l23);
    ((uint32_t*)H)[2*i]   = h01; ((uint32_t*)H)[2*i+1] = h23;
    ((uint32_t*)L)[2*i]   = l01; ((uint32_t*)L)[2*i+1] = l23;
}

__global__ __launch_bounds__(256) void transpose_split_kernel(
    const float* __restrict__ W, __nv_bfloat16* __restrict__ TH,
    __nv_bfloat16* __restrict__ TL, int K, int N, float scale)
{
    __shared__ float tile[32][33];
    const int tx = threadIdx.x, ty = threadIdx.y;
    const int n0 = blockIdx.x * 32, k0 = blockIdx.y * 32;
    #pragma unroll
    for (int i = 0; i < 4; i++)
        tile[ty + 8*i][tx] = W[(size_t)(k0 + ty + 8*i) * N + n0 + tx];
    __syncthreads();
    #pragma unroll
    for (int i = 0; i < 4; i++) {
        float a = tile[tx][ty + 8*i] * scale;
        __nv_bfloat16 h = __float2bfloat16(a);
        __nv_bfloat16 l = __float2bfloat16(a - __bfloat162float(h));
        size_t o = (size_t)(n0 + ty + 8*i) * K + k0 + tx;
        TH[o] = h; TL[o] = l;
    }
}

__global__ __launch_bounds__(256) void kvsplit_kernel(
    const float* __restrict__ KVin,
    __nv_bfloat16* __restrict__ KH, __nv_bfloat16* __restrict__ KL,
    __nv_bfloat16* __restrict__ VTH, __nv_bfloat16* __restrict__ VTL)
{
    __shared__ float vt[64][65];
    const int b = blockIdx.y, j0 = blockIdx.x * 64;
    const int tid = threadIdx.x;
    const int j = tid >> 2, g = (tid & 3) * 16;
    const float* rp = KVin + (size_t)(b*SEQ + j0 + j) * (2*DHD);
    #pragma unroll
    for (int c = 0; c < 4; c++) {
        float4 kq = *(const float4*)(rp + g + c*4);
        uint32_t h01, l01, h23, l23;
        pack_hl(kq.x, kq.y, h01, l01);
        pack_hl(kq.z, kq.w, h23, l23);
        size_t ko = (size_t)(b*SEQ + j0 + j)*DHD + g + c*4;
        *(uint32_t*)(KH + ko) = h01; *(uint32_t*)(KH + ko + 2) = h23;
        *(uint32_t*)(KL + ko) = l01; *(uint32_t*)(KL + ko + 2) = l23;
        float4 vq = *(const float4*)(rp + DHD + g + c*4);
        vt[j][g + c*4 + 0] = vq.x; vt[j][g + c*4 + 1] = vq.y;
        vt[j][g + c*4 + 2] = vq.z; vt[j][g + c*4 + 3] = vq.w;
    }
    __syncthreads();
    const int d = tid >> 2, jg = (tid & 3) * 16;
    #pragma unroll
    for (int i = 0; i < 16; i += 2) {
        float a = vt[jg + i][d], bb = vt[jg + i + 1][d];
        uint32_t h, l; pack_hl(a, bb, h, l);
        size_t vo = (size_t)(b*DHD + d)*SEQ + j0 + jg + i;
        *(uint32_t*)(VTH + vo) = h;
        *(uint32_t*)(VTL + vo) = l;
    }
}

// ---------------------------------------------------------------------------
// HMMA GEMM: CTA 128x128, BK=32, 2-stage cp.async, 8 warps x 32x64.
// ldmatrix fragment loads + Bh-reuse pass order (Ah*Bh, Al*Bh, Ah*Bl).
// ---------------------------------------------------------------------------
#define GBK 32
#define GNSTG (KDIM/GBK)
#define GSTRIDE 40                  // elements; 80 bytes/row
#define GMATB (128*GSTRIDE*2)
#define GSTGB (4*GMATB)
#define GEMM_SMEM (2*GSTGB)

template<int MODE>
__global__ __launch_bounds__(256) void gemm_mma(
    const __nv_bfloat16* __restrict__ Ah, const __nv_bfloat16* __restrict__ Al,
    const __nv_bfloat16* __restrict__ Bh, const __nv_bfloat16* __restrict__ Bl,
    float* __restrict__ C, const float* __restrict__ bias, int Ncols,
    __nv_bfloat16* __restrict__ CH, __nv_bfloat16* __restrict__ CL,
    float* __restrict__ C2)
{
    extern __shared__ __align__(16) char smem[];
    const uint32_t sbuf = s2u(smem);
    const int tid = threadIdx.x, wid = tid >> 5, lane = tid & 31;
    const int l4 = lane >> 2, c2 = (lane & 3) * 2;
    const int wm = wid & 3, wn = wid >> 2;
    const int bn = blockIdx.x, bm = blockIdx.y;

    const uint32_t ltermB = ((lane & 7) + ((lane >> 4) << 3)) * (GSTRIDE*2)
                          + (((lane >> 3) & 1) << 4);
    const uint32_t ltermA = ((lane & 7) + (((lane >> 3) & 1) << 3)) * (GSTRIDE*2)
                          + (((lane >> 4) & 1) << 4);

    const __nv_bfloat16* pA[2] = { Ah + (size_t)(bm*128)*KDIM, Al + (size_t)(bm*128)*KDIM };
    const __nv_bfloat16* pB[2] = { Bh + (size_t)(bn*128)*KDIM, Bl + (size_t)(bn*128)*KDIM };

    const int r0 = tid >> 2, kc = tid & 3;
    const int r1 = r0 + 64;

    float acc[2][8][4];
    #pragma unroll
    for (int i = 0; i < 2; i++)
        #pragma unroll
        for (int j = 0; j < 8; j++)
            #pragma unroll
            for (int e = 0; e < 4; e++) acc[i][j][e] = 0.f;

    #define G_LOAD(S) do { \
        const int _k0 = (S) * GBK; \
        const uint32_t stb = sbuf + ((S) & 1) * GSTGB; \
        _Pragma("unroll") \
        for (int m = 0; m < 2; m++) { \
            cp16(stb + m*GMATB     + r0*80 + kc*16, pA[m] + (size_t)r0*KDIM + _k0 + kc*8); \
            cp16(stb + m*GMATB     + r1*80 + kc*16, pA[m] + (size_t)r1*KDIM + _k0 + kc*8); \
            cp16(stb + (m+2)*GMATB + r0*80 + kc*16, pB[m] + (size_t)r0*KDIM + _k0 + kc*8); \
            cp16(stb + (m+2)*GMATB + r1*80 + kc*16, pB[m] + (size_t)r1*KDIM + _k0 + kc*8); \
        } \
    } while (0)

    G_LOAD(0); cp_commit();

    for (int s = 0; s < GNSTG; s++) {
        if (s + 1 < GNSTG) {
            G_LOAD(s + 1); cp_commit();
            asm volatile("cp.async.wait_group 1;" ::: "memory");
        } else {
            asm volatile("cp.async.wait_group 0;" ::: "memory");
        }
        __syncthreads();

        const uint32_t stb = sbuf + (s & 1) * GSTGB;
        const uint32_t aBaseH = stb            + (wm*32)*80 + ltermA;
        const uint32_t aBaseL = stb + GMATB    + (wm*32)*80 + ltermA;
        const uint32_t bBaseH = stb + 2*GMATB  + (wn*64)*80 + ltermB;
        const uint32_t bBaseL = stb + 3*GMATB  + (wn*64)*80 + ltermB;

        #pragma unroll
        for (int k16 = 0; k16 < 2; k16++) {
            const uint32_t kc2 = (uint32_t)k16 * 32;
            uint32_t ah[2][4], al[2][4], bb[4][4];
            #pragma unroll
            for (int mt = 0; mt < 2; mt++) ldsm_x4(ah[mt], aBaseH + mt*(16*80) + kc2);
            #pragma unroll
            for (int np = 0; np < 4; np++) ldsm_x4(bb[np], bBaseH + np*(16*80) + kc2);
            #pragma unroll
            for (int mt = 0; mt < 2; mt++)
                #pragma unroll
                for (int np = 0; np < 4; np++) {
                    mma16816(acc[mt][2*np],   ah[mt], &bb[np][0]);
                    mma16816(acc[mt][2*np+1], ah[mt], &bb[np][2]);
                }
            #pragma unroll
            for (int mt = 0; mt < 2; mt++) ldsm_x4(al[mt], aBaseL + mt*(16*80) + kc2);
            #pragma unroll
            for (int mt = 0; mt < 2; mt++)
                #pragma unroll
                for (int np = 0; np < 4; np++) {
                    mma16816(acc[mt][2*np],   al[mt], &bb[np][0]);
                    mma16816(acc[mt][2*np+1], al[mt], &bb[np][2]);
                }
            #pragma unroll
            for (int np = 0; np < 4; np++) ldsm_x4(bb[np], bBaseL + np*(16*80) + kc2);
            #pragma unroll
            for (int mt = 0; mt < 2; mt++)
                #pragma unroll
                for (int np = 0; np < 4; np++) {
                    mma16816(acc[mt][2*np],   ah[mt], &bb[np][0]);
                    mma16816(acc[mt][2*np+1], ah[mt], &bb[np][2]);
                }
        }
        __syncthreads();
    }
    #undef G_LOAD

    #pragma unroll
    for (int mt = 0; mt < 2; mt++) {
        const int rg0 = bm*128 + wm*32 + mt*16 + l4;
        #pragma unroll
        for (int nt = 0; nt < 8; nt++) {
            const int cg = bn*128 + wn*64 + nt*8 + c2;
            if (MODE == 0) {
                float b0 = bias ? bias[cg] : 0.f;
                float b1 = bias ? bias[cg+1] : 0.f;
                float2 v0 = { acc[mt][nt][0] + b0, acc[mt][nt][1] + b1 };
                float2 v1 = { acc[mt][nt][2] + b0, acc[mt][nt][3] + b1 };
                *(float2*)(C + (size_t)rg0*Ncols + cg)     = v0;
                *(float2*)(C + (size_t)(rg0+8)*Ncols + cg) = v1;
            } else {
                if (bn < 8) {
                    uint32_t h0, l0v, h1, l1v;
                    pack_hl(acc[mt][nt][0], acc[mt][nt][1], h0, l0v);
                    pack_hl(acc[mt][nt][2], acc[mt][nt][3], h1, l1v);
                    *(uint32_t*)(CH + (size_t)rg0*INNER_ + cg)     = h0;
                    *(uint32_t*)(CL + (size_t)rg0*INNER_ + cg)     = l0v;
                    *(uint32_t*)(CH + (size_t)(rg0+8)*INNER_ + cg) = h1;
                    *(uint32_t*)(CL + (size_t)(rg0+8)*INNER_ + cg) = l1v;
                } else {
                    const int cc = cg - 1024;
                    float2 v0 = { acc[mt][nt][0], acc[mt][nt][1] };
                    float2 v1 = { acc[mt][nt][2], acc[mt][nt][3] };
                    *(float2*)(C2 + (size_t)rg0*(2*DHD) + cc)     = v0;
                    *(float2*)(C2 + (size_t)(rg0+8)*(2*DHD) + cc) = v1;
                }
            }
        }
    }
}

// ---------------------------------------------------------------------------
// T5 relative-position bucket (mirrors jax fp32 math)
// ---------------------------------------------------------------------------
__device__ __forceinline__ int rel_bucket(int nn) {
    if (nn < 16) return nn;
    float t = logf((float)nn * (1.0f/16.0f)) / 2.0794415416798357f * 16.0f;
    int v = 16 + (int)t;
    return v < 31 ? v : 31;
}

// ---------------------------------------------------------------------------
// Flash attention v4: product-major mma ordering (accumulator reuse distance 8),
// 3-stage cp.async ring, ldmatrix frags, exp2-domain softmax.
// Grid (SEQ/128, HEADS, BATCH), 256 threads = 8 warps (warp w -> 16 rows).
// ---------------------------------------------------------------------------
#define FSTRIDE 72                  // elements; 144 bytes/row
#define FTILE   (64*FSTRIDE*2)      // 9216 bytes per tile
#define FKHO 0
#define FKLO (1*FTILE)
#define FVHO (2*FTILE)
#define FVLO (3*FTILE)
#define FSTG (4*FTILE)              // 36864 per stage
#define FBIAS (3*FSTG)              // 110592
#define FLASH_SMEM (FBIAS + 2048*4) // 118784

__global__ __launch_bounds__(256) void flash2(
    const __nv_bfloat16* __restrict__ QH, const __nv_bfloat16* __restrict__ QL,
    const __nv_bfloat16* __restrict__ KH, const __nv_bfloat16* __restrict__ KL,
    const __nv_bfloat16* __restrict__ VTH, const __nv_bfloat16* __restrict__ VTL,
    const float* __restrict__ rel_emb,
    __nv_bfloat16* __restrict__ AOH, __nv_bfloat16* __restrict__ AOL)
{
    extern __shared__ __align__(16) char smem[];
    const uint32_t sb = s2u(smem);
    float* biasv = (float*)(smem + FBIAS);

    const int qtb = (SEQ/128 - 1) - blockIdx.x;     // heavy CTAs first
    const int h = blockIdx.y, b = blockIdx.z;
    const int tid = threadIdx.x, lane = tid & 31, w = tid >> 5;
    const int l4 = lane >> 2, c2 = (lane & 3) * 2;
    const int i0 = qtb * 128;
    const int wrow = i0 + w * 16;

    const uint32_t ltermB = ((lane & 7) + ((lane >> 4) << 3)) * (FSTRIDE*2)
                          + (((lane >> 3) & 1) << 4);

    for (int nn = tid; nn < 2048; nn += 256)
        biasv[nn] = rel_emb[rel_bucket(nn)*HEADS + h] * (8.0f * LOG2E);

    uint32_t qhf[4][4], qlf[4][4];
    {
        const size_t rb = (size_t)(b*SEQ + wrow + l4) * INNER_ + h*DHD;
        #pragma unroll
        for (int k16 = 0; k16 < 4; k16++) {
            const int c = k16*16 + c2;
            qhf[k16][0] = *(const uint32_t*)(QH + rb + c);
            qhf[k16][1] = *(const uint32_t*)(QH + rb + 8*INNER_ + c);
            qhf[k16][2] = *(const uint32_t*)(QH + rb + c + 8);
            qhf[k16][3] = *(const uint32_t*)(QH + rb + 8*INNER_ + c + 8);
            qlf[k16][0] = *(const uint32_t*)(QL + rb + c);
            qlf[k16][1] = *(const uint32_t*)(QL + rb + 8*INNER_ + c);
            qlf[k16][2] = *(const uint32_t*)(QL + rb + c + 8);
            qlf[k16][3] = *(const uint32_t*)(QL + rb + 8*INNER_ + c + 8);
        }
    }

    float o[8][4];
    #pragma unroll
    for (int nt = 0; nt < 8; nt++)
        #pragma unroll
        for (int e = 0; e < 4; e++) o[nt][e] = 0.f;
    float m0 = -INFINITY, m1 = -INFINITY, l0 = 0.f, l1 = 0.f;

    const int jmax = (i0 + 127) >> 6;
    const int iwmax = wrow + 15;

    #define LOADKV(JT, S) do { \
        const int _j0 = (JT) * 64; \
        const uint32_t _sb = sb + (uint32_t)(S) * FSTG; \
        _Pragma("unroll") \
        for (int q = 0; q < 2; q++) { \
            const int id = tid*2 + q; \
            const int r = id >> 3, cc = id & 7; \
            const uint32_t so = (uint32_t)(r*144 + cc*16); \
            const size_t ksrc = (size_t)(b*SEQ + _j0 + r)*DHD + cc*8; \
            const size_t vsrc = (size_t)(b*DHD + r)*SEQ + _j0 + cc*8; \
            cp16(_sb + FKHO + so, KH  + ksrc); \
            cp16(_sb + FKLO + so, KL  + ksrc); \
            cp16(_sb + FVHO + so, VTH + vsrc); \
            cp16(_sb + FVLO + so, VTL + vsrc); \
        } \
    } while (0)

    LOADKV(0, 0); cp_commit();
    LOADKV(1, 1); cp_commit();

    for (int jt = 0; jt <= jmax; jt++) {
        asm volatile("cp.async.wait_group 1;" ::: "memory");
        __syncthreads();
        if (jt + 2 <= jmax) LOADKV(jt + 2, (jt + 2) % 3);
        cp_commit();

        const int j0 = jt * 64;
        if (j0 <= iwmax) {
            const uint32_t stgb = sb + (uint32_t)(jt % 3) * FSTG;

            // ---- S = Q K^T, product-major: all 8 accumulators between reuses ----
            float s[8][4];
            #pragma unroll
            for (int nt = 0; nt < 8; nt++)
                #pragma unroll
                for (int e = 0; e < 4; e++) s[nt][e] = 0.f;

            #pragma unroll
            for (int k16 = 0; k16 < 4; k16++) {
                const uint32_t kc2 = (uint32_t)k16 * 32;
                uint32_t kh4[4][4], kl4[4][4];
                #pragma unroll
                for (int np = 0; np < 4; np++) {
                    const uint32_t a0 = stgb + FKHO + np*(16*144) + kc2 + ltermB;
                    ldsm_x4(kh4[np], a0);
                    ldsm_x4(kl4[np], a0 + (FKLO - FKHO));
                }
                #pragma unroll
                for (int np = 0; np < 4; np++) {
                    mma16816(s[2*np],   qhf[k16], &kh4[np][0]);
                    mma16816(s[2*np+1], qhf[k16], &kh4[np][2]);
                }
                #pragma unroll
                for (int np = 0; np < 4; np++) {
                    mma16816(s[2*np],   qhf[k16], &kl4[np][0]);
                    mma16816(s[2*np+1], qhf[k16], &kl4[np][2]);
                }
                #pragma unroll
                for (int np = 0; np < 4; np++) {
                    mma16816(s[2*np],   qlf[k16], &kh4[np][0]);
                    mma16816(s[2*np+1], qlf[k16], &kh4[np][2]);
                }
            }

            // ---- bias + causal mask (log2 domain) ----
            const bool masked = (j0 + 63 > wrow);
            const int irow0 = wrow + l4;
            #pragma unroll
            for (int nt = 0; nt < 8; nt++) {
                #pragma unroll
                for (int e = 0; e < 4; e++) {
                    const int ri = irow0 + ((e >> 1) << 3);
                    const int cj = j0 + nt*8 + c2 + (e & 1);
                    const int nn = ri - cj;
                    if (masked && nn < 0) s[nt][e] = -INFINITY;
                    else                  s[nt][e] += biasv[nn];
                }
            }

            // ---- warp-local online softmax (exp2 domain) ----
            float mc0 = -INFINITY, mc1 = -INFINITY;
            #pragma unroll
            for (int nt = 0; nt < 8; nt++) {
                mc0 = fmaxf(mc0, fmaxf(s[nt][0], s[nt][1]));
                mc1 = fmaxf(mc1, fmaxf(s[nt][2], s[nt][3]));
            }
            mc0 = fmaxf(mc0, __shfl_xor_sync(0xffffffffu, mc0, 1));
            mc0 = fmaxf(mc0, __shfl_xor_sync(0xffffffffu, mc0, 2));
            mc1 = fmaxf(mc1, __shfl_xor_sync(0xffffffffu, mc1, 1));
            mc1 = fmaxf(mc1, __shfl_xor_sync(0xffffffffu, mc1, 2));
            const float mn0 = fmaxf(m0, mc0), mn1 = fmaxf(m1, mc1);
            const float sc0 = exp2f(m0 - mn0), sc1 = exp2f(m1 - mn1);
            m0 = mn0; m1 = mn1;

            float rs0 = 0.f, rs1 = 0.f;
            #pragma unroll
            for (int nt = 0; nt < 8; nt++) {
                s[nt][0] = exp2f(s[nt][0] - mn0);
                s[nt][1] = exp2f(s[nt][1] - mn0);
                s[nt][2] = exp2f(s[nt][2] - mn1);
                s[nt][3] = exp2f(s[nt][3] - mn1);
                rs0 += s[nt][0] + s[nt][1];
                rs1 += s[nt][2] + s[nt][3];
            }
            rs0 += __shfl_xor_sync(0xffffffffu, rs0, 1);
            rs0 += __shfl_xor_sync(0xffffffffu, rs0, 2);
            rs1 += __shfl_xor_sync(0xffffffffu, rs1, 1);
            rs1 += __shfl_xor_sync(0xffffffffu, rs1, 2);
            l0 = l0*sc0 + rs0;
            l1 = l1*sc1 + rs1;

            #pragma unroll
            for (int nt = 0; nt < 8; nt++) {
                o[nt][0] *= sc0; o[nt][1] *= sc0;
                o[nt][2] *= sc1; o[nt][3] *= sc1;
            }

            // ---- O += P V, product-major ordering ----
            #pragma unroll
            for (int kk = 0; kk < 4; kk++) {
                uint32_t pah[4], pal[4];
                pack_hl(s[2*kk  ][0], s[2*kk  ][1], pah[0], pal[0]);
                pack_hl(s[2*kk  ][2], s[2*kk  ][3], pah[1], pal[1]);
                pack_hl(s[2*kk+1][0], s[2*kk+1][1], pah[2], pal[2]);
                pack_hl(s[2*kk+1][2], s[2*kk+1][3], pah[3], pal[3]);
                const uint32_t kc2 = (uint32_t)kk * 32;
                uint32_t vh4[4][4], vl4[4][4];
                #pragma unroll
                for (int np = 0; np < 4; np++) {
                    const uint32_t a0 = stgb + FVHO + np*(16*144) + kc2 + ltermB;
                    ldsm_x4(vh4[np], a0);
                    ldsm_x4(vl4[np], a0 + (FVLO - FVHO));
                }
                #pragma unroll
                for (int np = 0; np < 4; np++) {
                    mma16816(o[2*np],   pah, &vh4[np][0]);
                    mma16816(o[2*np+1], pah, &vh4[np][2]);
                }
                #pragma unroll
                for (int np = 0; np < 4; np++) {
                    mma16816(o[2*np],   pah, &vl4[np][0]);
                    mma16816(o[2*np+1], pah, &vl4[np][2]);
                }
                #pragma unroll
                for (int np = 0; np < 4; np++) {
                    mma16816(o[2*np],   pal, &vh4[np][0]);
                    mma16816(o[2*np+1], pal, &vh4[np][2]);
                }
            }
        }
    }
    #undef LOADKV

    // ---- normalize + write split bf16 output ----
    {
        const float inv0 = 1.0f / l0, inv1 = 1.0f / l1;
        const size_t rb = (size_t)(b*SEQ + wrow + l4) * INNER_ + h*DHD;
        #pragma unroll
        for (int nt = 0; nt < 8; nt++) {
            const int col = nt*8 + c2;
            uint32_t ph, pl;
            pack_hl(o[nt][0]*inv0, o[nt][1]*inv0, ph, pl);
            *(uint32_t*)(AOH + rb + col) = ph;
            *(uint32_t*)(AOL + rb + col) = pl;
            pack_hl(o[nt][2]*inv1, o[nt][3]*inv1, ph, pl);
            *(uint32_t*)(AOH + rb + 8*INNER_ + col) = ph;
            *(uint32_t*)(AOL + rb + 8*INNER_ + col) = pl;
        }
    }
}

// ---------------------------------------------------------------------------
extern "C" void kernel_launch(void* const* d_in, const int* in_sizes, int n_in,
                              void* d_out, int out_size)
{
    const float* x       = (const float*)d_in[0];
    const float* Wq      = (const float*)d_in[1];
    const float* Wkv     = (const float*)d_in[2];
    const float* Wout    = (const float*)d_in[3];
    const float* bout    = (const float*)d_in[4];
    const float* rel_emb = (const float*)d_in[5];
    float* out = (float*)d_out;

    void* p;
    cudaGetSymbolAddress(&p, g_kv);   float* kvp = (float*)p;
    cudaGetSymbolAddress(&p, g_qh);   __nv_bfloat16* qh  = (__nv_bfloat16*)p;
    cudaGetSymbolAddress(&p, g_ql);   __nv_bfloat16* ql  = (__nv_bfloat16*)p;
    cudaGetSymbolAddress(&p, g_kh);   __nv_bfloat16* kh  = (__nv_bfloat16*)p;
    cudaGetSymbolAddress(&p, g_kl);   __nv_bfloat16* kl  = (__nv_bfloat16*)p;
    cudaGetSymbolAddress(&p, g_vth);  __nv_bfloat16* vth = (__nv_bfloat16*)p;
    cudaGetSymbolAddress(&p, g_vtl);  __nv_bfloat16* vtl = (__nv_bfloat16*)p;
    cudaGetSymbolAddress(&p, g_aoh);  __nv_bfloat16* aoh = (__nv_bfloat16*)p;
    cudaGetSymbolAddress(&p, g_aol);  __nv_bfloat16* aol = (__nv_bfloat16*)p;
    cudaGetSymbolAddress(&p, g_xh);   __nv_bfloat16* xh  = (__nv_bfloat16*)p;
    cudaGetSymbolAddress(&p, g_xl);   __nv_bfloat16* xl  = (__nv_bfloat16*)p;
    cudaGetSymbolAddress(&p, g_wcth); __nv_bfloat16* wch = (__nv_bfloat16*)p;
    cudaGetSymbolAddress(&p, g_wctl); __nv_bfloat16* wcl = (__nv_bfloat16*)p;
    cudaGetSymbolAddress(&p, g_woth); __nv_bfloat16* woh = (__nv_bfloat16*)p;
    cudaGetSymbolAddress(&p, g_wotl); __nv_bfloat16* wol = (__nv_bfloat16*)p;

    cudaFuncSetAttribute(gemm_mma<0>, cudaFuncAttributeMaxDynamicSharedMemorySize, GEMM_SMEM);
    cudaFuncSetAttribute(gemm_mma<1>, cudaFuncAttributeMaxDynamicSharedMemorySize, GEMM_SMEM);
    cudaFuncSetAttribute(flash2, cudaFuncAttributeMaxDynamicSharedMemorySize, FLASH_SMEM);

    dim3 tb(32, 8);
    transpose_split_kernel<<<dim3(INNER_/32, DIMM/32), tb>>>(Wq,  wch, wcl, DIMM, INNER_, 0.125f * LOG2E);
    transpose_split_kernel<<<dim3((2*DHD)/32, DIMM/32), tb>>>(Wkv, wch + (size_t)INNER_*DIMM,
                                                              wcl + (size_t)INNER_*DIMM, DIMM, 2*DHD, 1.0f);
    transpose_split_kernel<<<dim3(DIMM/32, INNER_/32), tb>>>(Wout, woh, wol, INNER_, DIMM, 1.0f);
    split_kernel<<<(ROWS*DIMM/4 + 255)/256, 256>>>(x, xh, xl, ROWS*DIMM/4);

    gemm_mma<1><<<dim3(9, ROWS/128), 256, GEMM_SMEM>>>(xh, xl, wch, wcl,
                                                       nullptr, nullptr, 0, qh, ql, kvp);
    kvsplit_kernel<<<dim3(SEQ/64, BATCH), 256>>>(kvp, kh, kl, vth, vtl);
    flash2<<<dim3(SEQ/128, HEADS, BATCH), 256, FLASH_SMEM>>>(qh, ql, kh, kl, vth, vtl,
                                                             rel_emb, aoh, aol);
    gemm_mma<0><<<dim3(DIMM/128, ROWS/128), 256, GEMM_SMEM>>>(aoh, aol, woh, wol,
                                                              out, bout, DIMM,
                                                              nullptr, nullptr, nullptr);
}

// round 9
// speedup vs baseline: 1.2664x; 1.1384x over previous
#include <cuda_runtime.h>
#include <cuda_bf16.h>
#include <cuda_fp16.h>
#include <math.h>
#include <stdint.h>

#define BATCH 2
#define SEQ   2048
#define DIMM  1024
#define HEADS 16
#define DHD   64
#define INNER_ (HEADS*DHD)      // 1024
#define ROWS  (BATCH*SEQ)       // 4096
#define KDIM  1024
#define LOG2E 1.4426950408889634f

// ---------------- scratch (no cudaMalloc allowed) ----------------
__device__ __align__(256) float g_kv[ROWS*2*DHD];
__device__ __align__(256) __nv_bfloat16 g_qh [ROWS*INNER_];
__device__ __align__(256) __nv_bfloat16 g_ql [ROWS*INNER_];
__device__ __align__(256) __nv_bfloat16 g_kh [BATCH*SEQ*DHD];
__device__ __align__(256) __nv_bfloat16 g_kl [BATCH*SEQ*DHD];
__device__ __align__(256) __half        g_vtf[BATCH*DHD*SEQ];     // transposed V, fp16
__device__ __align__(256) __nv_bfloat16 g_aoh[ROWS*INNER_];
__device__ __align__(256) __nv_bfloat16 g_aol[ROWS*INNER_];
__device__ __align__(256) __nv_bfloat16 g_xh [ROWS*DIMM];
__device__ __align__(256) __nv_bfloat16 g_xl [ROWS*DIMM];
__device__ __align__(256) __nv_bfloat16 g_wcth[(INNER_+2*DHD)*DIMM];
__device__ __align__(256) __nv_bfloat16 g_wctl[(INNER_+2*DHD)*DIMM];
__device__ __align__(256) __nv_bfloat16 g_woth[DIMM*INNER_];
__device__ __align__(256) __nv_bfloat16 g_wotl[DIMM*INNER_];

// ---------------- helpers ----------------
__device__ __forceinline__ uint32_t s2u(const void* p) {
    uint32_t a;
    asm("{ .reg .u64 t; cvta.to.shared.u64 t, %1; cvt.u32.u64 %0, t; }"
        : "=r"(a) : "l"(p));
    return a;
}
__device__ __forceinline__ void cp16(uint32_t dst, const void* src) {
    asm volatile("cp.async.cg.shared.global [%0], [%1], 16;" :: "r"(dst), "l"(src));
}
__device__ __forceinline__ void cp_commit() { asm volatile("cp.async.commit_group;" ::: "memory"); }

__device__ __forceinline__ void mma16816(float c[4], const uint32_t a[4], const uint32_t b[2]) {
    asm volatile("mma.sync.aligned.m16n8k16.row.col.f32.bf16.bf16.f32 "
        "{%0,%1,%2,%3}, {%4,%5,%6,%7}, {%8,%9}, {%0,%1,%2,%3};"
        : "+f"(c[0]), "+f"(c[1]), "+f"(c[2]), "+f"(c[3])
        : "r"(a[0]), "r"(a[1]), "r"(a[2]), "r"(a[3]), "r"(b[0]), "r"(b[1]));
}
__device__ __forceinline__ void mma16816h(float c[4], const uint32_t a[4], const uint32_t b[2]) {
    asm volatile("mma.sync.aligned.m16n8k16.row.col.f32.f16.f16.f32 "
        "{%0,%1,%2,%3}, {%4,%5,%6,%7}, {%8,%9}, {%0,%1,%2,%3};"
        : "+f"(c[0]), "+f"(c[1]), "+f"(c[2]), "+f"(c[3])
        : "r"(a[0]), "r"(a[1]), "r"(a[2]), "r"(a[3]), "r"(b[0]), "r"(b[1]));
}

// ldmatrix x4
__device__ __forceinline__ void ldsm_x4(uint32_t r[4], uint32_t saddr) {
    asm volatile("ldmatrix.sync.aligned.m8n8.x4.shared.b16 {%0,%1,%2,%3}, [%4];"
        : "=r"(r[0]), "=r"(r[1]), "=r"(r[2]), "=r"(r[3]) : "r"(saddr));
}

// pack two floats -> fp16x2 (first arg = low half)
__device__ __forceinline__ uint32_t pack_f16x2(float lo, float hi) {
    uint32_t r;
    asm("cvt.rn.f16x2.f32 %0, %1, %2;" : "=r"(r) : "f"(hi), "f"(lo));
    return r;
}

// pack two floats into bf16x2 hi + bf16x2 lo (residual)
__device__ __forceinline__ void pack_hl(float a, float b, uint32_t& h, uint32_t& l) {
    __nv_bfloat16 ha = __float2bfloat16(a), hb = __float2bfloat16(b);
    __nv_bfloat16 la = __float2bfloat16(a - __bfloat162float(ha));
    __nv_bfloat16 lb = __float2bfloat16(b - __bfloat162float(hb));
    __nv_bfloat162 hh = __halves2bfloat162(ha, hb);
    __nv_bfloat162 ll = __halves2bfloat162(la, lb);
    h = *reinterpret_cast<uint32_t*>(&hh);
    l = *reinterpret_cast<uint32_t*>(&ll);
}

// ---------------------------------------------------------------------------
// Prep kernels
// ---------------------------------------------------------------------------
__global__ __launch_bounds__(256) void split_kernel(
    const float* __restrict__ A, __nv_bfloat16* __restrict__ H,
    __nv_bfloat16* __restrict__ L, int n4)
{
    int i = blockIdx.x * blockDim.x + threadIdx.x;
    if (i >= n4) return;
    float4 a = ((const float4*)A)[i];
    uint32_t h01, l01, h23, l23;
    pack_hl(a.x, a.y, h01, l01);
    pack_hl(a.z, a.w, h23, l23);
    ((uint32_t*)H)[2*i]   = h01; ((uint32_t*)H)[2*i+1] = h23;
    ((uint32_t*)L)[2*i]   = l01; ((uint32_t*)L)[2*i+1] = l23;
}

__global__ __launch_bounds__(256) void transpose_split_kernel(
    const float* __restrict__ W, __nv_bfloat16* __restrict__ TH,
    __nv_bfloat16* __restrict__ TL, int K, int N, float scale)
{
    __shared__ float tile[32][33];
    const int tx = threadIdx.x, ty = threadIdx.y;
    const int n0 = blockIdx.x * 32, k0 = blockIdx.y * 32;
    #pragma unroll
    for (int i = 0; i < 4; i++)
        tile[ty + 8*i][tx] = W[(size_t)(k0 + ty + 8*i) * N + n0 + tx];
    __syncthreads();
    #pragma unroll
    for (int i = 0; i < 4; i++) {
        float a = tile[tx][ty + 8*i] * scale;
        __nv_bfloat16 h = __float2bfloat16(a);
        __nv_bfloat16 l = __float2bfloat16(a - __bfloat162float(h));
        size_t o = (size_t)(n0 + ty + 8*i) * K + k0 + tx;
        TH[o] = h; TL[o] = l;
    }
}

// kv: g_kv [row][128] -> Kh/Kl bf16 [b][j][64], Vtf fp16 [b][d][SEQ]
__global__ __launch_bounds__(256) void kvsplit_kernel(
    const float* __restrict__ KVin,
    __nv_bfloat16* __restrict__ KH, __nv_bfloat16* __restrict__ KL,
    __half* __restrict__ VTF)
{
    __shared__ float vt[64][65];
    const int b = blockIdx.y, j0 = blockIdx.x * 64;
    const int tid = threadIdx.x;
    const int j = tid >> 2, g = (tid & 3) * 16;
    const float* rp = KVin + (size_t)(b*SEQ + j0 + j) * (2*DHD);
    #pragma unroll
    for (int c = 0; c < 4; c++) {
        float4 kq = *(const float4*)(rp + g + c*4);
        uint32_t h01, l01, h23, l23;
        pack_hl(kq.x, kq.y, h01, l01);
        pack_hl(kq.z, kq.w, h23, l23);
        size_t ko = (size_t)(b*SEQ + j0 + j)*DHD + g + c*4;
        *(uint32_t*)(KH + ko) = h01; *(uint32_t*)(KH + ko + 2) = h23;
        *(uint32_t*)(KL + ko) = l01; *(uint32_t*)(KL + ko + 2) = l23;
        float4 vq = *(const float4*)(rp + DHD + g + c*4);
        vt[j][g + c*4 + 0] = vq.x; vt[j][g + c*4 + 1] = vq.y;
        vt[j][g + c*4 + 2] = vq.z; vt[j][g + c*4 + 3] = vq.w;
    }
    __syncthreads();
    const int d = tid >> 2, jg = (tid & 3) * 16;
    #pragma unroll
    for (int i = 0; i < 16; i += 2) {
        float a = vt[jg + i][d], bb = vt[jg + i + 1][d];
        size_t vo = (size_t)(b*DHD + d)*SEQ + j0 + jg + i;
        *(__half2*)(VTF + vo) = __floats2half2_rn(a, bb);
    }
}

// ---------------------------------------------------------------------------
// HMMA GEMM (unchanged from round 8)
// ---------------------------------------------------------------------------
#define GBK 32
#define GNSTG (KDIM/GBK)
#define GSTRIDE 40
#define GMATB (128*GSTRIDE*2)
#define GSTGB (4*GMATB)
#define GEMM_SMEM (2*GSTGB)

template<int MODE>
__global__ __launch_bounds__(256) void gemm_mma(
    const __nv_bfloat16* __restrict__ Ah, const __nv_bfloat16* __restrict__ Al,
    const __nv_bfloat16* __restrict__ Bh, const __nv_bfloat16* __restrict__ Bl,
    float* __restrict__ C, const float* __restrict__ bias, int Ncols,
    __nv_bfloat16* __restrict__ CH, __nv_bfloat16* __restrict__ CL,
    float* __restrict__ C2)
{
    extern __shared__ __align__(16) char smem[];
    const uint32_t sbuf = s2u(smem);
    const int tid = threadIdx.x, wid = tid >> 5, lane = tid & 31;
    const int l4 = lane >> 2, c2 = (lane & 3) * 2;
    const int wm = wid & 3, wn = wid >> 2;
    const int bn = blockIdx.x, bm = blockIdx.y;

    const uint32_t ltermB = ((lane & 7) + ((lane >> 4) << 3)) * (GSTRIDE*2)
                          + (((lane >> 3) & 1) << 4);
    const uint32_t ltermA = ((lane & 7) + (((lane >> 3) & 1) << 3)) * (GSTRIDE*2)
                          + (((lane >> 4) & 1) << 4);

    const __nv_bfloat16* pA[2] = { Ah + (size_t)(bm*128)*KDIM, Al + (size_t)(bm*128)*KDIM };
    const __nv_bfloat16* pB[2] = { Bh + (size_t)(bn*128)*KDIM, Bl + (size_t)(bn*128)*KDIM };

    const int r0 = tid >> 2, kc = tid & 3;
    const int r1 = r0 + 64;

    float acc[2][8][4];
    #pragma unroll
    for (int i = 0; i < 2; i++)
        #pragma unroll
        for (int j = 0; j < 8; j++)
            #pragma unroll
            for (int e = 0; e < 4; e++) acc[i][j][e] = 0.f;

    #define G_LOAD(S) do { \
        const int _k0 = (S) * GBK; \
        const uint32_t stb = sbuf + ((S) & 1) * GSTGB; \
        _Pragma("unroll") \
        for (int m = 0; m < 2; m++) { \
            cp16(stb + m*GMATB     + r0*80 + kc*16, pA[m] + (size_t)r0*KDIM + _k0 + kc*8); \
            cp16(stb + m*GMATB     + r1*80 + kc*16, pA[m] + (size_t)r1*KDIM + _k0 + kc*8); \
            cp16(stb + (m+2)*GMATB + r0*80 + kc*16, pB[m] + (size_t)r0*KDIM + _k0 + kc*8); \
            cp16(stb + (m+2)*GMATB + r1*80 + kc*16, pB[m] + (size_t)r1*KDIM + _k0 + kc*8); \
        } \
    } while (0)

    G_LOAD(0); cp_commit();

    for (int s = 0; s < GNSTG; s++) {
        if (s + 1 < GNSTG) {
            G_LOAD(s + 1); cp_commit();
            asm volatile("cp.async.wait_group 1;" ::: "memory");
        } else {
            asm volatile("cp.async.wait_group 0;" ::: "memory");
        }
        __syncthreads();

        const uint32_t stb = sbuf + (s & 1) * GSTGB;
        const uint32_t aBaseH = stb            + (wm*32)*80 + ltermA;
        const uint32_t aBaseL = stb + GMATB    + (wm*32)*80 + ltermA;
        const uint32_t bBaseH = stb + 2*GMATB  + (wn*64)*80 + ltermB;
        const uint32_t bBaseL = stb + 3*GMATB  + (wn*64)*80 + ltermB;

        #pragma unroll
        for (int k16 = 0; k16 < 2; k16++) {
            const uint32_t kc2 = (uint32_t)k16 * 32;
            uint32_t ah[2][4], al[2][4], bb[4][4];
            #pragma unroll
            for (int mt = 0; mt < 2; mt++) ldsm_x4(ah[mt], aBaseH + mt*(16*80) + kc2);
            #pragma unroll
            for (int np = 0; np < 4; np++) ldsm_x4(bb[np], bBaseH + np*(16*80) + kc2);
            #pragma unroll
            for (int mt = 0; mt < 2; mt++)
                #pragma unroll
                for (int np = 0; np < 4; np++) {
                    mma16816(acc[mt][2*np],   ah[mt], &bb[np][0]);
                    mma16816(acc[mt][2*np+1], ah[mt], &bb[np][2]);
                }
            #pragma unroll
            for (int mt = 0; mt < 2; mt++) ldsm_x4(al[mt], aBaseL + mt*(16*80) + kc2);
            #pragma unroll
            for (int mt = 0; mt < 2; mt++)
                #pragma unroll
                for (int np = 0; np < 4; np++) {
                    mma16816(acc[mt][2*np],   al[mt], &bb[np][0]);
                    mma16816(acc[mt][2*np+1], al[mt], &bb[np][2]);
                }
            #pragma unroll
            for (int np = 0; np < 4; np++) ldsm_x4(bb[np], bBaseL + np*(16*80) + kc2);
            #pragma unroll
            for (int mt = 0; mt < 2; mt++)
                #pragma unroll
                for (int np = 0; np < 4; np++) {
                    mma16816(acc[mt][2*np],   ah[mt], &bb[np][0]);
                    mma16816(acc[mt][2*np+1], ah[mt], &bb[np][2]);
                }
        }
        __syncthreads();
    }
    #undef G_LOAD

    #pragma unroll
    for (int mt = 0; mt < 2; mt++) {
        const int rg0 = bm*128 + wm*32 + mt*16 + l4;
        #pragma unroll
        for (int nt = 0; nt < 8; nt++) {
            const int cg = bn*128 + wn*64 + nt*8 + c2;
            if (MODE == 0) {
                float b0 = bias ? bias[cg] : 0.f;
                float b1 = bias ? bias[cg+1] : 0.f;
                float2 v0 = { acc[mt][nt][0] + b0, acc[mt][nt][1] + b1 };
                float2 v1 = { acc[mt][nt][2] + b0, acc[mt][nt][3] + b1 };
                *(float2*)(C + (size_t)rg0*Ncols + cg)     = v0;
                *(float2*)(C + (size_t)(rg0+8)*Ncols + cg) = v1;
            } else {
                if (bn < 8) {
                    uint32_t h0, l0v, h1, l1v;
                    pack_hl(acc[mt][nt][0], acc[mt][nt][1], h0, l0v);
                    pack_hl(acc[mt][nt][2], acc[mt][nt][3], h1, l1v);
                    *(uint32_t*)(CH + (size_t)rg0*INNER_ + cg)     = h0;
                    *(uint32_t*)(CL + (size_t)rg0*INNER_ + cg)     = l0v;
                    *(uint32_t*)(CH + (size_t)(rg0+8)*INNER_ + cg) = h1;
                    *(uint32_t*)(CL + (size_t)(rg0+8)*INNER_ + cg) = l1v;
                } else {
                    const int cc = cg - 1024;
                    float2 v0 = { acc[mt][nt][0], acc[mt][nt][1] };
                    float2 v1 = { acc[mt][nt][2], acc[mt][nt][3] };
                    *(float2*)(C2 + (size_t)rg0*(2*DHD) + cc)     = v0;
                    *(float2*)(C2 + (size_t)(rg0+8)*(2*DHD) + cc) = v1;
                }
            }
        }
    }
}

// ---------------------------------------------------------------------------
// T5 relative-position bucket (mirrors jax fp32 math)
// ---------------------------------------------------------------------------
__device__ __forceinline__ int rel_bucket(int nn) {
    if (nn < 16) return nn;
    float t = logf((float)nn * (1.0f/16.0f)) / 2.0794415416798357f * 16.0f;
    int v = 16 + (int)t;
    return v < 31 ? v : 31;
}

// ---------------------------------------------------------------------------
// Flash attention v5: PV in fp16 single-product (P via cvt.f16x2, V fp16),
// QK unchanged (bf16 3-product). 3-stage cp.async ring, ldmatrix, exp2 softmax.
// Grid (SEQ/128, HEADS, BATCH), 256 threads = 8 warps (warp w -> 16 rows).
// ---------------------------------------------------------------------------
#define FSTRIDE 72                  // elements; 144 bytes/row
#define FTILE   (64*FSTRIDE*2)      // 9216 bytes per tile
#define FKHO 0
#define FKLO (1*FTILE)
#define FVFO (2*FTILE)
#define FSTG (3*FTILE)              // 27648 per stage
#define FBIAS (3*FSTG)              // 82944
#define FLASH_SMEM (FBIAS + 2048*4) // 91136

__global__ __launch_bounds__(256) void flash2(
    const __nv_bfloat16* __restrict__ QH, const __nv_bfloat16* __restrict__ QL,
    const __nv_bfloat16* __restrict__ KH, const __nv_bfloat16* __restrict__ KL,
    const __half* __restrict__ VTF,
    const float* __restrict__ rel_emb,
    __nv_bfloat16* __restrict__ AOH, __nv_bfloat16* __restrict__ AOL)
{
    extern __shared__ __align__(16) char smem[];
    const uint32_t sb = s2u(smem);
    float* biasv = (float*)(smem + FBIAS);

    const int qtb = (SEQ/128 - 1) - blockIdx.x;
    const int h = blockIdx.y, b = blockIdx.z;
    const int tid = threadIdx.x, lane = tid & 31, w = tid >> 5;
    const int l4 = lane >> 2, c2 = (lane & 3) * 2;
    const int i0 = qtb * 128;
    const int wrow = i0 + w * 16;

    const uint32_t ltermB = ((lane & 7) + ((lane >> 4) << 3)) * (FSTRIDE*2)
                          + (((lane >> 3) & 1) << 4);

    for (int nn = tid; nn < 2048; nn += 256)
        biasv[nn] = rel_emb[rel_bucket(nn)*HEADS + h] * (8.0f * LOG2E);

    uint32_t qhf[4][4], qlf[4][4];
    {
        const size_t rb = (size_t)(b*SEQ + wrow + l4) * INNER_ + h*DHD;
        #pragma unroll
        for (int k16 = 0; k16 < 4; k16++) {
            const int c = k16*16 + c2;
            qhf[k16][0] = *(const uint32_t*)(QH + rb + c);
            qhf[k16][1] = *(const uint32_t*)(QH + rb + 8*INNER_ + c);
            qhf[k16][2] = *(const uint32_t*)(QH + rb + c + 8);
            qhf[k16][3] = *(const uint32_t*)(QH + rb + 8*INNER_ + c + 8);
            qlf[k16][0] = *(const uint32_t*)(QL + rb + c);
            qlf[k16][1] = *(const uint32_t*)(QL + rb + 8*INNER_ + c);
            qlf[k16][2] = *(const uint32_t*)(QL + rb + c + 8);
            qlf[k16][3] = *(const uint32_t*)(QL + rb + 8*INNER_ + c + 8);
        }
    }

    float o[8][4];
    #pragma unroll
    for (int nt = 0; nt < 8; nt++)
        #pragma unroll
        for (int e = 0; e < 4; e++) o[nt][e] = 0.f;
    float m0 = -INFINITY, m1 = -INFINITY, l0 = 0.f, l1 = 0.f;

    const int jmax = (i0 + 127) >> 6;
    const int iwmax = wrow + 15;

    // 3 tiles x 64 rows x 8 x 16B = 1536 cp16 per stage / 256 thr = 6 each
    #define LOADKV(JT, S) do { \
        const int _j0 = (JT) * 64; \
        const uint32_t _sb = sb + (uint32_t)(S) * FSTG; \
        _Pragma("unroll") \
        for (int q = 0; q < 2; q++) { \
            const int id = tid*2 + q; \
            const int r = id >> 3, cc = id & 7; \
            const uint32_t so = (uint32_t)(r*144 + cc*16); \
            const size_t ksrc = (size_t)(b*SEQ + _j0 + r)*DHD + cc*8; \
            cp16(_sb + FKHO + so, KH  + ksrc); \
            cp16(_sb + FKLO + so, KL  + ksrc); \
            const size_t vsrc = (size_t)(b*DHD + r)*SEQ + _j0 + cc*8; \
            cp16(_sb + FVFO + so, VTF + vsrc); \
        } \
    } while (0)

    LOADKV(0, 0); cp_commit();
    LOADKV(1, 1); cp_commit();

    for (int jt = 0; jt <= jmax; jt++) {
        asm volatile("cp.async.wait_group 1;" ::: "memory");
        __syncthreads();
        if (jt + 2 <= jmax) LOADKV(jt + 2, (jt + 2) % 3);
        cp_commit();

        const int j0 = jt * 64;
        if (j0 <= iwmax) {
            const uint32_t stgb = sb + (uint32_t)(jt % 3) * FSTG;

            // ---- S = Q K^T (bf16 3-product, product-major) ----
            float s[8][4];
            #pragma unroll
            for (int nt = 0; nt < 8; nt++)
                #pragma unroll
                for (int e = 0; e < 4; e++) s[nt][e] = 0.f;

            #pragma unroll
            for (int k16 = 0; k16 < 4; k16++) {
                const uint32_t kc2 = (uint32_t)k16 * 32;
                uint32_t kh4[4][4], kl4[4][4];
                #pragma unroll
                for (int np = 0; np < 4; np++) {
                    const uint32_t a0 = stgb + FKHO + np*(16*144) + kc2 + ltermB;
                    ldsm_x4(kh4[np], a0);
                    ldsm_x4(kl4[np], a0 + (FKLO - FKHO));
                }
                #pragma unroll
                for (int np = 0; np < 4; np++) {
                    mma16816(s[2*np],   qhf[k16], &kh4[np][0]);
                    mma16816(s[2*np+1], qhf[k16], &kh4[np][2]);
                }
                #pragma unroll
                for (int np = 0; np < 4; np++) {
                    mma16816(s[2*np],   qhf[k16], &kl4[np][0]);
                    mma16816(s[2*np+1], qhf[k16], &kl4[np][2]);
                }
                #pragma unroll
                for (int np = 0; np < 4; np++) {
                    mma16816(s[2*np],   qlf[k16], &kh4[np][0]);
                    mma16816(s[2*np+1], qlf[k16], &kh4[np][2]);
                }
            }

            // ---- bias + causal mask (log2 domain) ----
            const bool masked = (j0 + 63 > wrow);
            const int irow0 = wrow + l4;
            #pragma unroll
            for (int nt = 0; nt < 8; nt++) {
                #pragma unroll
                for (int e = 0; e < 4; e++) {
                    const int ri = irow0 + ((e >> 1) << 3);
                    const int cj = j0 + nt*8 + c2 + (e & 1);
                    const int nn = ri - cj;
                    if (masked && nn < 0) s[nt][e] = -INFINITY;
                    else                  s[nt][e] += biasv[nn];
                }
            }

            // ---- warp-local online softmax (exp2 domain) ----
            float mc0 = -INFINITY, mc1 = -INFINITY;
            #pragma unroll
            for (int nt = 0; nt < 8; nt++) {
                mc0 = fmaxf(mc0, fmaxf(s[nt][0], s[nt][1]));
                mc1 = fmaxf(mc1, fmaxf(s[nt][2], s[nt][3]));
            }
            mc0 = fmaxf(mc0, __shfl_xor_sync(0xffffffffu, mc0, 1));
            mc0 = fmaxf(mc0, __shfl_xor_sync(0xffffffffu, mc0, 2));
            mc1 = fmaxf(mc1, __shfl_xor_sync(0xffffffffu, mc1, 1));
            mc1 = fmaxf(mc1, __shfl_xor_sync(0xffffffffu, mc1, 2));
            const float mn0 = fmaxf(m0, mc0), mn1 = fmaxf(m1, mc1);
            const float sc0 = exp2f(m0 - mn0), sc1 = exp2f(m1 - mn1);
            m0 = mn0; m1 = mn1;

            float rs0 = 0.f, rs1 = 0.f;
            #pragma unroll
            for (int nt = 0; nt < 8; nt++) {
                s[nt][0] = exp2f(s[nt][0] - mn0);
                s[nt][1] = exp2f(s[nt][1] - mn0);
                s[nt][2] = exp2f(s[nt][2] - mn1);
                s[nt][3] = exp2f(s[nt][3] - mn1);
                rs0 += s[nt][0] + s[nt][1];
                rs1 += s[nt][2] + s[nt][3];
            }
            rs0 += __shfl_xor_sync(0xffffffffu, rs0, 1);
            rs0 += __shfl_xor_sync(0xffffffffu, rs0, 2);
            rs1 += __shfl_xor_sync(0xffffffffu, rs1, 1);
            rs1 += __shfl_xor_sync(0xffffffffu, rs1, 2);
            l0 = l0*sc0 + rs0;
            l1 = l1*sc1 + rs1;

            #pragma unroll
            for (int nt = 0; nt < 8; nt++) {
                o[nt][0] *= sc0; o[nt][1] *= sc0;
                o[nt][2] *= sc1; o[nt][3] *= sc1;
            }

            // ---- O += P V (fp16 single product) ----
            #pragma unroll
            for (int kk = 0; kk < 4; kk++) {
                uint32_t pf[4];
                pf[0] = pack_f16x2(s[2*kk  ][0], s[2*kk  ][1]);
                pf[1] = pack_f16x2(s[2*kk  ][2], s[2*kk  ][3]);
                pf[2] = pack_f16x2(s[2*kk+1][0], s[2*kk+1][1]);
                pf[3] = pack_f16x2(s[2*kk+1][2], s[2*kk+1][3]);
                const uint32_t kc2 = (uint32_t)kk * 32;
                uint32_t vf[4][4];
                #pragma unroll
                for (int np = 0; np < 4; np++)
                    ldsm_x4(vf[np], stgb + FVFO + np*(16*144) + kc2 + ltermB);
                #pragma unroll
                for (int np = 0; np < 4; np++) {
                    mma16816h(o[2*np],   pf, &vf[np][0]);
                    mma16816h(o[2*np+1], pf, &vf[np][2]);
                }
            }
        }
    }
    #undef LOADKV

    // ---- normalize + write split bf16 output ----
    {
        const float inv0 = 1.0f / l0, inv1 = 1.0f / l1;
        const size_t rb = (size_t)(b*SEQ + wrow + l4) * INNER_ + h*DHD;
        #pragma unroll
        for (int nt = 0; nt < 8; nt++) {
            const int col = nt*8 + c2;
            uint32_t ph, pl;
            pack_hl(o[nt][0]*inv0, o[nt][1]*inv0, ph, pl);
            *(uint32_t*)(AOH + rb + col) = ph;
            *(uint32_t*)(AOL + rb + col) = pl;
            pack_hl(o[nt][2]*inv1, o[nt][3]*inv1, ph, pl);
            *(uint32_t*)(AOH + rb + 8*INNER_ + col) = ph;
            *(uint32_t*)(AOL + rb + 8*INNER_ + col) = pl;
        }
    }
}

// ---------------------------------------------------------------------------
extern "C" void kernel_launch(void* const* d_in, const int* in_sizes, int n_in,
                              void* d_out, int out_size)
{
    const float* x       = (const float*)d_in[0];
    const float* Wq      = (const float*)d_in[1];
    const float* Wkv     = (const float*)d_in[2];
    const float* Wout    = (const float*)d_in[3];
    const float* bout    = (const float*)d_in[4];
    const float* rel_emb = (const float*)d_in[5];
    float* out = (float*)d_out;

    void* p;
    cudaGetSymbolAddress(&p, g_kv);   float* kvp = (float*)p;
    cudaGetSymbolAddress(&p, g_qh);   __nv_bfloat16* qh  = (__nv_bfloat16*)p;
    cudaGetSymbolAddress(&p, g_ql);   __nv_bfloat16* ql  = (__nv_bfloat16*)p;
    cudaGetSymbolAddress(&p, g_kh);   __nv_bfloat16* kh  = (__nv_bfloat16*)p;
    cudaGetSymbolAddress(&p, g_kl);   __nv_bfloat16* kl  = (__nv_bfloat16*)p;
    cudaGetSymbolAddress(&p, g_vtf);  __half* vtf        = (__half*)p;
    cudaGetSymbolAddress(&p, g_aoh);  __nv_bfloat16* aoh = (__nv_bfloat16*)p;
    cudaGetSymbolAddress(&p, g_aol);  __nv_bfloat16* aol = (__nv_bfloat16*)p;
    cudaGetSymbolAddress(&p, g_xh);   __nv_bfloat16* xh  = (__nv_bfloat16*)p;
    cudaGetSymbolAddress(&p, g_xl);   __nv_bfloat16* xl  = (__nv_bfloat16*)p;
    cudaGetSymbolAddress(&p, g_wcth); __nv_bfloat16* wch = (__nv_bfloat16*)p;
    cudaGetSymbolAddress(&p, g_wctl); __nv_bfloat16* wcl = (__nv_bfloat16*)p;
    cudaGetSymbolAddress(&p, g_woth); __nv_bfloat16* woh = (__nv_bfloat16*)p;
    cudaGetSymbolAddress(&p, g_wotl); __nv_bfloat16* wol = (__nv_bfloat16*)p;

    cudaFuncSetAttribute(gemm_mma<0>, cudaFuncAttributeMaxDynamicSharedMemorySize, GEMM_SMEM);
    cudaFuncSetAttribute(gemm_mma<1>, cudaFuncAttributeMaxDynamicSharedMemorySize, GEMM_SMEM);
    cudaFuncSetAttribute(flash2, cudaFuncAttributeMaxDynamicSharedMemorySize, FLASH_SMEM);

    dim3 tb(32, 8);
    transpose_split_kernel<<<dim3(INNER_/32, DIMM/32), tb>>>(Wq,  wch, wcl, DIMM, INNER_, 0.125f * LOG2E);
    transpose_split_kernel<<<dim3((2*DHD)/32, DIMM/32), tb>>>(Wkv, wch + (size_t)INNER_*DIMM,
                                                              wcl + (size_t)INNER_*DIMM, DIMM, 2*DHD, 1.0f);
    transpose_split_kernel<<<dim3(DIMM/32, INNER_/32), tb>>>(Wout, woh, wol, INNER_, DIMM, 1.0f);
    split_kernel<<<(ROWS*DIMM/4 + 255)/256, 256>>>(x, xh, xl, ROWS*DIMM/4);

    gemm_mma<1><<<dim3(9, ROWS/128), 256, GEMM_SMEM>>>(xh, xl, wch, wcl,
                                                       nullptr, nullptr, 0, qh, ql, kvp);
    kvsplit_kernel<<<dim3(SEQ/64, BATCH), 256>>>(kvp, kh, kl, vtf);
    flash2<<<dim3(SEQ/128, HEADS, BATCH), 256, FLASH_SMEM>>>(qh, ql, kh, kl, vtf,
                                                             rel_emb, aoh, aol);
    gemm_mma<0><<<dim3(DIMM/128, ROWS/128), 256, GEMM_SMEM>>>(aoh, aol, woh, wol,
                                                              out, bout, DIMM,
                                                              nullptr, nullptr, nullptr);
}

// round 10
// speedup vs baseline: 1.5752x; 1.2438x over previous
#include <cuda_runtime.h>
#include <cuda_bf16.h>
#include <cuda_fp16.h>
#include <math.h>
#include <stdint.h>

#define BATCH 2
#define SEQ   2048
#define DIMM  1024
#define HEADS 16
#define DHD   64
#define INNER_ (HEADS*DHD)      // 1024
#define ROWS  (BATCH*SEQ)       // 4096
#define KDIM  1024
#define LOG2E 1.4426950408889634f

// ---------------- scratch (no cudaMalloc allowed) ----------------
__device__ __align__(256) float  g_kv [ROWS*2*DHD];
__device__ __align__(256) __half g_qh [ROWS*INNER_];
__device__ __align__(256) __half g_ql [ROWS*INNER_];
__device__ __align__(256) __half g_kf [BATCH*SEQ*DHD];
__device__ __align__(256) __half g_vtf[BATCH*DHD*SEQ];
__device__ __align__(256) __half g_aoh[ROWS*INNER_];
__device__ __align__(256) __half g_aol[ROWS*INNER_];
__device__ __align__(256) __half g_xh [ROWS*DIMM];
__device__ __align__(256) __half g_xl [ROWS*DIMM];
__device__ __align__(256) __half g_wcf[(INNER_+2*DHD)*DIMM];   // [Wq^T ; Wkv^T] fp16
__device__ __align__(256) __half g_wof[DIMM*INNER_];           // Wout^T fp16

// ---------------- helpers ----------------
__device__ __forceinline__ uint32_t s2u(const void* p) {
    uint32_t a;
    asm("{ .reg .u64 t; cvta.to.shared.u64 t, %1; cvt.u32.u64 %0, t; }"
        : "=r"(a) : "l"(p));
    return a;
}
__device__ __forceinline__ void cp16(uint32_t dst, const void* src) {
    asm volatile("cp.async.cg.shared.global [%0], [%1], 16;" :: "r"(dst), "l"(src));
}
__device__ __forceinline__ void cp_commit() { asm volatile("cp.async.commit_group;" ::: "memory"); }

__device__ __forceinline__ void mma16816h(float c[4], const uint32_t a[4], const uint32_t b[2]) {
    asm volatile("mma.sync.aligned.m16n8k16.row.col.f32.f16.f16.f32 "
        "{%0,%1,%2,%3}, {%4,%5,%6,%7}, {%8,%9}, {%0,%1,%2,%3};"
        : "+f"(c[0]), "+f"(c[1]), "+f"(c[2]), "+f"(c[3])
        : "r"(a[0]), "r"(a[1]), "r"(a[2]), "r"(a[3]), "r"(b[0]), "r"(b[1]));
}

// ldmatrix x4
__device__ __forceinline__ void ldsm_x4(uint32_t r[4], uint32_t saddr) {
    asm volatile("ldmatrix.sync.aligned.m8n8.x4.shared.b16 {%0,%1,%2,%3}, [%4];"
        : "=r"(r[0]), "=r"(r[1]), "=r"(r[2]), "=r"(r[3]) : "r"(saddr));
}

// pack two floats -> fp16x2 (first arg = low half)
__device__ __forceinline__ uint32_t pack_f16x2(float lo, float hi) {
    uint32_t r;
    asm("cvt.rn.f16x2.f32 %0, %1, %2;" : "=r"(r) : "f"(hi), "f"(lo));
    return r;
}

// pack two floats into fp16x2 hi + fp16x2 lo (residual)
__device__ __forceinline__ void pack_hl16(float a, float b, uint32_t& h, uint32_t& l) {
    __half ha = __float2half_rn(a), hb = __float2half_rn(b);
    __half la = __float2half_rn(a - __half2float(ha));
    __half lb = __float2half_rn(b - __half2float(hb));
    __half2 hh = __halves2half2(ha, hb);
    __half2 ll = __halves2half2(la, lb);
    h = *reinterpret_cast<uint32_t*>(&hh);
    l = *reinterpret_cast<uint32_t*>(&ll);
}

// ---------------------------------------------------------------------------
// Prep kernels
// ---------------------------------------------------------------------------
__global__ __launch_bounds__(256) void split_kernel(
    const float* __restrict__ A, __half* __restrict__ H,
    __half* __restrict__ L, int n4)
{
    int i = blockIdx.x * blockDim.x + threadIdx.x;
    if (i >= n4) return;
    float4 a = ((const float4*)A)[i];
    uint32_t h01, l01, h23, l23;
    pack_hl16(a.x, a.y, h01, l01);
    pack_hl16(a.z, a.w, h23, l23);
    ((uint32_t*)H)[2*i]   = h01; ((uint32_t*)H)[2*i+1] = h23;
    ((uint32_t*)L)[2*i]   = l01; ((uint32_t*)L)[2*i+1] = l23;
}

// transpose to [N][K] fp16 single
__global__ __launch_bounds__(256) void transpose_f16_kernel(
    const float* __restrict__ W, __half* __restrict__ T,
    int K, int N, float scale)
{
    __shared__ float tile[32][33];
    const int tx = threadIdx.x, ty = threadIdx.y;
    const int n0 = blockIdx.x * 32, k0 = blockIdx.y * 32;
    #pragma unroll
    for (int i = 0; i < 4; i++)
        tile[ty + 8*i][tx] = W[(size_t)(k0 + ty + 8*i) * N + n0 + tx];
    __syncthreads();
    #pragma unroll
    for (int i = 0; i < 4; i++) {
        float a = tile[tx][ty + 8*i] * scale;
        T[(size_t)(n0 + ty + 8*i) * K + k0 + tx] = __float2half_rn(a);
    }
}

// kv fp32 -> K fp16 [b][j][64], V^T fp16 [b][d][SEQ]
__global__ __launch_bounds__(256) void kvsplit_kernel(
    const float* __restrict__ KVin,
    __half* __restrict__ KF, __half* __restrict__ VTF)
{
    __shared__ float vt[64][65];
    const int b = blockIdx.y, j0 = blockIdx.x * 64;
    const int tid = threadIdx.x;
    const int j = tid >> 2, g = (tid & 3) * 16;
    const float* rp = KVin + (size_t)(b*SEQ + j0 + j) * (2*DHD);
    #pragma unroll
    for (int c = 0; c < 4; c++) {
        float4 kq = *(const float4*)(rp + g + c*4);
        size_t ko = (size_t)(b*SEQ + j0 + j)*DHD + g + c*4;
        *(__half2*)(KF + ko)     = __floats2half2_rn(kq.x, kq.y);
        *(__half2*)(KF + ko + 2) = __floats2half2_rn(kq.z, kq.w);
        float4 vq = *(const float4*)(rp + DHD + g + c*4);
        vt[j][g + c*4 + 0] = vq.x; vt[j][g + c*4 + 1] = vq.y;
        vt[j][g + c*4 + 2] = vq.z; vt[j][g + c*4 + 3] = vq.w;
    }
    __syncthreads();
    const int d = tid >> 2, jg = (tid & 3) * 16;
    #pragma unroll
    for (int i = 0; i < 16; i += 2) {
        float a = vt[jg + i][d], bb = vt[jg + i + 1][d];
        size_t vo = (size_t)(b*DHD + d)*SEQ + j0 + jg + i;
        *(__half2*)(VTF + vo) = __floats2half2_rn(a, bb);
    }
}

// ---------------------------------------------------------------------------
// HMMA GEMM fp16 2-product: C = (Ah+Al)[M,K] @ B^T, B single fp16 [N][K].
// CTA 128x128, BK=32, 2-stage cp.async, 8 warps x 32x64.
// MODE 0: fp32 C + bias.  MODE 1: cols<1024 -> split fp16 (q), col>=1024 -> fp32 kv.
// ---------------------------------------------------------------------------
#define GBK 32
#define GNSTG (KDIM/GBK)
#define GSTRIDE 40                  // elements; 80 bytes/row
#define GMATB (128*GSTRIDE*2)       // 10240 bytes per matrix
#define GSTGB (3*GMATB)             // 30720 per stage
#define GEMM_SMEM (2*GSTGB)         // 61440

template<int MODE>
__global__ __launch_bounds__(256) void gemm_mma(
    const __half* __restrict__ Ah, const __half* __restrict__ Al,
    const __half* __restrict__ Bf,
    float* __restrict__ C, const float* __restrict__ bias, int Ncols,
    __half* __restrict__ CH, __half* __restrict__ CL,
    float* __restrict__ C2)
{
    extern __shared__ __align__(16) char smem[];
    const uint32_t sbuf = s2u(smem);
    const int tid = threadIdx.x, wid = tid >> 5, lane = tid & 31;
    const int l4 = lane >> 2, c2 = (lane & 3) * 2;
    const int wm = wid & 3, wn = wid >> 2;
    const int bn = blockIdx.x, bm = blockIdx.y;

    const uint32_t ltermB = ((lane & 7) + ((lane >> 4) << 3)) * (GSTRIDE*2)
                          + (((lane >> 3) & 1) << 4);
    const uint32_t ltermA = ((lane & 7) + (((lane >> 3) & 1) << 3)) * (GSTRIDE*2)
                          + (((lane >> 4) & 1) << 4);

    const __half* pAh = Ah + (size_t)(bm*128)*KDIM;
    const __half* pAl = Al + (size_t)(bm*128)*KDIM;
    const __half* pB  = Bf + (size_t)(bn*128)*KDIM;

    const int r0 = tid >> 2, kc = tid & 3;
    const int r1 = r0 + 64;

    float acc[2][8][4];
    #pragma unroll
    for (int i = 0; i < 2; i++)
        #pragma unroll
        for (int j = 0; j < 8; j++)
            #pragma unroll
            for (int e = 0; e < 4; e++) acc[i][j][e] = 0.f;

    #define G_LOAD(S) do { \
        const int _k0 = (S) * GBK; \
        const uint32_t stb = sbuf + ((S) & 1) * GSTGB; \
        cp16(stb           + r0*80 + kc*16, pAh + (size_t)r0*KDIM + _k0 + kc*8); \
        cp16(stb           + r1*80 + kc*16, pAh + (size_t)r1*KDIM + _k0 + kc*8); \
        cp16(stb + GMATB   + r0*80 + kc*16, pAl + (size_t)r0*KDIM + _k0 + kc*8); \
        cp16(stb + GMATB   + r1*80 + kc*16, pAl + (size_t)r1*KDIM + _k0 + kc*8); \
        cp16(stb + 2*GMATB + r0*80 + kc*16, pB  + (size_t)r0*KDIM + _k0 + kc*8); \
        cp16(stb + 2*GMATB + r1*80 + kc*16, pB  + (size_t)r1*KDIM + _k0 + kc*8); \
    } while (0)

    G_LOAD(0); cp_commit();

    for (int s = 0; s < GNSTG; s++) {
        if (s + 1 < GNSTG) {
            G_LOAD(s + 1); cp_commit();
            asm volatile("cp.async.wait_group 1;" ::: "memory");
        } else {
            asm volatile("cp.async.wait_group 0;" ::: "memory");
        }
        __syncthreads();

        const uint32_t stb = sbuf + (s & 1) * GSTGB;
        const uint32_t aBaseH = stb            + (wm*32)*80 + ltermA;
        const uint32_t aBaseL = stb + GMATB    + (wm*32)*80 + ltermA;
        const uint32_t bBase  = stb + 2*GMATB  + (wn*64)*80 + ltermB;

        #pragma unroll
        for (int k16 = 0; k16 < 2; k16++) {
            const uint32_t kc2 = (uint32_t)k16 * 32;
            uint32_t ah[2][4], al[2][4], bb[4][4];
            #pragma unroll
            for (int mt = 0; mt < 2; mt++) ldsm_x4(ah[mt], aBaseH + mt*(16*80) + kc2);
            #pragma unroll
            for (int np = 0; np < 4; np++) ldsm_x4(bb[np], bBase + np*(16*80) + kc2);
            #pragma unroll
            for (int mt = 0; mt < 2; mt++)
                #pragma unroll
                for (int np = 0; np < 4; np++) {
                    mma16816h(acc[mt][2*np],   ah[mt], &bb[np][0]);
                    mma16816h(acc[mt][2*np+1], ah[mt], &bb[np][2]);
                }
            #pragma unroll
            for (int mt = 0; mt < 2; mt++) ldsm_x4(al[mt], aBaseL + mt*(16*80) + kc2);
            #pragma unroll
            for (int mt = 0; mt < 2; mt++)
                #pragma unroll
                for (int np = 0; np < 4; np++) {
                    mma16816h(acc[mt][2*np],   al[mt], &bb[np][0]);
                    mma16816h(acc[mt][2*np+1], al[mt], &bb[np][2]);
                }
        }
        __syncthreads();
    }
    #undef G_LOAD

    #pragma unroll
    for (int mt = 0; mt < 2; mt++) {
        const int rg0 = bm*128 + wm*32 + mt*16 + l4;
        #pragma unroll
        for (int nt = 0; nt < 8; nt++) {
            const int cg = bn*128 + wn*64 + nt*8 + c2;
            if (MODE == 0) {
                float b0 = bias ? bias[cg] : 0.f;
                float b1 = bias ? bias[cg+1] : 0.f;
                float2 v0 = { acc[mt][nt][0] + b0, acc[mt][nt][1] + b1 };
                float2 v1 = { acc[mt][nt][2] + b0, acc[mt][nt][3] + b1 };
                *(float2*)(C + (size_t)rg0*Ncols + cg)     = v0;
                *(float2*)(C + (size_t)(rg0+8)*Ncols + cg) = v1;
            } else {
                if (bn < 8) {
                    uint32_t h0, l0v, h1, l1v;
                    pack_hl16(acc[mt][nt][0], acc[mt][nt][1], h0, l0v);
                    pack_hl16(acc[mt][nt][2], acc[mt][nt][3], h1, l1v);
                    *(uint32_t*)(CH + (size_t)rg0*INNER_ + cg)     = h0;
                    *(uint32_t*)(CL + (size_t)rg0*INNER_ + cg)     = l0v;
                    *(uint32_t*)(CH + (size_t)(rg0+8)*INNER_ + cg) = h1;
                    *(uint32_t*)(CL + (size_t)(rg0+8)*INNER_ + cg) = l1v;
                } else {
                    const int cc = cg - 1024;
                    float2 v0 = { acc[mt][nt][0], acc[mt][nt][1] };
                    float2 v1 = { acc[mt][nt][2], acc[mt][nt][3] };
                    *(float2*)(C2 + (size_t)rg0*(2*DHD) + cc)     = v0;
                    *(float2*)(C2 + (size_t)(rg0+8)*(2*DHD) + cc) = v1;
                }
            }
        }
    }
}

// ---------------------------------------------------------------------------
// T5 relative-position bucket (mirrors jax fp32 math)
// ---------------------------------------------------------------------------
__device__ __forceinline__ int rel_bucket(int nn) {
    if (nn < 16) return nn;
    float t = logf((float)nn * (1.0f/16.0f)) / 2.0794415416798357f * 16.0f;
    int v = 16 + (int)t;
    return v < 31 ? v : 31;
}

// ---------------------------------------------------------------------------
// Flash attention v6: all-fp16 mma. QK = (qh+ql)·K (2-product), PV = P·V (1-product).
// 3-stage cp.async ring (K + V^T per stage), ldmatrix, exp2 softmax.
// Grid (SEQ/128, HEADS, BATCH), 256 threads = 8 warps (warp w -> 16 rows).
// ---------------------------------------------------------------------------
#define FSTRIDE 72                  // elements; 144 bytes/row
#define FTILE   (64*FSTRIDE*2)      // 9216 bytes per tile
#define FKFO 0
#define FVFO (1*FTILE)
#define FSTG (2*FTILE)              // 18432 per stage
#define FBIAS (3*FSTG)              // 55296
#define FLASH_SMEM (FBIAS + 2048*4) // 63488

__global__ __launch_bounds__(256) void flash2(
    const __half* __restrict__ QH, const __half* __restrict__ QL,
    const __half* __restrict__ KF, const __half* __restrict__ VTF,
    const float* __restrict__ rel_emb,
    __half* __restrict__ AOH, __half* __restrict__ AOL)
{
    extern __shared__ __align__(16) char smem[];
    const uint32_t sb = s2u(smem);
    float* biasv = (float*)(smem + FBIAS);

    const int qtb = (SEQ/128 - 1) - blockIdx.x;
    const int h = blockIdx.y, b = blockIdx.z;
    const int tid = threadIdx.x, lane = tid & 31, w = tid >> 5;
    const int l4 = lane >> 2, c2 = (lane & 3) * 2;
    const int i0 = qtb * 128;
    const int wrow = i0 + w * 16;

    const uint32_t ltermB = ((lane & 7) + ((lane >> 4) << 3)) * (FSTRIDE*2)
                          + (((lane >> 3) & 1) << 4);

    for (int nn = tid; nn < 2048; nn += 256)
        biasv[nn] = rel_emb[rel_bucket(nn)*HEADS + h] * (8.0f * LOG2E);

    uint32_t qhf[4][4], qlf[4][4];
    {
        const size_t rb = (size_t)(b*SEQ + wrow + l4) * INNER_ + h*DHD;
        #pragma unroll
        for (int k16 = 0; k16 < 4; k16++) {
            const int c = k16*16 + c2;
            qhf[k16][0] = *(const uint32_t*)(QH + rb + c);
            qhf[k16][1] = *(const uint32_t*)(QH + rb + 8*INNER_ + c);
            qhf[k16][2] = *(const uint32_t*)(QH + rb + c + 8);
            qhf[k16][3] = *(const uint32_t*)(QH + rb + 8*INNER_ + c + 8);
            qlf[k16][0] = *(const uint32_t*)(QL + rb + c);
            qlf[k16][1] = *(const uint32_t*)(QL + rb + 8*INNER_ + c);
            qlf[k16][2] = *(const uint32_t*)(QL + rb + c + 8);
            qlf[k16][3] = *(const uint32_t*)(QL + rb + 8*INNER_ + c + 8);
        }
    }

    float o[8][4];
    #pragma unroll
    for (int nt = 0; nt < 8; nt++)
        #pragma unroll
        for (int e = 0; e < 4; e++) o[nt][e] = 0.f;
    float m0 = -INFINITY, m1 = -INFINITY, l0 = 0.f, l1 = 0.f;

    const int jmax = (i0 + 127) >> 6;
    const int iwmax = wrow + 15;

    // 2 tiles x 64 rows x 8 x 16B = 1024 cp16 per stage / 256 thr = 4 each
    #define LOADKV(JT, S) do { \
        const int _j0 = (JT) * 64; \
        const uint32_t _sb = sb + (uint32_t)(S) * FSTG; \
        _Pragma("unroll") \
        for (int q = 0; q < 2; q++) { \
            const int id = tid*2 + q; \
            const int r = id >> 3, cc = id & 7; \
            const uint32_t so = (uint32_t)(r*144 + cc*16); \
            const size_t ksrc = (size_t)(b*SEQ + _j0 + r)*DHD + cc*8; \
            cp16(_sb + FKFO + so, KF  + ksrc); \
            const size_t vsrc = (size_t)(b*DHD + r)*SEQ + _j0 + cc*8; \
            cp16(_sb + FVFO + so, VTF + vsrc); \
        } \
    } while (0)

    LOADKV(0, 0); cp_commit();
    LOADKV(1, 1); cp_commit();

    for (int jt = 0; jt <= jmax; jt++) {
        asm volatile("cp.async.wait_group 1;" ::: "memory");
        __syncthreads();
        if (jt + 2 <= jmax) LOADKV(jt + 2, (jt + 2) % 3);
        cp_commit();

        const int j0 = jt * 64;
        if (j0 <= iwmax) {
            const uint32_t stgb = sb + (uint32_t)(jt % 3) * FSTG;

            // ---- S = Q K^T (fp16 2-product) ----
            float s[8][4];
            #pragma unroll
            for (int nt = 0; nt < 8; nt++)
                #pragma unroll
                for (int e = 0; e < 4; e++) s[nt][e] = 0.f;

            #pragma unroll
            for (int k16 = 0; k16 < 4; k16++) {
                const uint32_t kc2 = (uint32_t)k16 * 32;
                uint32_t kf4[4][4];
                #pragma unroll
                for (int np = 0; np < 4; np++)
                    ldsm_x4(kf4[np], stgb + FKFO + np*(16*144) + kc2 + ltermB);
                #pragma unroll
                for (int np = 0; np < 4; np++) {
                    mma16816h(s[2*np],   qhf[k16], &kf4[np][0]);
                    mma16816h(s[2*np+1], qhf[k16], &kf4[np][2]);
                }
                #pragma unroll
                for (int np = 0; np < 4; np++) {
                    mma16816h(s[2*np],   qlf[k16], &kf4[np][0]);
                    mma16816h(s[2*np+1], qlf[k16], &kf4[np][2]);
                }
            }

            // ---- bias + causal mask (log2 domain) ----
            const bool masked = (j0 + 63 > wrow);
            const int irow0 = wrow + l4;
            #pragma unroll
            for (int nt = 0; nt < 8; nt++) {
                #pragma unroll
                for (int e = 0; e < 4; e++) {
                    const int ri = irow0 + ((e >> 1) << 3);
                    const int cj = j0 + nt*8 + c2 + (e & 1);
                    const int nn = ri - cj;
                    if (masked && nn < 0) s[nt][e] = -INFINITY;
                    else                  s[nt][e] += biasv[nn];
                }
            }

            // ---- warp-local online softmax (exp2 domain) ----
            float mc0 = -INFINITY, mc1 = -INFINITY;
            #pragma unroll
            for (int nt = 0; nt < 8; nt++) {
                mc0 = fmaxf(mc0, fmaxf(s[nt][0], s[nt][1]));
                mc1 = fmaxf(mc1, fmaxf(s[nt][2], s[nt][3]));
            }
            mc0 = fmaxf(mc0, __shfl_xor_sync(0xffffffffu, mc0, 1));
            mc0 = fmaxf(mc0, __shfl_xor_sync(0xffffffffu, mc0, 2));
            mc1 = fmaxf(mc1, __shfl_xor_sync(0xffffffffu, mc1, 1));
            mc1 = fmaxf(mc1, __shfl_xor_sync(0xffffffffu, mc1, 2));
            const float mn0 = fmaxf(m0, mc0), mn1 = fmaxf(m1, mc1);
            const float sc0 = exp2f(m0 - mn0), sc1 = exp2f(m1 - mn1);
            m0 = mn0; m1 = mn1;

            float rs0 = 0.f, rs1 = 0.f;
            #pragma unroll
            for (int nt = 0; nt < 8; nt++) {
                s[nt][0] = exp2f(s[nt][0] - mn0);
                s[nt][1] = exp2f(s[nt][1] - mn0);
                s[nt][2] = exp2f(s[nt][2] - mn1);
                s[nt][3] = exp2f(s[nt][3] - mn1);
                rs0 += s[nt][0] + s[nt][1];
                rs1 += s[nt][2] + s[nt][3];
            }
            rs0 += __shfl_xor_sync(0xffffffffu, rs0, 1);
            rs0 += __shfl_xor_sync(0xffffffffu, rs0, 2);
            rs1 += __shfl_xor_sync(0xffffffffu, rs1, 1);
            rs1 += __shfl_xor_sync(0xffffffffu, rs1, 2);
            l0 = l0*sc0 + rs0;
            l1 = l1*sc1 + rs1;

            #pragma unroll
            for (int nt = 0; nt < 8; nt++) {
                o[nt][0] *= sc0; o[nt][1] *= sc0;
                o[nt][2] *= sc1; o[nt][3] *= sc1;
            }

            // ---- O += P V (fp16 single product) ----
            #pragma unroll
            for (int kk = 0; kk < 4; kk++) {
                uint32_t pf[4];
                pf[0] = pack_f16x2(s[2*kk  ][0], s[2*kk  ][1]);
                pf[1] = pack_f16x2(s[2*kk  ][2], s[2*kk  ][3]);
                pf[2] = pack_f16x2(s[2*kk+1][0], s[2*kk+1][1]);
                pf[3] = pack_f16x2(s[2*kk+1][2], s[2*kk+1][3]);
                const uint32_t kc2 = (uint32_t)kk * 32;
                uint32_t vf[4][4];
                #pragma unroll
                for (int np = 0; np < 4; np++)
                    ldsm_x4(vf[np], stgb + FVFO + np*(16*144) + kc2 + ltermB);
                #pragma unroll
                for (int np = 0; np < 4; np++) {
                    mma16816h(o[2*np],   pf, &vf[np][0]);
                    mma16816h(o[2*np+1], pf, &vf[np][2]);
                }
            }
        }
    }
    #undef LOADKV

    // ---- normalize + write split fp16 output ----
    {
        const float inv0 = 1.0f / l0, inv1 = 1.0f / l1;
        const size_t rb = (size_t)(b*SEQ + wrow + l4) * INNER_ + h*DHD;
        #pragma unroll
        for (int nt = 0; nt < 8; nt++) {
            const int col = nt*8 + c2;
            uint32_t ph, pl;
            pack_hl16(o[nt][0]*inv0, o[nt][1]*inv0, ph, pl);
            *(uint32_t*)(AOH + rb + col) = ph;
            *(uint32_t*)(AOL + rb + col) = pl;
            pack_hl16(o[nt][2]*inv1, o[nt][3]*inv1, ph, pl);
            *(uint32_t*)(AOH + rb + 8*INNER_ + col) = ph;
            *(uint32_t*)(AOL + rb + 8*INNER_ + col) = pl;
        }
    }
}

// ---------------------------------------------------------------------------
extern "C" void kernel_launch(void* const* d_in, const int* in_sizes, int n_in,
                              void* d_out, int out_size)
{
    const float* x       = (const float*)d_in[0];
    const float* Wq      = (const float*)d_in[1];
    const float* Wkv     = (const float*)d_in[2];
    const float* Wout    = (const float*)d_in[3];
    const float* bout    = (const float*)d_in[4];
    const float* rel_emb = (const float*)d_in[5];
    float* out = (float*)d_out;

    void* p;
    cudaGetSymbolAddress(&p, g_kv);   float* kvp = (float*)p;
    cudaGetSymbolAddress(&p, g_qh);   __half* qh  = (__half*)p;
    cudaGetSymbolAddress(&p, g_ql);   __half* ql  = (__half*)p;
    cudaGetSymbolAddress(&p, g_kf);   __half* kf  = (__half*)p;
    cudaGetSymbolAddress(&p, g_vtf);  __half* vtf = (__half*)p;
    cudaGetSymbolAddress(&p, g_aoh);  __half* aoh = (__half*)p;
    cudaGetSymbolAddress(&p, g_aol);  __half* aol = (__half*)p;
    cudaGetSymbolAddress(&p, g_xh);   __half* xh  = (__half*)p;
    cudaGetSymbolAddress(&p, g_xl);   __half* xl  = (__half*)p;
    cudaGetSymbolAddress(&p, g_wcf);  __half* wcf = (__half*)p;
    cudaGetSymbolAddress(&p, g_wof);  __half* wof = (__half*)p;

    cudaFuncSetAttribute(gemm_mma<0>, cudaFuncAttributeMaxDynamicSharedMemorySize, GEMM_SMEM);
    cudaFuncSetAttribute(gemm_mma<1>, cudaFuncAttributeMaxDynamicSharedMemorySize, GEMM_SMEM);
    cudaFuncSetAttribute(flash2, cudaFuncAttributeMaxDynamicSharedMemorySize, FLASH_SMEM);

    dim3 tb(32, 8);
    // weight prep (Wq pre-scaled by dim_head^-0.5 * log2e for exp2-domain softmax)
    transpose_f16_kernel<<<dim3(INNER_/32, DIMM/32), tb>>>(Wq,  wcf, DIMM, INNER_, 0.125f * LOG2E);
    transpose_f16_kernel<<<dim3((2*DHD)/32, DIMM/32), tb>>>(Wkv, wcf + (size_t)INNER_*DIMM, DIMM, 2*DHD, 1.0f);
    transpose_f16_kernel<<<dim3(DIMM/32, INNER_/32), tb>>>(Wout, wof, INNER_, DIMM, 1.0f);
    split_kernel<<<(ROWS*DIMM/4 + 255)/256, 256>>>(x, xh, xl, ROWS*DIMM/4);

    // fused q|kv projection: writes q as split fp16, kv as fp32
    gemm_mma<1><<<dim3(9, ROWS/128), 256, GEMM_SMEM>>>(xh, xl, wcf,
                                                       nullptr, nullptr, 0, qh, ql, kvp);
    // kv -> K fp16 + transposed V fp16
    kvsplit_kernel<<<dim3(SEQ/64, BATCH), 256>>>(kvp, kf, vtf);
    // attention
    flash2<<<dim3(SEQ/128, HEADS, BATCH), 256, FLASH_SMEM>>>(qh, ql, kf, vtf,
                                                             rel_emb, aoh, aol);
    // out = ao @ Wout + bout
    gemm_mma<0><<<dim3(DIMM/128, ROWS/128), 256, GEMM_SMEM>>>(aoh, aol, wof,
                                                              out, bout, DIMM,
                                                              nullptr, nullptr, nullptr);
}

// round 11
// speedup vs baseline: 1.8102x; 1.1492x over previous
#include <cuda_runtime.h>
#include <cuda_bf16.h>
#include <cuda_fp16.h>
#include <math.h>
#include <stdint.h>

#define BATCH 2
#define SEQ   2048
#define DIMM  1024
#define HEADS 16
#define DHD   64
#define INNER_ (HEADS*DHD)      // 1024
#define ROWS  (BATCH*SEQ)       // 4096
#define KDIM  1024
#define LOG2E 1.4426950408889634f

// ---------------- scratch (no cudaMalloc allowed) ----------------
__device__ __align__(256) float  g_kv [ROWS*2*DHD];
__device__ __align__(256) __half g_qf [ROWS*INNER_];
__device__ __align__(256) __half g_kf [BATCH*SEQ*DHD];
__device__ __align__(256) __half g_vtf[BATCH*DHD*SEQ];
__device__ __align__(256) __half g_aoh[ROWS*INNER_];
__device__ __align__(256) __half g_aol[ROWS*INNER_];
__device__ __align__(256) __half g_xh [ROWS*DIMM];
__device__ __align__(256) __half g_xl [ROWS*DIMM];
__device__ __align__(256) __half g_wcf[(INNER_+2*DHD)*DIMM];   // [Wq^T ; Wkv^T] fp16
__device__ __align__(256) __half g_wof[DIMM*INNER_];           // Wout^T fp16

// ---------------- helpers ----------------
__device__ __forceinline__ uint32_t s2u(const void* p) {
    uint32_t a;
    asm("{ .reg .u64 t; cvta.to.shared.u64 t, %1; cvt.u32.u64 %0, t; }"
        : "=r"(a) : "l"(p));
    return a;
}
__device__ __forceinline__ void cp16(uint32_t dst, const void* src) {
    asm volatile("cp.async.cg.shared.global [%0], [%1], 16;" :: "r"(dst), "l"(src));
}
__device__ __forceinline__ void cp_commit() { asm volatile("cp.async.commit_group;" ::: "memory"); }

__device__ __forceinline__ void mma16816h(float c[4], const uint32_t a[4], const uint32_t b[2]) {
    asm volatile("mma.sync.aligned.m16n8k16.row.col.f32.f16.f16.f32 "
        "{%0,%1,%2,%3}, {%4,%5,%6,%7}, {%8,%9}, {%0,%1,%2,%3};"
        : "+f"(c[0]), "+f"(c[1]), "+f"(c[2]), "+f"(c[3])
        : "r"(a[0]), "r"(a[1]), "r"(a[2]), "r"(a[3]), "r"(b[0]), "r"(b[1]));
}

// ldmatrix x4
__device__ __forceinline__ void ldsm_x4(uint32_t r[4], uint32_t saddr) {
    asm volatile("ldmatrix.sync.aligned.m8n8.x4.shared.b16 {%0,%1,%2,%3}, [%4];"
        : "=r"(r[0]), "=r"(r[1]), "=r"(r[2]), "=r"(r[3]) : "r"(saddr));
}

// pack two floats -> fp16x2 (first arg = low half)
__device__ __forceinline__ uint32_t pack_f16x2(float lo, float hi) {
    uint32_t r;
    asm("cvt.rn.f16x2.f32 %0, %1, %2;" : "=r"(r) : "f"(hi), "f"(lo));
    return r;
}

// pack two floats into fp16x2 hi + fp16x2 lo (residual)
__device__ __forceinline__ void pack_hl16(float a, float b, uint32_t& h, uint32_t& l) {
    __half ha = __float2half_rn(a), hb = __float2half_rn(b);
    __half la = __float2half_rn(a - __half2float(ha));
    __half lb = __float2half_rn(b - __half2float(hb));
    __half2 hh = __halves2half2(ha, hb);
    __half2 ll = __halves2half2(la, lb);
    h = *reinterpret_cast<uint32_t*>(&hh);
    l = *reinterpret_cast<uint32_t*>(&ll);
}

// ---------------------------------------------------------------------------
// Prep kernels
// ---------------------------------------------------------------------------
__global__ __launch_bounds__(256) void split_kernel(
    const float* __restrict__ A, __half* __restrict__ H,
    __half* __restrict__ L, int n4)
{
    int i = blockIdx.x * blockDim.x + threadIdx.x;
    if (i >= n4) return;
    float4 a = ((const float4*)A)[i];
    uint32_t h01, l01, h23, l23;
    pack_hl16(a.x, a.y, h01, l01);
    pack_hl16(a.z, a.w, h23, l23);
    ((uint32_t*)H)[2*i]   = h01; ((uint32_t*)H)[2*i+1] = h23;
    ((uint32_t*)L)[2*i]   = l01; ((uint32_t*)L)[2*i+1] = l23;
}

// transpose to [N][K] fp16 single
__global__ __launch_bounds__(256) void transpose_f16_kernel(
    const float* __restrict__ W, __half* __restrict__ T,
    int K, int N, float scale)
{
    __shared__ float tile[32][33];
    const int tx = threadIdx.x, ty = threadIdx.y;
    const int n0 = blockIdx.x * 32, k0 = blockIdx.y * 32;
    #pragma unroll
    for (int i = 0; i < 4; i++)
        tile[ty + 8*i][tx] = W[(size_t)(k0 + ty + 8*i) * N + n0 + tx];
    __syncthreads();
    #pragma unroll
    for (int i = 0; i < 4; i++) {
        float a = tile[tx][ty + 8*i] * scale;
        T[(size_t)(n0 + ty + 8*i) * K + k0 + tx] = __float2half_rn(a);
    }
}

// kv fp32 -> K fp16 [b][j][64], V^T fp16 [b][d][SEQ]
__global__ __launch_bounds__(256) void kvsplit_kernel(
    const float* __restrict__ KVin,
    __half* __restrict__ KF, __half* __restrict__ VTF)
{
    __shared__ float vt[64][65];
    const int b = blockIdx.y, j0 = blockIdx.x * 64;
    const int tid = threadIdx.x;
    const int j = tid >> 2, g = (tid & 3) * 16;
    const float* rp = KVin + (size_t)(b*SEQ + j0 + j) * (2*DHD);
    #pragma unroll
    for (int c = 0; c < 4; c++) {
        float4 kq = *(const float4*)(rp + g + c*4);
        size_t ko = (size_t)(b*SEQ + j0 + j)*DHD + g + c*4;
        *(__half2*)(KF + ko)     = __floats2half2_rn(kq.x, kq.y);
        *(__half2*)(KF + ko + 2) = __floats2half2_rn(kq.z, kq.w);
        float4 vq = *(const float4*)(rp + DHD + g + c*4);
        vt[j][g + c*4 + 0] = vq.x; vt[j][g + c*4 + 1] = vq.y;
        vt[j][g + c*4 + 2] = vq.z; vt[j][g + c*4 + 3] = vq.w;
    }
    __syncthreads();
    const int d = tid >> 2, jg = (tid & 3) * 16;
    #pragma unroll
    for (int i = 0; i < 16; i += 2) {
        float a = vt[jg + i][d], bb = vt[jg + i + 1][d];
        size_t vo = (size_t)(b*DHD + d)*SEQ + j0 + jg + i;
        *(__half2*)(VTF + vo) = __floats2half2_rn(a, bb);
    }
}

// ---------------------------------------------------------------------------
// HMMA GEMM fp16 2-product: C = (Ah+Al)[M,K] @ B^T, B single fp16 [N][K].
// MODE 0: fp32 C + bias.  MODE 1: cols<1024 -> single fp16 (q), col>=1024 -> fp32 kv.
// ---------------------------------------------------------------------------
#define GBK 32
#define GNSTG (KDIM/GBK)
#define GSTRIDE 40                  // elements; 80 bytes/row
#define GMATB (128*GSTRIDE*2)       // 10240 bytes per matrix
#define GSTGB (3*GMATB)             // 30720 per stage
#define GEMM_SMEM (2*GSTGB)         // 61440

template<int MODE>
__global__ __launch_bounds__(256) void gemm_mma(
    const __half* __restrict__ Ah, const __half* __restrict__ Al,
    const __half* __restrict__ Bf,
    float* __restrict__ C, const float* __restrict__ bias, int Ncols,
    __half* __restrict__ CF, float* __restrict__ C2)
{
    extern __shared__ __align__(16) char smem[];
    const uint32_t sbuf = s2u(smem);
    const int tid = threadIdx.x, wid = tid >> 5, lane = tid & 31;
    const int l4 = lane >> 2, c2 = (lane & 3) * 2;
    const int wm = wid & 3, wn = wid >> 2;
    const int bn = blockIdx.x, bm = blockIdx.y;

    const uint32_t ltermB = ((lane & 7) + ((lane >> 4) << 3)) * (GSTRIDE*2)
                          + (((lane >> 3) & 1) << 4);
    const uint32_t ltermA = ((lane & 7) + (((lane >> 3) & 1) << 3)) * (GSTRIDE*2)
                          + (((lane >> 4) & 1) << 4);

    const __half* pAh = Ah + (size_t)(bm*128)*KDIM;
    const __half* pAl = Al + (size_t)(bm*128)*KDIM;
    const __half* pB  = Bf + (size_t)(bn*128)*KDIM;

    const int r0 = tid >> 2, kc = tid & 3;
    const int r1 = r0 + 64;

    float acc[2][8][4];
    #pragma unroll
    for (int i = 0; i < 2; i++)
        #pragma unroll
        for (int j = 0; j < 8; j++)
            #pragma unroll
            for (int e = 0; e < 4; e++) acc[i][j][e] = 0.f;

    #define G_LOAD(S) do { \
        const int _k0 = (S) * GBK; \
        const uint32_t stb = sbuf + ((S) & 1) * GSTGB; \
        cp16(stb           + r0*80 + kc*16, pAh + (size_t)r0*KDIM + _k0 + kc*8); \
        cp16(stb           + r1*80 + kc*16, pAh + (size_t)r1*KDIM + _k0 + kc*8); \
        cp16(stb + GMATB   + r0*80 + kc*16, pAl + (size_t)r0*KDIM + _k0 + kc*8); \
        cp16(stb + GMATB   + r1*80 + kc*16, pAl + (size_t)r1*KDIM + _k0 + kc*8); \
        cp16(stb + 2*GMATB + r0*80 + kc*16, pB  + (size_t)r0*KDIM + _k0 + kc*8); \
        cp16(stb + 2*GMATB + r1*80 + kc*16, pB  + (size_t)r1*KDIM + _k0 + kc*8); \
    } while (0)

    G_LOAD(0); cp_commit();

    for (int s = 0; s < GNSTG; s++) {
        if (s + 1 < GNSTG) {
            G_LOAD(s + 1); cp_commit();
            asm volatile("cp.async.wait_group 1;" ::: "memory");
        } else {
            asm volatile("cp.async.wait_group 0;" ::: "memory");
        }
        __syncthreads();

        const uint32_t stb = sbuf + (s & 1) * GSTGB;
        const uint32_t aBaseH = stb            + (wm*32)*80 + ltermA;
        const uint32_t aBaseL = stb + GMATB    + (wm*32)*80 + ltermA;
        const uint32_t bBase  = stb + 2*GMATB  + (wn*64)*80 + ltermB;

        #pragma unroll
        for (int k16 = 0; k16 < 2; k16++) {
            const uint32_t kc2 = (uint32_t)k16 * 32;
            uint32_t ah[2][4], al[2][4], bb[4][4];
            #pragma unroll
            for (int mt = 0; mt < 2; mt++) ldsm_x4(ah[mt], aBaseH + mt*(16*80) + kc2);
            #pragma unroll
            for (int np = 0; np < 4; np++) ldsm_x4(bb[np], bBase + np*(16*80) + kc2);
            #pragma unroll
            for (int mt = 0; mt < 2; mt++)
                #pragma unroll
                for (int np = 0; np < 4; np++) {
                    mma16816h(acc[mt][2*np],   ah[mt], &bb[np][0]);
                    mma16816h(acc[mt][2*np+1], ah[mt], &bb[np][2]);
                }
            #pragma unroll
            for (int mt = 0; mt < 2; mt++) ldsm_x4(al[mt], aBaseL + mt*(16*80) + kc2);
            #pragma unroll
            for (int mt = 0; mt < 2; mt++)
                #pragma unroll
                for (int np = 0; np < 4; np++) {
                    mma16816h(acc[mt][2*np],   al[mt], &bb[np][0]);
                    mma16816h(acc[mt][2*np+1], al[mt], &bb[np][2]);
                }
        }
        __syncthreads();
    }
    #undef G_LOAD

    #pragma unroll
    for (int mt = 0; mt < 2; mt++) {
        const int rg0 = bm*128 + wm*32 + mt*16 + l4;
        #pragma unroll
        for (int nt = 0; nt < 8; nt++) {
            const int cg = bn*128 + wn*64 + nt*8 + c2;
            if (MODE == 0) {
                float b0 = bias ? bias[cg] : 0.f;
                float b1 = bias ? bias[cg+1] : 0.f;
                float2 v0 = { acc[mt][nt][0] + b0, acc[mt][nt][1] + b1 };
                float2 v1 = { acc[mt][nt][2] + b0, acc[mt][nt][3] + b1 };
                *(float2*)(C + (size_t)rg0*Ncols + cg)     = v0;
                *(float2*)(C + (size_t)(rg0+8)*Ncols + cg) = v1;
            } else {
                if (bn < 8) {
                    // q: single fp16
                    *(uint32_t*)(CF + (size_t)rg0*INNER_ + cg) =
                        pack_f16x2(acc[mt][nt][0], acc[mt][nt][1]);
                    *(uint32_t*)(CF + (size_t)(rg0+8)*INNER_ + cg) =
                        pack_f16x2(acc[mt][nt][2], acc[mt][nt][3]);
                } else {
                    const int cc = cg - 1024;
                    float2 v0 = { acc[mt][nt][0], acc[mt][nt][1] };
                    float2 v1 = { acc[mt][nt][2], acc[mt][nt][3] };
                    *(float2*)(C2 + (size_t)rg0*(2*DHD) + cc)     = v0;
                    *(float2*)(C2 + (size_t)(rg0+8)*(2*DHD) + cc) = v1;
                }
            }
        }
    }
}

// ---------------------------------------------------------------------------
// T5 relative-position bucket (mirrors jax fp32 math)
// ---------------------------------------------------------------------------
__device__ __forceinline__ int rel_bucket(int nn) {
    if (nn < 16) return nn;
    float t = logf((float)nn * (1.0f/16.0f)) / 2.0794415416798357f * 16.0f;
    int v = 16 + (int)t;
    return v < 31 ? v : 31;
}

// ---------------------------------------------------------------------------
// Flash attention v7: Q single fp16 (QK 1-product), PV 1-product, 2 CTAs/SM.
// 3-stage cp.async ring, ldmatrix, exp2 softmax.
// Grid (SEQ/128, HEADS, BATCH), 256 threads = 8 warps (warp w -> 16 rows).
// ---------------------------------------------------------------------------
#define FSTRIDE 72                  // elements; 144 bytes/row
#define FTILE   (64*FSTRIDE*2)      // 9216 bytes per tile
#define FKFO 0
#define FVFO (1*FTILE)
#define FSTG (2*FTILE)              // 18432 per stage
#define FBIAS (3*FSTG)              // 55296
#define FLASH_SMEM (FBIAS + 2048*4) // 63488

__global__ __launch_bounds__(256, 2) void flash2(
    const __half* __restrict__ QF,
    const __half* __restrict__ KF, const __half* __restrict__ VTF,
    const float* __restrict__ rel_emb,
    __half* __restrict__ AOH, __half* __restrict__ AOL)
{
    extern __shared__ __align__(16) char smem[];
    const uint32_t sb = s2u(smem);
    float* biasv = (float*)(smem + FBIAS);

    const int qtb = (SEQ/128 - 1) - blockIdx.x;
    const int h = blockIdx.y, b = blockIdx.z;
    const int tid = threadIdx.x, lane = tid & 31, w = tid >> 5;
    const int l4 = lane >> 2, c2 = (lane & 3) * 2;
    const int i0 = qtb * 128;
    const int wrow = i0 + w * 16;

    const uint32_t ltermB = ((lane & 7) + ((lane >> 4) << 3)) * (FSTRIDE*2)
                          + (((lane >> 3) & 1) << 4);

    for (int nn = tid; nn < 2048; nn += 256)
        biasv[nn] = rel_emb[rel_bucket(nn)*HEADS + h] * (8.0f * LOG2E);

    // Q fragments (single fp16): 16 regs
    uint32_t qf[4][4];
    {
        const size_t rb = (size_t)(b*SEQ + wrow + l4) * INNER_ + h*DHD;
        #pragma unroll
        for (int k16 = 0; k16 < 4; k16++) {
            const int c = k16*16 + c2;
            qf[k16][0] = *(const uint32_t*)(QF + rb + c);
            qf[k16][1] = *(const uint32_t*)(QF + rb + 8*INNER_ + c);
            qf[k16][2] = *(const uint32_t*)(QF + rb + c + 8);
            qf[k16][3] = *(const uint32_t*)(QF + rb + 8*INNER_ + c + 8);
        }
    }

    float o[8][4];
    #pragma unroll
    for (int nt = 0; nt < 8; nt++)
        #pragma unroll
        for (int e = 0; e < 4; e++) o[nt][e] = 0.f;
    float m0 = -INFINITY, m1 = -INFINITY, l0 = 0.f, l1 = 0.f;

    const int jmax = (i0 + 127) >> 6;
    const int iwmax = wrow + 15;

    #define LOADKV(JT, S) do { \
        const int _j0 = (JT) * 64; \
        const uint32_t _sb = sb + (uint32_t)(S) * FSTG; \
        _Pragma("unroll") \
        for (int q = 0; q < 2; q++) { \
            const int id = tid*2 + q; \
            const int r = id >> 3, cc = id & 7; \
            const uint32_t so = (uint32_t)(r*144 + cc*16); \
            const size_t ksrc = (size_t)(b*SEQ + _j0 + r)*DHD + cc*8; \
            cp16(_sb + FKFO + so, KF  + ksrc); \
            const size_t vsrc = (size_t)(b*DHD + r)*SEQ + _j0 + cc*8; \
            cp16(_sb + FVFO + so, VTF + vsrc); \
        } \
    } while (0)

    LOADKV(0, 0); cp_commit();
    LOADKV(1, 1); cp_commit();

    for (int jt = 0; jt <= jmax; jt++) {
        asm volatile("cp.async.wait_group 1;" ::: "memory");
        __syncthreads();
        if (jt + 2 <= jmax) LOADKV(jt + 2, (jt + 2) % 3);
        cp_commit();

        const int j0 = jt * 64;
        if (j0 <= iwmax) {
            const uint32_t stgb = sb + (uint32_t)(jt % 3) * FSTG;

            // ---- S = Q K^T (fp16 single product) ----
            float s[8][4];
            #pragma unroll
            for (int nt = 0; nt < 8; nt++)
                #pragma unroll
                for (int e = 0; e < 4; e++) s[nt][e] = 0.f;

            #pragma unroll
            for (int k16 = 0; k16 < 4; k16++) {
                const uint32_t kc2 = (uint32_t)k16 * 32;
                uint32_t kf4[4][4];
                #pragma unroll
                for (int np = 0; np < 4; np++)
                    ldsm_x4(kf4[np], stgb + FKFO + np*(16*144) + kc2 + ltermB);
                #pragma unroll
                for (int np = 0; np < 4; np++) {
                    mma16816h(s[2*np],   qf[k16], &kf4[np][0]);
                    mma16816h(s[2*np+1], qf[k16], &kf4[np][2]);
                }
            }

            // ---- bias + causal mask (log2 domain) ----
            const bool masked = (j0 + 63 > wrow);
            const int irow0 = wrow + l4;
            #pragma unroll
            for (int nt = 0; nt < 8; nt++) {
                #pragma unroll
                for (int e = 0; e < 4; e++) {
                    const int ri = irow0 + ((e >> 1) << 3);
                    const int cj = j0 + nt*8 + c2 + (e & 1);
                    const int nn = ri - cj;
                    if (masked && nn < 0) s[nt][e] = -INFINITY;
                    else                  s[nt][e] += biasv[nn];
                }
            }

            // ---- warp-local online softmax (exp2 domain) ----
            float mc0 = -INFINITY, mc1 = -INFINITY;
            #pragma unroll
            for (int nt = 0; nt < 8; nt++) {
                mc0 = fmaxf(mc0, fmaxf(s[nt][0], s[nt][1]));
                mc1 = fmaxf(mc1, fmaxf(s[nt][2], s[nt][3]));
            }
            mc0 = fmaxf(mc0, __shfl_xor_sync(0xffffffffu, mc0, 1));
            mc0 = fmaxf(mc0, __shfl_xor_sync(0xffffffffu, mc0, 2));
            mc1 = fmaxf(mc1, __shfl_xor_sync(0xffffffffu, mc1, 1));
            mc1 = fmaxf(mc1, __shfl_xor_sync(0xffffffffu, mc1, 2));
            const float mn0 = fmaxf(m0, mc0), mn1 = fmaxf(m1, mc1);
            const float sc0 = exp2f(m0 - mn0), sc1 = exp2f(m1 - mn1);
            m0 = mn0; m1 = mn1;

            float rs0 = 0.f, rs1 = 0.f;
            #pragma unroll
            for (int nt = 0; nt < 8; nt++) {
                s[nt][0] = exp2f(s[nt][0] - mn0);
                s[nt][1] = exp2f(s[nt][1] - mn0);
                s[nt][2] = exp2f(s[nt][2] - mn1);
                s[nt][3] = exp2f(s[nt][3] - mn1);
                rs0 += s[nt][0] + s[nt][1];
                rs1 += s[nt][2] + s[nt][3];
            }
            rs0 += __shfl_xor_sync(0xffffffffu, rs0, 1);
            rs0 += __shfl_xor_sync(0xffffffffu, rs0, 2);
            rs1 += __shfl_xor_sync(0xffffffffu, rs1, 1);
            rs1 += __shfl_xor_sync(0xffffffffu, rs1, 2);
            l0 = l0*sc0 + rs0;
            l1 = l1*sc1 + rs1;

            #pragma unroll
            for (int nt = 0; nt < 8; nt++) {
                o[nt][0] *= sc0; o[nt][1] *= sc0;
                o[nt][2] *= sc1; o[nt][3] *= sc1;
            }

            // ---- O += P V (fp16 single product) ----
            #pragma unroll
            for (int kk = 0; kk < 4; kk++) {
                uint32_t pf[4];
                pf[0] = pack_f16x2(s[2*kk  ][0], s[2*kk  ][1]);
                pf[1] = pack_f16x2(s[2*kk  ][2], s[2*kk  ][3]);
                pf[2] = pack_f16x2(s[2*kk+1][0], s[2*kk+1][1]);
                pf[3] = pack_f16x2(s[2*kk+1][2], s[2*kk+1][3]);
                const uint32_t kc2 = (uint32_t)kk * 32;
                uint32_t vf[4][4];
                #pragma unroll
                for (int np = 0; np < 4; np++)
                    ldsm_x4(vf[np], stgb + FVFO + np*(16*144) + kc2 + ltermB);
                #pragma unroll
                for (int np = 0; np < 4; np++) {
                    mma16816h(o[2*np],   pf, &vf[np][0]);
                    mma16816h(o[2*np+1], pf, &vf[np][2]);
                }
            }
        }
    }
    #undef LOADKV

    // ---- normalize + write split fp16 output ----
    {
        const float inv0 = 1.0f / l0, inv1 = 1.0f / l1;
        const size_t rb = (size_t)(b*SEQ + wrow + l4) * INNER_ + h*DHD;
        #pragma unroll
        for (int nt = 0; nt < 8; nt++) {
            const int col = nt*8 + c2;
            uint32_t ph, pl;
            pack_hl16(o[nt][0]*inv0, o[nt][1]*inv0, ph, pl);
            *(uint32_t*)(AOH + rb + col) = ph;
            *(uint32_t*)(AOL + rb + col) = pl;
            pack_hl16(o[nt][2]*inv1, o[nt][3]*inv1, ph, pl);
            *(uint32_t*)(AOH + rb + 8*INNER_ + col) = ph;
            *(uint32_t*)(AOL + rb + 8*INNER_ + col) = pl;
        }
    }
}

// ---------------------------------------------------------------------------
extern "C" void kernel_launch(void* const* d_in, const int* in_sizes, int n_in,
                              void* d_out, int out_size)
{
    const float* x       = (const float*)d_in[0];
    const float* Wq      = (const float*)d_in[1];
    const float* Wkv     = (const float*)d_in[2];
    const float* Wout    = (const float*)d_in[3];
    const float* bout    = (const float*)d_in[4];
    const float* rel_emb = (const float*)d_in[5];
    float* out = (float*)d_out;

    void* p;
    cudaGetSymbolAddress(&p, g_kv);   float* kvp = (float*)p;
    cudaGetSymbolAddress(&p, g_qf);   __half* qf  = (__half*)p;
    cudaGetSymbolAddress(&p, g_kf);   __half* kf  = (__half*)p;
    cudaGetSymbolAddress(&p, g_vtf);  __half* vtf = (__half*)p;
    cudaGetSymbolAddress(&p, g_aoh);  __half* aoh = (__half*)p;
    cudaGetSymbolAddress(&p, g_aol);  __half* aol = (__half*)p;
    cudaGetSymbolAddress(&p, g_xh);   __half* xh  = (__half*)p;
    cudaGetSymbolAddress(&p, g_xl);   __half* xl  = (__half*)p;
    cudaGetSymbolAddress(&p, g_wcf);  __half* wcf = (__half*)p;
    cudaGetSymbolAddress(&p, g_wof);  __half* wof = (__half*)p;

    cudaFuncSetAttribute(gemm_mma<0>, cudaFuncAttributeMaxDynamicSharedMemorySize, GEMM_SMEM);
    cudaFuncSetAttribute(gemm_mma<1>, cudaFuncAttributeMaxDynamicSharedMemorySize, GEMM_SMEM);
    cudaFuncSetAttribute(flash2, cudaFuncAttributeMaxDynamicSharedMemorySize, FLASH_SMEM);

    dim3 tb(32, 8);
    // weight prep (Wq pre-scaled by dim_head^-0.5 * log2e for exp2-domain softmax)
    transpose_f16_kernel<<<dim3(INNER_/32, DIMM/32), tb>>>(Wq,  wcf, DIMM, INNER_, 0.125f * LOG2E);
    transpose_f16_kernel<<<dim3((2*DHD)/32, DIMM/32), tb>>>(Wkv, wcf + (size_t)INNER_*DIMM, DIMM, 2*DHD, 1.0f);
    transpose_f16_kernel<<<dim3(DIMM/32, INNER_/32), tb>>>(Wout, wof, INNER_, DIMM, 1.0f);
    split_kernel<<<(ROWS*DIMM/4 + 255)/256, 256>>>(x, xh, xl, ROWS*DIMM/4);

    // fused q|kv projection: q single fp16, kv fp32
    gemm_mma<1><<<dim3(9, ROWS/128), 256, GEMM_SMEM>>>(xh, xl, wcf,
                                                       nullptr, nullptr, 0, qf, kvp);
    // kv -> K fp16 + transposed V fp16
    kvsplit_kernel<<<dim3(SEQ/64, BATCH), 256>>>(kvp, kf, vtf);
    // attention
    flash2<<<dim3(SEQ/128, HEADS, BATCH), 256, FLASH_SMEM>>>(qf, kf, vtf,
                                                             rel_emb, aoh, aol);
    // out = ao @ Wout + bout
    gemm_mma<0><<<dim3(DIMM/128, ROWS/128), 256, GEMM_SMEM>>>(aoh, aol, wof,
                                                              out, bout, DIMM,
                                                              nullptr, nullptr);
}

// round 12
// speedup vs baseline: 2.4204x; 1.3371x over previous
#include <cuda_runtime.h>
#include <cuda_bf16.h>
#include <cuda_fp16.h>
#include <math.h>
#include <stdint.h>

#define BATCH 2
#define SEQ   2048
#define DIMM  1024
#define HEADS 16
#define DHD   64
#define INNER_ (HEADS*DHD)      // 1024
#define ROWS  (BATCH*SEQ)       // 4096
#define KDIM  1024
#define LOG2E 1.4426950408889634f

// ---------------- scratch (no cudaMalloc allowed) ----------------
__device__ __align__(256) float  g_kv [ROWS*2*DHD];
__device__ __align__(256) __half g_qf [ROWS*INNER_];
__device__ __align__(256) __half g_kf [BATCH*SEQ*DHD];
__device__ __align__(256) __half g_vtf[BATCH*DHD*SEQ];
__device__ __align__(256) __half g_aof[ROWS*INNER_];
__device__ __align__(256) __half g_xf [ROWS*DIMM];
__device__ __align__(256) __half g_wcf[(INNER_+2*DHD)*DIMM];   // [Wq^T ; Wkv^T] fp16
__device__ __align__(256) __half g_wof[DIMM*INNER_];           // Wout^T fp16

// ---------------- helpers ----------------
__device__ __forceinline__ uint32_t s2u(const void* p) {
    uint32_t a;
    asm("{ .reg .u64 t; cvta.to.shared.u64 t, %1; cvt.u32.u64 %0, t; }"
        : "=r"(a) : "l"(p));
    return a;
}
__device__ __forceinline__ void cp16(uint32_t dst, const void* src) {
    asm volatile("cp.async.cg.shared.global [%0], [%1], 16;" :: "r"(dst), "l"(src));
}
__device__ __forceinline__ void cp_commit() { asm volatile("cp.async.commit_group;" ::: "memory"); }

__device__ __forceinline__ void mma16816h(float c[4], const uint32_t a[4], const uint32_t b[2]) {
    asm volatile("mma.sync.aligned.m16n8k16.row.col.f32.f16.f16.f32 "
        "{%0,%1,%2,%3}, {%4,%5,%6,%7}, {%8,%9}, {%0,%1,%2,%3};"
        : "+f"(c[0]), "+f"(c[1]), "+f"(c[2]), "+f"(c[3])
        : "r"(a[0]), "r"(a[1]), "r"(a[2]), "r"(a[3]), "r"(b[0]), "r"(b[1]));
}

// ldmatrix x4
__device__ __forceinline__ void ldsm_x4(uint32_t r[4], uint32_t saddr) {
    asm volatile("ldmatrix.sync.aligned.m8n8.x4.shared.b16 {%0,%1,%2,%3}, [%4];"
        : "=r"(r[0]), "=r"(r[1]), "=r"(r[2]), "=r"(r[3]) : "r"(saddr));
}

// pack two floats -> fp16x2 (first arg = low half)
__device__ __forceinline__ uint32_t pack_f16x2(float lo, float hi) {
    uint32_t r;
    asm("cvt.rn.f16x2.f32 %0, %1, %2;" : "=r"(r) : "f"(hi), "f"(lo));
    return r;
}

// ---------------------------------------------------------------------------
// Prep kernels
// ---------------------------------------------------------------------------
__global__ __launch_bounds__(256) void convert_f16_kernel(
    const float* __restrict__ A, __half* __restrict__ F, int n4)
{
    int i = blockIdx.x * blockDim.x + threadIdx.x;
    if (i >= n4) return;
    float4 a = ((const float4*)A)[i];
    ((uint32_t*)F)[2*i]   = pack_f16x2(a.x, a.y);
    ((uint32_t*)F)[2*i+1] = pack_f16x2(a.z, a.w);
}

// transpose to [N][K] fp16 single
__global__ __launch_bounds__(256) void transpose_f16_kernel(
    const float* __restrict__ W, __half* __restrict__ T,
    int K, int N, float scale)
{
    __shared__ float tile[32][33];
    const int tx = threadIdx.x, ty = threadIdx.y;
    const int n0 = blockIdx.x * 32, k0 = blockIdx.y * 32;
    #pragma unroll
    for (int i = 0; i < 4; i++)
        tile[ty + 8*i][tx] = W[(size_t)(k0 + ty + 8*i) * N + n0 + tx];
    __syncthreads();
    #pragma unroll
    for (int i = 0; i < 4; i++) {
        float a = tile[tx][ty + 8*i] * scale;
        T[(size_t)(n0 + ty + 8*i) * K + k0 + tx] = __float2half_rn(a);
    }
}

// kv fp32 -> K fp16 [b][j][64], V^T fp16 [b][d][SEQ]
__global__ __launch_bounds__(256) void kvsplit_kernel(
    const float* __restrict__ KVin,
    __half* __restrict__ KF, __half* __restrict__ VTF)
{
    __shared__ float vt[64][65];
    const int b = blockIdx.y, j0 = blockIdx.x * 64;
    const int tid = threadIdx.x;
    const int j = tid >> 2, g = (tid & 3) * 16;
    const float* rp = KVin + (size_t)(b*SEQ + j0 + j) * (2*DHD);
    #pragma unroll
    for (int c = 0; c < 4; c++) {
        float4 kq = *(const float4*)(rp + g + c*4);
        size_t ko = (size_t)(b*SEQ + j0 + j)*DHD + g + c*4;
        *(__half2*)(KF + ko)     = __floats2half2_rn(kq.x, kq.y);
        *(__half2*)(KF + ko + 2) = __floats2half2_rn(kq.z, kq.w);
        float4 vq = *(const float4*)(rp + DHD + g + c*4);
        vt[j][g + c*4 + 0] = vq.x; vt[j][g + c*4 + 1] = vq.y;
        vt[j][g + c*4 + 2] = vq.z; vt[j][g + c*4 + 3] = vq.w;
    }
    __syncthreads();
    const int d = tid >> 2, jg = (tid & 3) * 16;
    #pragma unroll
    for (int i = 0; i < 16; i += 2) {
        float a = vt[jg + i][d], bb = vt[jg + i + 1][d];
        size_t vo = (size_t)(b*DHD + d)*SEQ + j0 + jg + i;
        *(__half2*)(VTF + vo) = __floats2half2_rn(a, bb);
    }
}

// ---------------------------------------------------------------------------
// HMMA GEMM fp16 single-product: C = A[M,K] @ B^T, both fp16 [.][K].
// CTA 128x128, BK=32, 2-stage cp.async, 8 warps x 32x64, 2 CTAs/SM.
// MODE 0: fp32 C + bias.  MODE 1: cols<1024 -> fp16 (q), col>=1024 -> fp32 kv.
// ---------------------------------------------------------------------------
#define GBK 32
#define GNSTG (KDIM/GBK)
#define GSTRIDE 40                  // elements; 80 bytes/row
#define GMATB (128*GSTRIDE*2)       // 10240 bytes per matrix
#define GSTGB (2*GMATB)             // 20480 per stage
#define GEMM_SMEM (2*GSTGB)         // 40960

template<int MODE>
__global__ __launch_bounds__(256, 2) void gemm_mma(
    const __half* __restrict__ Af, const __half* __restrict__ Bf,
    float* __restrict__ C, const float* __restrict__ bias, int Ncols,
    __half* __restrict__ CF, float* __restrict__ C2)
{
    extern __shared__ __align__(16) char smem[];
    const uint32_t sbuf = s2u(smem);
    const int tid = threadIdx.x, wid = tid >> 5, lane = tid & 31;
    const int l4 = lane >> 2, c2 = (lane & 3) * 2;
    const int wm = wid & 3, wn = wid >> 2;
    const int bn = blockIdx.x, bm = blockIdx.y;

    const uint32_t ltermB = ((lane & 7) + ((lane >> 4) << 3)) * (GSTRIDE*2)
                          + (((lane >> 3) & 1) << 4);
    const uint32_t ltermA = ((lane & 7) + (((lane >> 3) & 1) << 3)) * (GSTRIDE*2)
                          + (((lane >> 4) & 1) << 4);

    const __half* pA = Af + (size_t)(bm*128)*KDIM;
    const __half* pB = Bf + (size_t)(bn*128)*KDIM;

    const int r0 = tid >> 2, kc = tid & 3;
    const int r1 = r0 + 64;

    float acc[2][8][4];
    #pragma unroll
    for (int i = 0; i < 2; i++)
        #pragma unroll
        for (int j = 0; j < 8; j++)
            #pragma unroll
            for (int e = 0; e < 4; e++) acc[i][j][e] = 0.f;

    #define G_LOAD(S) do { \
        const int _k0 = (S) * GBK; \
        const uint32_t stb = sbuf + ((S) & 1) * GSTGB; \
        cp16(stb         + r0*80 + kc*16, pA + (size_t)r0*KDIM + _k0 + kc*8); \
        cp16(stb         + r1*80 + kc*16, pA + (size_t)r1*KDIM + _k0 + kc*8); \
        cp16(stb + GMATB + r0*80 + kc*16, pB + (size_t)r0*KDIM + _k0 + kc*8); \
        cp16(stb + GMATB + r1*80 + kc*16, pB + (size_t)r1*KDIM + _k0 + kc*8); \
    } while (0)

    G_LOAD(0); cp_commit();

    for (int s = 0; s < GNSTG; s++) {
        if (s + 1 < GNSTG) {
            G_LOAD(s + 1); cp_commit();
            asm volatile("cp.async.wait_group 1;" ::: "memory");
        } else {
            asm volatile("cp.async.wait_group 0;" ::: "memory");
        }
        __syncthreads();

        const uint32_t stb = sbuf + (s & 1) * GSTGB;
        const uint32_t aBase = stb         + (wm*32)*80 + ltermA;
        const uint32_t bBase = stb + GMATB + (wn*64)*80 + ltermB;

        #pragma unroll
        for (int k16 = 0; k16 < 2; k16++) {
            const uint32_t kc2 = (uint32_t)k16 * 32;
            uint32_t ah[2][4], bb[4][4];
            #pragma unroll
            for (int mt = 0; mt < 2; mt++) ldsm_x4(ah[mt], aBase + mt*(16*80) + kc2);
            #pragma unroll
            for (int np = 0; np < 4; np++) ldsm_x4(bb[np], bBase + np*(16*80) + kc2);
            #pragma unroll
            for (int mt = 0; mt < 2; mt++)
                #pragma unroll
                for (int np = 0; np < 4; np++) {
                    mma16816h(acc[mt][2*np],   ah[mt], &bb[np][0]);
                    mma16816h(acc[mt][2*np+1], ah[mt], &bb[np][2]);
                }
        }
        __syncthreads();
    }
    #undef G_LOAD

    #pragma unroll
    for (int mt = 0; mt < 2; mt++) {
        const int rg0 = bm*128 + wm*32 + mt*16 + l4;
        #pragma unroll
        for (int nt = 0; nt < 8; nt++) {
            const int cg = bn*128 + wn*64 + nt*8 + c2;
            if (MODE == 0) {
                float b0 = bias ? bias[cg] : 0.f;
                float b1 = bias ? bias[cg+1] : 0.f;
                float2 v0 = { acc[mt][nt][0] + b0, acc[mt][nt][1] + b1 };
                float2 v1 = { acc[mt][nt][2] + b0, acc[mt][nt][3] + b1 };
                *(float2*)(C + (size_t)rg0*Ncols + cg)     = v0;
                *(float2*)(C + (size_t)(rg0+8)*Ncols + cg) = v1;
            } else {
                if (bn < 8) {
                    *(uint32_t*)(CF + (size_t)rg0*INNER_ + cg) =
                        pack_f16x2(acc[mt][nt][0], acc[mt][nt][1]);
                    *(uint32_t*)(CF + (size_t)(rg0+8)*INNER_ + cg) =
                        pack_f16x2(acc[mt][nt][2], acc[mt][nt][3]);
                } else {
                    const int cc = cg - 1024;
                    float2 v0 = { acc[mt][nt][0], acc[mt][nt][1] };
                    float2 v1 = { acc[mt][nt][2], acc[mt][nt][3] };
                    *(float2*)(C2 + (size_t)rg0*(2*DHD) + cc)     = v0;
                    *(float2*)(C2 + (size_t)(rg0+8)*(2*DHD) + cc) = v1;
                }
            }
        }
    }
}

// ---------------------------------------------------------------------------
// T5 relative-position bucket (mirrors jax fp32 math)
// ---------------------------------------------------------------------------
__device__ __forceinline__ int rel_bucket(int nn) {
    if (nn < 16) return nn;
    float t = logf((float)nn * (1.0f/16.0f)) / 2.0794415416798357f * 16.0f;
    int v = 16 + (int)t;
    return v < 31 ? v : 31;
}

// ---------------------------------------------------------------------------
// Flash attention v8: all single-fp16 mma, single fp16 output, 2 CTAs/SM.
// 3-stage cp.async ring, ldmatrix, exp2 softmax.
// Grid (SEQ/128, HEADS, BATCH), 256 threads = 8 warps (warp w -> 16 rows).
// ---------------------------------------------------------------------------
#define FSTRIDE 72                  // elements; 144 bytes/row
#define FTILE   (64*FSTRIDE*2)      // 9216 bytes per tile
#define FKFO 0
#define FVFO (1*FTILE)
#define FSTG (2*FTILE)              // 18432 per stage
#define FBIAS (3*FSTG)              // 55296
#define FLASH_SMEM (FBIAS + 2048*4) // 63488

__global__ __launch_bounds__(256, 2) void flash2(
    const __half* __restrict__ QF,
    const __half* __restrict__ KF, const __half* __restrict__ VTF,
    const float* __restrict__ rel_emb,
    __half* __restrict__ AOF)
{
    extern __shared__ __align__(16) char smem[];
    const uint32_t sb = s2u(smem);
    float* biasv = (float*)(smem + FBIAS);

    const int qtb = (SEQ/128 - 1) - blockIdx.x;
    const int h = blockIdx.y, b = blockIdx.z;
    const int tid = threadIdx.x, lane = tid & 31, w = tid >> 5;
    const int l4 = lane >> 2, c2 = (lane & 3) * 2;
    const int i0 = qtb * 128;
    const int wrow = i0 + w * 16;

    const uint32_t ltermB = ((lane & 7) + ((lane >> 4) << 3)) * (FSTRIDE*2)
                          + (((lane >> 3) & 1) << 4);

    for (int nn = tid; nn < 2048; nn += 256)
        biasv[nn] = rel_emb[rel_bucket(nn)*HEADS + h] * (8.0f * LOG2E);

    uint32_t qf[4][4];
    {
        const size_t rb = (size_t)(b*SEQ + wrow + l4) * INNER_ + h*DHD;
        #pragma unroll
        for (int k16 = 0; k16 < 4; k16++) {
            const int c = k16*16 + c2;
            qf[k16][0] = *(const uint32_t*)(QF + rb + c);
            qf[k16][1] = *(const uint32_t*)(QF + rb + 8*INNER_ + c);
            qf[k16][2] = *(const uint32_t*)(QF + rb + c + 8);
            qf[k16][3] = *(const uint32_t*)(QF + rb + 8*INNER_ + c + 8);
        }
    }

    float o[8][4];
    #pragma unroll
    for (int nt = 0; nt < 8; nt++)
        #pragma unroll
        for (int e = 0; e < 4; e++) o[nt][e] = 0.f;
    float m0 = -INFINITY, m1 = -INFINITY, l0 = 0.f, l1 = 0.f;

    const int jmax = (i0 + 127) >> 6;
    const int iwmax = wrow + 15;

    #define LOADKV(JT, S) do { \
        const int _j0 = (JT) * 64; \
        const uint32_t _sb = sb + (uint32_t)(S) * FSTG; \
        _Pragma("unroll") \
        for (int q = 0; q < 2; q++) { \
            const int id = tid*2 + q; \
            const int r = id >> 3, cc = id & 7; \
            const uint32_t so = (uint32_t)(r*144 + cc*16); \
            const size_t ksrc = (size_t)(b*SEQ + _j0 + r)*DHD + cc*8; \
            cp16(_sb + FKFO + so, KF  + ksrc); \
            const size_t vsrc = (size_t)(b*DHD + r)*SEQ + _j0 + cc*8; \
            cp16(_sb + FVFO + so, VTF + vsrc); \
        } \
    } while (0)

    LOADKV(0, 0); cp_commit();
    LOADKV(1, 1); cp_commit();

    for (int jt = 0; jt <= jmax; jt++) {
        asm volatile("cp.async.wait_group 1;" ::: "memory");
        __syncthreads();
        if (jt + 2 <= jmax) LOADKV(jt + 2, (jt + 2) % 3);
        cp_commit();

        const int j0 = jt * 64;
        if (j0 <= iwmax) {
            const uint32_t stgb = sb + (uint32_t)(jt % 3) * FSTG;

            // ---- S = Q K^T (fp16 single product) ----
            float s[8][4];
            #pragma unroll
            for (int nt = 0; nt < 8; nt++)
                #pragma unroll
                for (int e = 0; e < 4; e++) s[nt][e] = 0.f;

            #pragma unroll
            for (int k16 = 0; k16 < 4; k16++) {
                const uint32_t kc2 = (uint32_t)k16 * 32;
                uint32_t kf4[4][4];
                #pragma unroll
                for (int np = 0; np < 4; np++)
                    ldsm_x4(kf4[np], stgb + FKFO + np*(16*144) + kc2 + ltermB);
                #pragma unroll
                for (int np = 0; np < 4; np++) {
                    mma16816h(s[2*np],   qf[k16], &kf4[np][0]);
                    mma16816h(s[2*np+1], qf[k16], &kf4[np][2]);
                }
            }

            // ---- bias + causal mask (log2 domain) ----
            const bool masked = (j0 + 63 > wrow);
            const int irow0 = wrow + l4;
            #pragma unroll
            for (int nt = 0; nt < 8; nt++) {
                #pragma unroll
                for (int e = 0; e < 4; e++) {
                    const int ri = irow0 + ((e >> 1) << 3);
                    const int cj = j0 + nt*8 + c2 + (e & 1);
                    const int nn = ri - cj;
                    if (masked && nn < 0) s[nt][e] = -INFINITY;
                    else                  s[nt][e] += biasv[nn];
                }
            }

            // ---- warp-local online softmax (exp2 domain) ----
            float mc0 = -INFINITY, mc1 = -INFINITY;
            #pragma unroll
            for (int nt = 0; nt < 8; nt++) {
                mc0 = fmaxf(mc0, fmaxf(s[nt][0], s[nt][1]));
                mc1 = fmaxf(mc1, fmaxf(s[nt][2], s[nt][3]));
            }
            mc0 = fmaxf(mc0, __shfl_xor_sync(0xffffffffu, mc0, 1));
            mc0 = fmaxf(mc0, __shfl_xor_sync(0xffffffffu, mc0, 2));
            mc1 = fmaxf(mc1, __shfl_xor_sync(0xffffffffu, mc1, 1));
            mc1 = fmaxf(mc1, __shfl_xor_sync(0xffffffffu, mc1, 2));
            const float mn0 = fmaxf(m0, mc0), mn1 = fmaxf(m1, mc1);
            const float sc0 = exp2f(m0 - mn0), sc1 = exp2f(m1 - mn1);
            m0 = mn0; m1 = mn1;

            float rs0 = 0.f, rs1 = 0.f;
            #pragma unroll
            for (int nt = 0; nt < 8; nt++) {
                s[nt][0] = exp2f(s[nt][0] - mn0);
                s[nt][1] = exp2f(s[nt][1] - mn0);
                s[nt][2] = exp2f(s[nt][2] - mn1);
                s[nt][3] = exp2f(s[nt][3] - mn1);
                rs0 += s[nt][0] + s[nt][1];
                rs1 += s[nt][2] + s[nt][3];
            }
            rs0 += __shfl_xor_sync(0xffffffffu, rs0, 1);
            rs0 += __shfl_xor_sync(0xffffffffu, rs0, 2);
            rs1 += __shfl_xor_sync(0xffffffffu, rs1, 1);
            rs1 += __shfl_xor_sync(0xffffffffu, rs1, 2);
            l0 = l0*sc0 + rs0;
            l1 = l1*sc1 + rs1;

            #pragma unroll
            for (int nt = 0; nt < 8; nt++) {
                o[nt][0] *= sc0; o[nt][1] *= sc0;
                o[nt][2] *= sc1; o[nt][3] *= sc1;
            }

            // ---- O += P V (fp16 single product) ----
            #pragma unroll
            for (int kk = 0; kk < 4; kk++) {
                uint32_t pf[4];
                pf[0] = pack_f16x2(s[2*kk  ][0], s[2*kk  ][1]);
                pf[1] = pack_f16x2(s[2*kk  ][2], s[2*kk  ][3]);
                pf[2] = pack_f16x2(s[2*kk+1][0], s[2*kk+1][1]);
                pf[3] = pack_f16x2(s[2*kk+1][2], s[2*kk+1][3]);
                const uint32_t kc2 = (uint32_t)kk * 32;
                uint32_t vf[4][4];
                #pragma unroll
                for (int np = 0; np < 4; np++)
                    ldsm_x4(vf[np], stgb + FVFO + np*(16*144) + kc2 + ltermB);
                #pragma unroll
                for (int np = 0; np < 4; np++) {
                    mma16816h(o[2*np],   pf, &vf[np][0]);
                    mma16816h(o[2*np+1], pf, &vf[np][2]);
                }
            }
        }
    }
    #undef LOADKV

    // ---- normalize + write fp16 output ----
    {
        const float inv0 = 1.0f / l0, inv1 = 1.0f / l1;
        const size_t rb = (size_t)(b*SEQ + wrow + l4) * INNER_ + h*DHD;
        #pragma unroll
        for (int nt = 0; nt < 8; nt++) {
            const int col = nt*8 + c2;
            *(uint32_t*)(AOF + rb + col) =
                pack_f16x2(o[nt][0]*inv0, o[nt][1]*inv0);
            *(uint32_t*)(AOF + rb + 8*INNER_ + col) =
                pack_f16x2(o[nt][2]*inv1, o[nt][3]*inv1);
        }
    }
}

// ---------------------------------------------------------------------------
extern "C" void kernel_launch(void* const* d_in, const int* in_sizes, int n_in,
                              void* d_out, int out_size)
{
    const float* x       = (const float*)d_in[0];
    const float* Wq      = (const float*)d_in[1];
    const float* Wkv     = (const float*)d_in[2];
    const float* Wout    = (const float*)d_in[3];
    const float* bout    = (const float*)d_in[4];
    const float* rel_emb = (const float*)d_in[5];
    float* out = (float*)d_out;

    void* p;
    cudaGetSymbolAddress(&p, g_kv);   float* kvp = (float*)p;
    cudaGetSymbolAddress(&p, g_qf);   __half* qf  = (__half*)p;
    cudaGetSymbolAddress(&p, g_kf);   __half* kf  = (__half*)p;
    cudaGetSymbolAddress(&p, g_vtf);  __half* vtf = (__half*)p;
    cudaGetSymbolAddress(&p, g_aof);  __half* aof = (__half*)p;
    cudaGetSymbolAddress(&p, g_xf);   __half* xf  = (__half*)p;
    cudaGetSymbolAddress(&p, g_wcf);  __half* wcf = (__half*)p;
    cudaGetSymbolAddress(&p, g_wof);  __half* wof = (__half*)p;

    cudaFuncSetAttribute(gemm_mma<0>, cudaFuncAttributeMaxDynamicSharedMemorySize, GEMM_SMEM);
    cudaFuncSetAttribute(gemm_mma<1>, cudaFuncAttributeMaxDynamicSharedMemorySize, GEMM_SMEM);
    cudaFuncSetAttribute(flash2, cudaFuncAttributeMaxDynamicSharedMemorySize, FLASH_SMEM);

    dim3 tb(32, 8);
    // weight prep (Wq pre-scaled by dim_head^-0.5 * log2e for exp2-domain softmax)
    transpose_f16_kernel<<<dim3(INNER_/32, DIMM/32), tb>>>(Wq,  wcf, DIMM, INNER_, 0.125f * LOG2E);
    transpose_f16_kernel<<<dim3((2*DHD)/32, DIMM/32), tb>>>(Wkv, wcf + (size_t)INNER_*DIMM, DIMM, 2*DHD, 1.0f);
    transpose_f16_kernel<<<dim3(DIMM/32, INNER_/32), tb>>>(Wout, wof, INNER_, DIMM, 1.0f);
    convert_f16_kernel<<<(ROWS*DIMM/4 + 255)/256, 256>>>(x, xf, ROWS*DIMM/4);

    // fused q|kv projection: q fp16, kv fp32
    gemm_mma<1><<<dim3(9, ROWS/128), 256, GEMM_SMEM>>>(xf, wcf,
                                                       nullptr, nullptr, 0, qf, kvp);
    // kv -> K fp16 + transposed V fp16
    kvsplit_kernel<<<dim3(SEQ/64, BATCH), 256>>>(kvp, kf, vtf);
    // attention
    flash2<<<dim3(SEQ/128, HEADS, BATCH), 256, FLASH_SMEM>>>(qf, kf, vtf,
                                                             rel_emb, aof);
    // out = ao @ Wout + bout
    gemm_mma<0><<<dim3(DIMM/128, ROWS/128), 256, GEMM_SMEM>>>(aof, wof,
                                                              out, bout, DIMM,
                                                              nullptr, nullptr);
}

// round 13
// speedup vs baseline: 2.4502x; 1.0123x over previous
#include <cuda_runtime.h>
#include <cuda_bf16.h>
#include <cuda_fp16.h>
#include <math.h>
#include <stdint.h>

#define BATCH 2
#define SEQ   2048
#define DIMM  1024
#define HEADS 16
#define DHD   64
#define INNER_ (HEADS*DHD)      // 1024
#define ROWS  (BATCH*SEQ)       // 4096
#define KDIM  1024
#define LOG2E 1.4426950408889634f

// ---------------- scratch (no cudaMalloc allowed) ----------------
__device__ __align__(256) __half g_qf [ROWS*INNER_];
__device__ __align__(256) __half g_kf [BATCH*SEQ*DHD];
__device__ __align__(256) __half g_vtf[BATCH*DHD*SEQ];
__device__ __align__(256) __half g_aof[ROWS*INNER_];
__device__ __align__(256) __half g_xf [ROWS*DIMM];
__device__ __align__(256) __half g_wcf[(INNER_+2*DHD)*DIMM];   // [Wq^T ; Wkv^T] fp16
__device__ __align__(256) __half g_wof[DIMM*INNER_];           // Wout^T fp16

// ---------------- helpers ----------------
__device__ __forceinline__ uint32_t s2u(const void* p) {
    uint32_t a;
    asm("{ .reg .u64 t; cvta.to.shared.u64 t, %1; cvt.u32.u64 %0, t; }"
        : "=r"(a) : "l"(p));
    return a;
}
__device__ __forceinline__ void cp16(uint32_t dst, const void* src) {
    asm volatile("cp.async.cg.shared.global [%0], [%1], 16;" :: "r"(dst), "l"(src));
}
__device__ __forceinline__ void cp_commit() { asm volatile("cp.async.commit_group;" ::: "memory"); }

__device__ __forceinline__ void mma16816h(float c[4], const uint32_t a[4], const uint32_t b[2]) {
    asm volatile("mma.sync.aligned.m16n8k16.row.col.f32.f16.f16.f32 "
        "{%0,%1,%2,%3}, {%4,%5,%6,%7}, {%8,%9}, {%0,%1,%2,%3};"
        : "+f"(c[0]), "+f"(c[1]), "+f"(c[2]), "+f"(c[3])
        : "r"(a[0]), "r"(a[1]), "r"(a[2]), "r"(a[3]), "r"(b[0]), "r"(b[1]));
}

// ldmatrix x4
__device__ __forceinline__ void ldsm_x4(uint32_t r[4], uint32_t saddr) {
    asm volatile("ldmatrix.sync.aligned.m8n8.x4.shared.b16 {%0,%1,%2,%3}, [%4];"
        : "=r"(r[0]), "=r"(r[1]), "=r"(r[2]), "=r"(r[3]) : "r"(saddr));
}

// pack two floats -> fp16x2 (first arg = low half)
__device__ __forceinline__ uint32_t pack_f16x2(float lo, float hi) {
    uint32_t r;
    asm("cvt.rn.f16x2.f32 %0, %1, %2;" : "=r"(r) : "f"(hi), "f"(lo));
    return r;
}

// ---------------------------------------------------------------------------
// Prep kernels
// ---------------------------------------------------------------------------
__global__ __launch_bounds__(256) void convert_f16_kernel(
    const float* __restrict__ A, __half* __restrict__ F, int n4)
{
    int i = blockIdx.x * blockDim.x + threadIdx.x;
    if (i >= n4) return;
    float4 a = ((const float4*)A)[i];
    ((uint32_t*)F)[2*i]   = pack_f16x2(a.x, a.y);
    ((uint32_t*)F)[2*i+1] = pack_f16x2(a.z, a.w);
}

// transpose to [N][K] fp16 single (generic)
__global__ __launch_bounds__(256) void transpose_f16_kernel(
    const float* __restrict__ W, __half* __restrict__ T,
    int K, int N, float scale)
{
    __shared__ float tile[32][33];
    const int tx = threadIdx.x, ty = threadIdx.y;
    const int n0 = blockIdx.x * 32, k0 = blockIdx.y * 32;
    #pragma unroll
    for (int i = 0; i < 4; i++)
        tile[ty + 8*i][tx] = W[(size_t)(k0 + ty + 8*i) * N + n0 + tx];
    __syncthreads();
    #pragma unroll
    for (int i = 0; i < 4; i++) {
        float a = tile[tx][ty + 8*i] * scale;
        T[(size_t)(n0 + ty + 8*i) * K + k0 + tx] = __float2half_rn(a);
    }
}

// fused [Wq ; Wkv] transpose into g_wcf: rows 0..1023 from Wq (scaled),
// rows 1024..1151 from Wkv. Grid x = 1152/32 = 36.
__global__ __launch_bounds__(256) void transpose_wc_kernel(
    const float* __restrict__ Wq, const float* __restrict__ Wkv,
    __half* __restrict__ T)
{
    __shared__ float tile[32][33];
    const int tx = threadIdx.x, ty = threadIdx.y;
    const int n0 = blockIdx.x * 32, k0 = blockIdx.y * 32;
    const bool isq = (n0 < INNER_);
    const float* W = isq ? Wq : Wkv;
    const int N = isq ? INNER_ : 2*DHD;
    const int cb = isq ? n0 : n0 - INNER_;
    const float scale = isq ? 0.125f * LOG2E : 1.0f;
    #pragma unroll
    for (int i = 0; i < 4; i++)
        tile[ty + 8*i][tx] = W[(size_t)(k0 + ty + 8*i) * N + cb + tx];
    __syncthreads();
    #pragma unroll
    for (int i = 0; i < 4; i++) {
        float a = tile[tx][ty + 8*i] * scale;
        T[(size_t)(n0 + ty + 8*i) * KDIM + k0 + tx] = __float2half_rn(a);
    }
}

// ---------------------------------------------------------------------------
// HMMA GEMM fp16 single-product: C = A[M,K] @ B^T, both fp16 [.][K].
// CTA 128x128, BK=32, 2-stage cp.async, 8 warps x 32x64, 2 CTAs/SM.
// MODE 0: fp32 C + bias.
// MODE 1: bn<8 -> fp16 q; bn==8 -> K fp16 (cols 0..63) + V^T fp16 (cols 64..127).
// ---------------------------------------------------------------------------
#define GBK 32
#define GNSTG (KDIM/GBK)
#define GSTRIDE 40                  // elements; 80 bytes/row
#define GMATB (128*GSTRIDE*2)       // 10240 bytes per matrix
#define GSTGB (2*GMATB)             // 20480 per stage
#define GEMM_SMEM (2*GSTGB)         // 40960

template<int MODE>
__global__ __launch_bounds__(256, 2) void gemm_mma(
    const __half* __restrict__ Af, const __half* __restrict__ Bf,
    float* __restrict__ C, const float* __restrict__ bias, int Ncols,
    __half* __restrict__ CF, __half* __restrict__ KF, __half* __restrict__ VTF)
{
    extern __shared__ __align__(16) char smem[];
    const uint32_t sbuf = s2u(smem);
    const int tid = threadIdx.x, wid = tid >> 5, lane = tid & 31;
    const int l4 = lane >> 2, c2 = (lane & 3) * 2;
    const int wm = wid & 3, wn = wid >> 2;
    const int bn = blockIdx.x, bm = blockIdx.y;

    const uint32_t ltermB = ((lane & 7) + ((lane >> 4) << 3)) * (GSTRIDE*2)
                          + (((lane >> 3) & 1) << 4);
    const uint32_t ltermA = ((lane & 7) + (((lane >> 3) & 1) << 3)) * (GSTRIDE*2)
                          + (((lane >> 4) & 1) << 4);

    const __half* pA = Af + (size_t)(bm*128)*KDIM;
    const __half* pB = Bf + (size_t)(bn*128)*KDIM;

    const int r0 = tid >> 2, kc = tid & 3;
    const int r1 = r0 + 64;

    float acc[2][8][4];
    #pragma unroll
    for (int i = 0; i < 2; i++)
        #pragma unroll
        for (int j = 0; j < 8; j++)
            #pragma unroll
            for (int e = 0; e < 4; e++) acc[i][j][e] = 0.f;

    #define G_LOAD(S) do { \
        const int _k0 = (S) * GBK; \
        const uint32_t stb = sbuf + ((S) & 1) * GSTGB; \
        cp16(stb         + r0*80 + kc*16, pA + (size_t)r0*KDIM + _k0 + kc*8); \
        cp16(stb         + r1*80 + kc*16, pA + (size_t)r1*KDIM + _k0 + kc*8); \
        cp16(stb + GMATB + r0*80 + kc*16, pB + (size_t)r0*KDIM + _k0 + kc*8); \
        cp16(stb + GMATB + r1*80 + kc*16, pB + (size_t)r1*KDIM + _k0 + kc*8); \
    } while (0)

    G_LOAD(0); cp_commit();

    for (int s = 0; s < GNSTG; s++) {
        if (s + 1 < GNSTG) {
            G_LOAD(s + 1); cp_commit();
            asm volatile("cp.async.wait_group 1;" ::: "memory");
        } else {
            asm volatile("cp.async.wait_group 0;" ::: "memory");
        }
        __syncthreads();

        const uint32_t stb = sbuf + (s & 1) * GSTGB;
        const uint32_t aBase = stb         + (wm*32)*80 + ltermA;
        const uint32_t bBase = stb + GMATB + (wn*64)*80 + ltermB;

        #pragma unroll
        for (int k16 = 0; k16 < 2; k16++) {
            const uint32_t kc2 = (uint32_t)k16 * 32;
            uint32_t ah[2][4], bb[4][4];
            #pragma unroll
            for (int mt = 0; mt < 2; mt++) ldsm_x4(ah[mt], aBase + mt*(16*80) + kc2);
            #pragma unroll
            for (int np = 0; np < 4; np++) ldsm_x4(bb[np], bBase + np*(16*80) + kc2);
            #pragma unroll
            for (int mt = 0; mt < 2; mt++)
                #pragma unroll
                for (int np = 0; np < 4; np++) {
                    mma16816h(acc[mt][2*np],   ah[mt], &bb[np][0]);
                    mma16816h(acc[mt][2*np+1], ah[mt], &bb[np][2]);
                }
        }
        __syncthreads();
    }
    #undef G_LOAD

    #pragma unroll
    for (int mt = 0; mt < 2; mt++) {
        const int rg0 = bm*128 + wm*32 + mt*16 + l4;
        #pragma unroll
        for (int nt = 0; nt < 8; nt++) {
            const int cg = bn*128 + wn*64 + nt*8 + c2;
            if (MODE == 0) {
                float b0 = bias ? bias[cg] : 0.f;
                float b1 = bias ? bias[cg+1] : 0.f;
                float2 v0 = { acc[mt][nt][0] + b0, acc[mt][nt][1] + b1 };
                float2 v1 = { acc[mt][nt][2] + b0, acc[mt][nt][3] + b1 };
                *(float2*)(C + (size_t)rg0*Ncols + cg)     = v0;
                *(float2*)(C + (size_t)(rg0+8)*Ncols + cg) = v1;
            } else {
                if (bn < 8) {
                    *(uint32_t*)(CF + (size_t)rg0*INNER_ + cg) =
                        pack_f16x2(acc[mt][nt][0], acc[mt][nt][1]);
                    *(uint32_t*)(CF + (size_t)(rg0+8)*INNER_ + cg) =
                        pack_f16x2(acc[mt][nt][2], acc[mt][nt][3]);
                } else if (wn == 0) {
                    // K half: cols 1024..1087 -> KF [row][0..63], row-major
                    const int kcol = cg - 1024;
                    *(uint32_t*)(KF + (size_t)rg0*DHD + kcol) =
                        pack_f16x2(acc[mt][nt][0], acc[mt][nt][1]);
                    *(uint32_t*)(KF + (size_t)(rg0+8)*DHD + kcol) =
                        pack_f16x2(acc[mt][nt][2], acc[mt][nt][3]);
                } else {
                    // V half: cols 1088..1151 -> VTF [b*DHD + d][SEQ] transposed
                    const int d0 = cg - 1088;
                    const int bb_ = rg0 >> 11;
                    const int rl = rg0 & (SEQ - 1);
                    const size_t base = (size_t)(bb_*DHD + d0) * SEQ;
                    VTF[base + rl]           = __float2half_rn(acc[mt][nt][0]);
                    VTF[base + SEQ + rl]     = __float2half_rn(acc[mt][nt][1]);
                    VTF[base + rl + 8]       = __float2half_rn(acc[mt][nt][2]);
                    VTF[base + SEQ + rl + 8] = __float2half_rn(acc[mt][nt][3]);
                }
            }
        }
    }
}

// ---------------------------------------------------------------------------
// T5 relative-position bucket (mirrors jax fp32 math)
// ---------------------------------------------------------------------------
__device__ __forceinline__ int rel_bucket(int nn) {
    if (nn < 16) return nn;
    float t = logf((float)nn * (1.0f/16.0f)) / 2.0794415416798357f * 16.0f;
    int v = 16 + (int)t;
    return v < 31 ? v : 31;
}

// ---------------------------------------------------------------------------
// Flash attention v9: fp16 single-product QK/PV, clean/diagonal tile split,
// 3-stage cp.async ring, ldmatrix, exp2 softmax, 2 CTAs/SM.
// Grid (SEQ/128, HEADS, BATCH), 256 threads = 8 warps (warp w -> 16 rows).
// ---------------------------------------------------------------------------
#define FSTRIDE 72                  // elements; 144 bytes/row
#define FTILE   (64*FSTRIDE*2)      // 9216 bytes per tile
#define FKFO 0
#define FVFO (1*FTILE)
#define FSTG (2*FTILE)              // 18432 per stage
#define FBIAS (3*FSTG)              // 55296
#define FLASH_SMEM (FBIAS + 2048*4) // 63488

__global__ __launch_bounds__(256, 2) void flash2(
    const __half* __restrict__ QF,
    const __half* __restrict__ KF, const __half* __restrict__ VTF,
    const float* __restrict__ rel_emb,
    __half* __restrict__ AOF)
{
    extern __shared__ __align__(16) char smem[];
    const uint32_t sb = s2u(smem);
    float* biasv = (float*)(smem + FBIAS);

    const int qtb = (SEQ/128 - 1) - blockIdx.x;
    const int h = blockIdx.y, b = blockIdx.z;
    const int tid = threadIdx.x, lane = tid & 31, w = tid >> 5;
    const int l4 = lane >> 2, c2 = (lane & 3) * 2;
    const int i0 = qtb * 128;
    const int wrow = i0 + w * 16;

    const uint32_t ltermB = ((lane & 7) + ((lane >> 4) << 3)) * (FSTRIDE*2)
                          + (((lane >> 3) & 1) << 4);

    for (int nn = tid; nn < 2048; nn += 256)
        biasv[nn] = rel_emb[rel_bucket(nn)*HEADS + h] * (8.0f * LOG2E);

    uint32_t qf[4][4];
    {
        const size_t rb = (size_t)(b*SEQ + wrow + l4) * INNER_ + h*DHD;
        #pragma unroll
        for (int k16 = 0; k16 < 4; k16++) {
            const int c = k16*16 + c2;
            qf[k16][0] = *(const uint32_t*)(QF + rb + c);
            qf[k16][1] = *(const uint32_t*)(QF + rb + 8*INNER_ + c);
            qf[k16][2] = *(const uint32_t*)(QF + rb + c + 8);
            qf[k16][3] = *(const uint32_t*)(QF + rb + 8*INNER_ + c + 8);
        }
    }

    float o[8][4];
    #pragma unroll
    for (int nt = 0; nt < 8; nt++)
        #pragma unroll
        for (int e = 0; e < 4; e++) o[nt][e] = 0.f;
    float m0 = -INFINITY, m1 = -INFINITY, l0 = 0.f, l1 = 0.f;

    const int jmax = (i0 + 127) >> 6;
    const int iwmax = wrow + 15;

    #define LOADKV(JT, S) do { \
        const int _j0 = (JT) * 64; \
        const uint32_t _sb = sb + (uint32_t)(S) * FSTG; \
        _Pragma("unroll") \
        for (int q = 0; q < 2; q++) { \
            const int id = tid*2 + q; \
            const int r = id >> 3, cc = id & 7; \
            const uint32_t so = (uint32_t)(r*144 + cc*16); \
            const size_t ksrc = (size_t)(b*SEQ + _j0 + r)*DHD + cc*8; \
            cp16(_sb + FKFO + so, KF  + ksrc); \
            const size_t vsrc = (size_t)(b*DHD + r)*SEQ + _j0 + cc*8; \
            cp16(_sb + FVFO + so, VTF + vsrc); \
        } \
    } while (0)

    LOADKV(0, 0); cp_commit();
    LOADKV(1, 1); cp_commit();

    for (int jt = 0; jt <= jmax; jt++) {
        asm volatile("cp.async.wait_group 1;" ::: "memory");
        __syncthreads();
        if (jt + 2 <= jmax) LOADKV(jt + 2, (jt + 2) % 3);
        cp_commit();

        const int j0 = jt * 64;
        if (j0 <= iwmax) {
            const uint32_t stgb = sb + (uint32_t)(jt % 3) * FSTG;

            // ---- S = Q K^T (fp16 single product) ----
            float s[8][4];
            #pragma unroll
            for (int nt = 0; nt < 8; nt++)
                #pragma unroll
                for (int e = 0; e < 4; e++) s[nt][e] = 0.f;

            #pragma unroll
            for (int k16 = 0; k16 < 4; k16++) {
                const uint32_t kc2 = (uint32_t)k16 * 32;
                uint32_t kf4[4][4];
                #pragma unroll
                for (int np = 0; np < 4; np++)
                    ldsm_x4(kf4[np], stgb + FKFO + np*(16*144) + kc2 + ltermB);
                #pragma unroll
                for (int np = 0; np < 4; np++) {
                    mma16816h(s[2*np],   qf[k16], &kf4[np][0]);
                    mma16816h(s[2*np+1], qf[k16], &kf4[np][2]);
                }
            }

            // ---- bias (+ causal mask on diagonal tiles only) ----
            const int irow0 = wrow + l4;
            if (j0 + 63 <= wrow) {
                // clean tile: bias only
                #pragma unroll
                for (int nt = 0; nt < 8; nt++) {
                    #pragma unroll
                    for (int e = 0; e < 4; e++) {
                        const int ri = irow0 + ((e >> 1) << 3);
                        const int cj = j0 + nt*8 + c2 + (e & 1);
                        s[nt][e] += biasv[ri - cj];
                    }
                }
            } else {
                #pragma unroll
                for (int nt = 0; nt < 8; nt++) {
                    #pragma unroll
                    for (int e = 0; e < 4; e++) {
                        const int ri = irow0 + ((e >> 1) << 3);
                        const int cj = j0 + nt*8 + c2 + (e & 1);
                        const int nn = ri - cj;
                        if (nn < 0) s[nt][e] = -INFINITY;
                        else        s[nt][e] += biasv[nn];
                    }
                }
            }

            // ---- warp-local online softmax (exp2 domain) ----
            float mc0 = -INFINITY, mc1 = -INFINITY;
            #pragma unroll
            for (int nt = 0; nt < 8; nt++) {
                mc0 = fmaxf(mc0, fmaxf(s[nt][0], s[nt][1]));
                mc1 = fmaxf(mc1, fmaxf(s[nt][2], s[nt][3]));
            }
            mc0 = fmaxf(mc0, __shfl_xor_sync(0xffffffffu, mc0, 1));
            mc0 = fmaxf(mc0, __shfl_xor_sync(0xffffffffu, mc0, 2));
            mc1 = fmaxf(mc1, __shfl_xor_sync(0xffffffffu, mc1, 1));
            mc1 = fmaxf(mc1, __shfl_xor_sync(0xffffffffu, mc1, 2));
            const float mn0 = fmaxf(m0, mc0), mn1 = fmaxf(m1, mc1);
            const float sc0 = exp2f(m0 - mn0), sc1 = exp2f(m1 - mn1);
            m0 = mn0; m1 = mn1;

            float rs0 = 0.f, rs1 = 0.f;
            #pragma unroll
            for (int nt = 0; nt < 8; nt++) {
                s[nt][0] = exp2f(s[nt][0] - mn0);
                s[nt][1] = exp2f(s[nt][1] - mn0);
                s[nt][2] = exp2f(s[nt][2] - mn1);
                s[nt][3] = exp2f(s[nt][3] - mn1);
                rs0 += s[nt][0] + s[nt][1];
                rs1 += s[nt][2] + s[nt][3];
            }
            rs0 += __shfl_xor_sync(0xffffffffu, rs0, 1);
            rs0 += __shfl_xor_sync(0xffffffffu, rs0, 2);
            rs1 += __shfl_xor_sync(0xffffffffu, rs1, 1);
            rs1 += __shfl_xor_sync(0xffffffffu, rs1, 2);
            l0 = l0*sc0 + rs0;
            l1 = l1*sc1 + rs1;

            #pragma unroll
            for (int nt = 0; nt < 8; nt++) {
                o[nt][0] *= sc0; o[nt][1] *= sc0;
                o[nt][2] *= sc1; o[nt][3] *= sc1;
            }

            // ---- O += P V (fp16 single product) ----
            #pragma unroll
            for (int kk = 0; kk < 4; kk++) {
                uint32_t pf[4];
                pf[0] = pack_f16x2(s[2*kk  ][0], s[2*kk  ][1]);
                pf[1] = pack_f16x2(s[2*kk  ][2], s[2*kk  ][3]);
                pf[2] = pack_f16x2(s[2*kk+1][0], s[2*kk+1][1]);
                pf[3] = pack_f16x2(s[2*kk+1][2], s[2*kk+1][3]);
                const uint32_t kc2 = (uint32_t)kk * 32;
                uint32_t vf[4][4];
                #pragma unroll
                for (int np = 0; np < 4; np++)
                    ldsm_x4(vf[np], stgb + FVFO + np*(16*144) + kc2 + ltermB);
                #pragma unroll
                for (int np = 0; np < 4; np++) {
                    mma16816h(o[2*np],   pf, &vf[np][0]);
                    mma16816h(o[2*np+1], pf, &vf[np][2]);
                }
            }
        }
    }
    #undef LOADKV

    // ---- normalize + write fp16 output ----
    {
        const float inv0 = 1.0f / l0, inv1 = 1.0f / l1;
        const size_t rb = (size_t)(b*SEQ + wrow + l4) * INNER_ + h*DHD;
        #pragma unroll
        for (int nt = 0; nt < 8; nt++) {
            const int col = nt*8 + c2;
            *(uint32_t*)(AOF + rb + col) =
                pack_f16x2(o[nt][0]*inv0, o[nt][1]*inv0);
            *(uint32_t*)(AOF + rb + 8*INNER_ + col) =
                pack_f16x2(o[nt][2]*inv1, o[nt][3]*inv1);
        }
    }
}

// ---------------------------------------------------------------------------
extern "C" void kernel_launch(void* const* d_in, const int* in_sizes, int n_in,
                              void* d_out, int out_size)
{
    const float* x       = (const float*)d_in[0];
    const float* Wq      = (const float*)d_in[1];
    const float* Wkv     = (const float*)d_in[2];
    const float* Wout    = (const float*)d_in[3];
    const float* bout    = (const float*)d_in[4];
    const float* rel_emb = (const float*)d_in[5];
    float* out = (float*)d_out;

    void* p;
    cudaGetSymbolAddress(&p, g_qf);   __half* qf  = (__half*)p;
    cudaGetSymbolAddress(&p, g_kf);   __half* kf  = (__half*)p;
    cudaGetSymbolAddress(&p, g_vtf);  __half* vtf = (__half*)p;
    cudaGetSymbolAddress(&p, g_aof);  __half* aof = (__half*)p;
    cudaGetSymbolAddress(&p, g_xf);   __half* xf  = (__half*)p;
    cudaGetSymbolAddress(&p, g_wcf);  __half* wcf = (__half*)p;
    cudaGetSymbolAddress(&p, g_wof);  __half* wof = (__half*)p;

    cudaFuncSetAttribute(gemm_mma<0>, cudaFuncAttributeMaxDynamicSharedMemorySize, GEMM_SMEM);
    cudaFuncSetAttribute(gemm_mma<1>, cudaFuncAttributeMaxDynamicSharedMemorySize, GEMM_SMEM);
    cudaFuncSetAttribute(flash2, cudaFuncAttributeMaxDynamicSharedMemorySize, FLASH_SMEM);

    dim3 tb(32, 8);
    // fused [Wq ; Wkv] transpose (Wq pre-scaled by 0.125*log2e)
    transpose_wc_kernel<<<dim3((INNER_+2*DHD)/32, DIMM/32), tb>>>(Wq, Wkv, wcf);
    // Wout transpose
    transpose_f16_kernel<<<dim3(DIMM/32, INNER_/32), tb>>>(Wout, wof, INNER_, DIMM, 1.0f);
    // x -> fp16
    convert_f16_kernel<<<(ROWS*DIMM/4 + 255)/256, 256>>>(x, xf, ROWS*DIMM/4);

    // fused q|kv projection: q fp16, K fp16 + V^T fp16 directly from epilogue
    gemm_mma<1><<<dim3(9, ROWS/128), 256, GEMM_SMEM>>>(xf, wcf,
                                                       nullptr, nullptr, 0,
                                                       qf, kf, vtf);
    // attention
    flash2<<<dim3(SEQ/128, HEADS, BATCH), 256, FLASH_SMEM>>>(qf, kf, vtf,
                                                             rel_emb, aof);
    // out = ao @ Wout + bout
    gemm_mma<0><<<dim3(DIMM/128, ROWS/128), 256, GEMM_SMEM>>>(aof, wof,
                                                              out, bout, DIMM,
                                                              nullptr, nullptr, nullptr);
}

// round 14
// speedup vs baseline: 2.5383x; 1.0360x over previous
#include <cuda_runtime.h>
#include <cuda_bf16.h>
#include <cuda_fp16.h>
#include <math.h>
#include <stdint.h>

#define BATCH 2
#define SEQ   2048
#define DIMM  1024
#define HEADS 16
#define DHD   64
#define INNER_ (HEADS*DHD)      // 1024
#define ROWS  (BATCH*SEQ)       // 4096
#define KDIM  1024
#define LOG2E 1.4426950408889634f

// ---------------- scratch (no cudaMalloc allowed) ----------------
__device__ __align__(256) __half g_qf [ROWS*INNER_];
__device__ __align__(256) __half g_kf [BATCH*SEQ*DHD];
__device__ __align__(256) __half g_vtf[BATCH*DHD*SEQ];
__device__ __align__(256) __half g_aof[ROWS*INNER_];
__device__ __align__(256) __half g_xf [ROWS*DIMM];
__device__ __align__(256) __half g_wcf[(INNER_+2*DHD)*DIMM];   // [Wq^T ; Wkv^T] fp16
__device__ __align__(256) __half g_wof[DIMM*INNER_];           // Wout^T fp16

// ---------------- helpers ----------------
__device__ __forceinline__ uint32_t s2u(const void* p) {
    uint32_t a;
    asm("{ .reg .u64 t; cvta.to.shared.u64 t, %1; cvt.u32.u64 %0, t; }"
        : "=r"(a) : "l"(p));
    return a;
}
__device__ __forceinline__ void cp16(uint32_t dst, const void* src) {
    asm volatile("cp.async.cg.shared.global [%0], [%1], 16;" :: "r"(dst), "l"(src));
}
__device__ __forceinline__ void cp_commit() { asm volatile("cp.async.commit_group;" ::: "memory"); }

__device__ __forceinline__ void mma16816h(float c[4], const uint32_t a[4], const uint32_t b[2]) {
    asm volatile("mma.sync.aligned.m16n8k16.row.col.f32.f16.f16.f32 "
        "{%0,%1,%2,%3}, {%4,%5,%6,%7}, {%8,%9}, {%0,%1,%2,%3};"
        : "+f"(c[0]), "+f"(c[1]), "+f"(c[2]), "+f"(c[3])
        : "r"(a[0]), "r"(a[1]), "r"(a[2]), "r"(a[3]), "r"(b[0]), "r"(b[1]));
}

// ldmatrix x4
__device__ __forceinline__ void ldsm_x4(uint32_t r[4], uint32_t saddr) {
    asm volatile("ldmatrix.sync.aligned.m8n8.x4.shared.b16 {%0,%1,%2,%3}, [%4];"
        : "=r"(r[0]), "=r"(r[1]), "=r"(r[2]), "=r"(r[3]) : "r"(saddr));
}

// pack two floats -> fp16x2 (first arg = low half)
__device__ __forceinline__ uint32_t pack_f16x2(float lo, float hi) {
    uint32_t r;
    asm("cvt.rn.f16x2.f32 %0, %1, %2;" : "=r"(r) : "f"(hi), "f"(lo));
    return r;
}

// ---------------------------------------------------------------------------
// Prep kernels
// ---------------------------------------------------------------------------
__global__ __launch_bounds__(256) void convert_f16_kernel(
    const float* __restrict__ A, __half* __restrict__ F, int n4)
{
    int i = blockIdx.x * blockDim.x + threadIdx.x;
    if (i >= n4) return;
    float4 a = ((const float4*)A)[i];
    ((uint32_t*)F)[2*i]   = pack_f16x2(a.x, a.y);
    ((uint32_t*)F)[2*i+1] = pack_f16x2(a.z, a.w);
}

// transpose to [N][K] fp16 single (generic)
__global__ __launch_bounds__(256) void transpose_f16_kernel(
    const float* __restrict__ W, __half* __restrict__ T,
    int K, int N, float scale)
{
    __shared__ float tile[32][33];
    const int tx = threadIdx.x, ty = threadIdx.y;
    const int n0 = blockIdx.x * 32, k0 = blockIdx.y * 32;
    #pragma unroll
    for (int i = 0; i < 4; i++)
        tile[ty + 8*i][tx] = W[(size_t)(k0 + ty + 8*i) * N + n0 + tx];
    __syncthreads();
    #pragma unroll
    for (int i = 0; i < 4; i++) {
        float a = tile[tx][ty + 8*i] * scale;
        T[(size_t)(n0 + ty + 8*i) * K + k0 + tx] = __float2half_rn(a);
    }
}

// fused [Wq ; Wkv] transpose into g_wcf
__global__ __launch_bounds__(256) void transpose_wc_kernel(
    const float* __restrict__ Wq, const float* __restrict__ Wkv,
    __half* __restrict__ T)
{
    __shared__ float tile[32][33];
    const int tx = threadIdx.x, ty = threadIdx.y;
    const int n0 = blockIdx.x * 32, k0 = blockIdx.y * 32;
    const bool isq = (n0 < INNER_);
    const float* W = isq ? Wq : Wkv;
    const int N = isq ? INNER_ : 2*DHD;
    const int cb = isq ? n0 : n0 - INNER_;
    const float scale = isq ? 0.125f * LOG2E : 1.0f;
    #pragma unroll
    for (int i = 0; i < 4; i++)
        tile[ty + 8*i][tx] = W[(size_t)(k0 + ty + 8*i) * N + cb + tx];
    __syncthreads();
    #pragma unroll
    for (int i = 0; i < 4; i++) {
        float a = tile[tx][ty + 8*i] * scale;
        T[(size_t)(n0 + ty + 8*i) * KDIM + k0 + tx] = __float2half_rn(a);
    }
}

// ---------------------------------------------------------------------------
// HMMA GEMM fp16 single-product: C = A[M,K] @ B^T, both fp16 [.][K].
// CTA 128x128, BK=32, 3-stage cp.async ring (one __syncthreads/stage), 2 CTAs/SM.
// MODE 0: fp32 C + bias.
// MODE 1: bn<8 -> fp16 q; bn==8 -> K fp16 (cols 0..63) + V^T fp16 (cols 64..127).
// ---------------------------------------------------------------------------
#define GBK 32
#define GNSTG (KDIM/GBK)
#define GSTRIDE 40                  // elements; 80 bytes/row
#define GMATB (128*GSTRIDE*2)       // 10240 bytes per matrix
#define GSTGB (2*GMATB)             // 20480 per stage
#define GEMM_SMEM (3*GSTGB)         // 61440 (3-stage ring)

template<int MODE>
__global__ __launch_bounds__(256, 2) void gemm_mma(
    const __half* __restrict__ Af, const __half* __restrict__ Bf,
    float* __restrict__ C, const float* __restrict__ bias, int Ncols,
    __half* __restrict__ CF, __half* __restrict__ KF, __half* __restrict__ VTF)
{
    extern __shared__ __align__(16) char smem[];
    const uint32_t sbuf = s2u(smem);
    const int tid = threadIdx.x, wid = tid >> 5, lane = tid & 31;
    const int l4 = lane >> 2, c2 = (lane & 3) * 2;
    const int wm = wid & 3, wn = wid >> 2;
    const int bn = blockIdx.x, bm = blockIdx.y;

    const uint32_t ltermB = ((lane & 7) + ((lane >> 4) << 3)) * (GSTRIDE*2)
                          + (((lane >> 3) & 1) << 4);
    const uint32_t ltermA = ((lane & 7) + (((lane >> 3) & 1) << 3)) * (GSTRIDE*2)
                          + (((lane >> 4) & 1) << 4);

    const __half* pA = Af + (size_t)(bm*128)*KDIM;
    const __half* pB = Bf + (size_t)(bn*128)*KDIM;

    const int r0 = tid >> 2, kc = tid & 3;
    const int r1 = r0 + 64;

    float acc[2][8][4];
    #pragma unroll
    for (int i = 0; i < 2; i++)
        #pragma unroll
        for (int j = 0; j < 8; j++)
            #pragma unroll
            for (int e = 0; e < 4; e++) acc[i][j][e] = 0.f;

    #define G_LOAD(S) do { \
        const int _k0 = (S) * GBK; \
        const uint32_t stb = sbuf + (uint32_t)((S) % 3) * GSTGB; \
        cp16(stb         + r0*80 + kc*16, pA + (size_t)r0*KDIM + _k0 + kc*8); \
        cp16(stb         + r1*80 + kc*16, pA + (size_t)r1*KDIM + _k0 + kc*8); \
        cp16(stb + GMATB + r0*80 + kc*16, pB + (size_t)r0*KDIM + _k0 + kc*8); \
        cp16(stb + GMATB + r1*80 + kc*16, pB + (size_t)r1*KDIM + _k0 + kc*8); \
    } while (0)

    G_LOAD(0); cp_commit();
    G_LOAD(1); cp_commit();

    for (int s = 0; s < GNSTG; s++) {
        asm volatile("cp.async.wait_group 1;" ::: "memory");
        __syncthreads();                       // stage s visible; stage s-1 buffer free
        if (s + 2 < GNSTG) G_LOAD(s + 2);
        cp_commit();                           // unconditional: keeps group counting

        const uint32_t stb = sbuf + (uint32_t)(s % 3) * GSTGB;
        const uint32_t aBase = stb         + (wm*32)*80 + ltermA;
        const uint32_t bBase = stb + GMATB + (wn*64)*80 + ltermB;

        #pragma unroll
        for (int k16 = 0; k16 < 2; k16++) {
            const uint32_t kc2 = (uint32_t)k16 * 32;
            uint32_t ah[2][4], bb[4][4];
            #pragma unroll
            for (int mt = 0; mt < 2; mt++) ldsm_x4(ah[mt], aBase + mt*(16*80) + kc2);
            #pragma unroll
            for (int np = 0; np < 4; np++) ldsm_x4(bb[np], bBase + np*(16*80) + kc2);
            #pragma unroll
            for (int mt = 0; mt < 2; mt++)
                #pragma unroll
                for (int np = 0; np < 4; np++) {
                    mma16816h(acc[mt][2*np],   ah[mt], &bb[np][0]);
                    mma16816h(acc[mt][2*np+1], ah[mt], &bb[np][2]);
                }
        }
    }
    #undef G_LOAD

    #pragma unroll
    for (int mt = 0; mt < 2; mt++) {
        const int rg0 = bm*128 + wm*32 + mt*16 + l4;
        #pragma unroll
        for (int nt = 0; nt < 8; nt++) {
            const int cg = bn*128 + wn*64 + nt*8 + c2;
            if (MODE == 0) {
                float b0 = bias ? bias[cg] : 0.f;
                float b1 = bias ? bias[cg+1] : 0.f;
                float2 v0 = { acc[mt][nt][0] + b0, acc[mt][nt][1] + b1 };
                float2 v1 = { acc[mt][nt][2] + b0, acc[mt][nt][3] + b1 };
                *(float2*)(C + (size_t)rg0*Ncols + cg)     = v0;
                *(float2*)(C + (size_t)(rg0+8)*Ncols + cg) = v1;
            } else {
                if (bn < 8) {
                    *(uint32_t*)(CF + (size_t)rg0*INNER_ + cg) =
                        pack_f16x2(acc[mt][nt][0], acc[mt][nt][1]);
                    *(uint32_t*)(CF + (size_t)(rg0+8)*INNER_ + cg) =
                        pack_f16x2(acc[mt][nt][2], acc[mt][nt][3]);
                } else if (wn == 0) {
                    const int kcol = cg - 1024;
                    *(uint32_t*)(KF + (size_t)rg0*DHD + kcol) =
                        pack_f16x2(acc[mt][nt][0], acc[mt][nt][1]);
                    *(uint32_t*)(KF + (size_t)(rg0+8)*DHD + kcol) =
                        pack_f16x2(acc[mt][nt][2], acc[mt][nt][3]);
                } else {
                    const int d0 = cg - 1088;
                    const int bb_ = rg0 >> 11;
                    const int rl = rg0 & (SEQ - 1);
                    const size_t base = (size_t)(bb_*DHD + d0) * SEQ;
                    VTF[base + rl]           = __float2half_rn(acc[mt][nt][0]);
                    VTF[base + SEQ + rl]     = __float2half_rn(acc[mt][nt][1]);
                    VTF[base + rl + 8]       = __float2half_rn(acc[mt][nt][2]);
                    VTF[base + SEQ + rl + 8] = __float2half_rn(acc[mt][nt][3]);
                }
            }
        }
    }
}

// ---------------------------------------------------------------------------
// T5 relative-position bucket (mirrors jax fp32 math)
// ---------------------------------------------------------------------------
__device__ __forceinline__ int rel_bucket(int nn) {
    if (nn < 16) return nn;
    float t = logf((float)nn * (1.0f/16.0f)) / 2.0794415416798357f * 16.0f;
    int v = 16 + (int)t;
    return v < 31 ? v : 31;
}

// ---------------------------------------------------------------------------
// Flash attention v9 (unchanged from round 13): fp16 single-product QK/PV,
// clean/diagonal tile split, 3-stage ring, ldmatrix, exp2 softmax, 2 CTAs/SM.
// ---------------------------------------------------------------------------
#define FSTRIDE 72                  // elements; 144 bytes/row
#define FTILE   (64*FSTRIDE*2)      // 9216 bytes per tile
#define FKFO 0
#define FVFO (1*FTILE)
#define FSTG (2*FTILE)              // 18432 per stage
#define FBIAS (3*FSTG)              // 55296
#define FLASH_SMEM (FBIAS + 2048*4) // 63488

__global__ __launch_bounds__(256, 2) void flash2(
    const __half* __restrict__ QF,
    const __half* __restrict__ KF, const __half* __restrict__ VTF,
    const float* __restrict__ rel_emb,
    __half* __restrict__ AOF)
{
    extern __shared__ __align__(16) char smem[];
    const uint32_t sb = s2u(smem);
    float* biasv = (float*)(smem + FBIAS);

    const int qtb = (SEQ/128 - 1) - blockIdx.x;
    const int h = blockIdx.y, b = blockIdx.z;
    const int tid = threadIdx.x, lane = tid & 31, w = tid >> 5;
    const int l4 = lane >> 2, c2 = (lane & 3) * 2;
    const int i0 = qtb * 128;
    const int wrow = i0 + w * 16;

    const uint32_t ltermB = ((lane & 7) + ((lane >> 4) << 3)) * (FSTRIDE*2)
                          + (((lane >> 3) & 1) << 4);

    for (int nn = tid; nn < 2048; nn += 256)
        biasv[nn] = rel_emb[rel_bucket(nn)*HEADS + h] * (8.0f * LOG2E);

    uint32_t qf[4][4];
    {
        const size_t rb = (size_t)(b*SEQ + wrow + l4) * INNER_ + h*DHD;
        #pragma unroll
        for (int k16 = 0; k16 < 4; k16++) {
            const int c = k16*16 + c2;
            qf[k16][0] = *(const uint32_t*)(QF + rb + c);
            qf[k16][1] = *(const uint32_t*)(QF + rb + 8*INNER_ + c);
            qf[k16][2] = *(const uint32_t*)(QF + rb + c + 8);
            qf[k16][3] = *(const uint32_t*)(QF + rb + 8*INNER_ + c + 8);
        }
    }

    float o[8][4];
    #pragma unroll
    for (int nt = 0; nt < 8; nt++)
        #pragma unroll
        for (int e = 0; e < 4; e++) o[nt][e] = 0.f;
    float m0 = -INFINITY, m1 = -INFINITY, l0 = 0.f, l1 = 0.f;

    const int jmax = (i0 + 127) >> 6;
    const int iwmax = wrow + 15;

    #define LOADKV(JT, S) do { \
        const int _j0 = (JT) * 64; \
        const uint32_t _sb = sb + (uint32_t)(S) * FSTG; \
        _Pragma("unroll") \
        for (int q = 0; q < 2; q++) { \
            const int id = tid*2 + q; \
            const int r = id >> 3, cc = id & 7; \
            const uint32_t so = (uint32_t)(r*144 + cc*16); \
            const size_t ksrc = (size_t)(b*SEQ + _j0 + r)*DHD + cc*8; \
            cp16(_sb + FKFO + so, KF  + ksrc); \
            const size_t vsrc = (size_t)(b*DHD + r)*SEQ + _j0 + cc*8; \
            cp16(_sb + FVFO + so, VTF + vsrc); \
        } \
    } while (0)

    LOADKV(0, 0); cp_commit();
    LOADKV(1, 1); cp_commit();

    for (int jt = 0; jt <= jmax; jt++) {
        asm volatile("cp.async.wait_group 1;" ::: "memory");
        __syncthreads();
        if (jt + 2 <= jmax) LOADKV(jt + 2, (jt + 2) % 3);
        cp_commit();

        const int j0 = jt * 64;
        if (j0 <= iwmax) {
            const uint32_t stgb = sb + (uint32_t)(jt % 3) * FSTG;

            float s[8][4];
            #pragma unroll
            for (int nt = 0; nt < 8; nt++)
                #pragma unroll
                for (int e = 0; e < 4; e++) s[nt][e] = 0.f;

            #pragma unroll
            for (int k16 = 0; k16 < 4; k16++) {
                const uint32_t kc2 = (uint32_t)k16 * 32;
                uint32_t kf4[4][4];
                #pragma unroll
                for (int np = 0; np < 4; np++)
                    ldsm_x4(kf4[np], stgb + FKFO + np*(16*144) + kc2 + ltermB);
                #pragma unroll
                for (int np = 0; np < 4; np++) {
                    mma16816h(s[2*np],   qf[k16], &kf4[np][0]);
                    mma16816h(s[2*np+1], qf[k16], &kf4[np][2]);
                }
            }

            const int irow0 = wrow + l4;
            if (j0 + 63 <= wrow) {
                #pragma unroll
                for (int nt = 0; nt < 8; nt++) {
                    #pragma unroll
                    for (int e = 0; e < 4; e++) {
                        const int ri = irow0 + ((e >> 1) << 3);
                        const int cj = j0 + nt*8 + c2 + (e & 1);
                        s[nt][e] += biasv[ri - cj];
                    }
                }
            } else {
                #pragma unroll
                for (int nt = 0; nt < 8; nt++) {
                    #pragma unroll
                    for (int e = 0; e < 4; e++) {
                        const int ri = irow0 + ((e >> 1) << 3);
                        const int cj = j0 + nt*8 + c2 + (e & 1);
                        const int nn = ri - cj;
                        if (nn < 0) s[nt][e] = -INFINITY;
                        else        s[nt][e] += biasv[nn];
                    }
                }
            }

            float mc0 = -INFINITY, mc1 = -INFINITY;
            #pragma unroll
            for (int nt = 0; nt < 8; nt++) {
                mc0 = fmaxf(mc0, fmaxf(s[nt][0], s[nt][1]));
                mc1 = fmaxf(mc1, fmaxf(s[nt][2], s[nt][3]));
            }
            mc0 = fmaxf(mc0, __shfl_xor_sync(0xffffffffu, mc0, 1));
            mc0 = fmaxf(mc0, __shfl_xor_sync(0xffffffffu, mc0, 2));
            mc1 = fmaxf(mc1, __shfl_xor_sync(0xffffffffu, mc1, 1));
            mc1 = fmaxf(mc1, __shfl_xor_sync(0xffffffffu, mc1, 2));
            const float mn0 = fmaxf(m0, mc0), mn1 = fmaxf(m1, mc1);
            const float sc0 = exp2f(m0 - mn0), sc1 = exp2f(m1 - mn1);
            m0 = mn0; m1 = mn1;

            float rs0 = 0.f, rs1 = 0.f;
            #pragma unroll
            for (int nt = 0; nt < 8; nt++) {
                s[nt][0] = exp2f(s[nt][0] - mn0);
                s[nt][1] = exp2f(s[nt][1] - mn0);
                s[nt][2] = exp2f(s[nt][2] - mn1);
                s[nt][3] = exp2f(s[nt][3] - mn1);
                rs0 += s[nt][0] + s[nt][1];
                rs1 += s[nt][2] + s[nt][3];
            }
            rs0 += __shfl_xor_sync(0xffffffffu, rs0, 1);
            rs0 += __shfl_xor_sync(0xffffffffu, rs0, 2);
            rs1 += __shfl_xor_sync(0xffffffffu, rs1, 1);
            rs1 += __shfl_xor_sync(0xffffffffu, rs1, 2);
            l0 = l0*sc0 + rs0;
            l1 = l1*sc1 + rs1;

            #pragma unroll
            for (int nt = 0; nt < 8; nt++) {
                o[nt][0] *= sc0; o[nt][1] *= sc0;
                o[nt][2] *= sc1; o[nt][3] *= sc1;
            }

            #pragma unroll
            for (int kk = 0; kk < 4; kk++) {
                uint32_t pf[4];
                pf[0] = pack_f16x2(s[2*kk  ][0], s[2*kk  ][1]);
                pf[1] = pack_f16x2(s[2*kk  ][2], s[2*kk  ][3]);
                pf[2] = pack_f16x2(s[2*kk+1][0], s[2*kk+1][1]);
                pf[3] = pack_f16x2(s[2*kk+1][2], s[2*kk+1][3]);
                const uint32_t kc2 = (uint32_t)kk * 32;
                uint32_t vf[4][4];
                #pragma unroll
                for (int np = 0; np < 4; np++)
                    ldsm_x4(vf[np], stgb + FVFO + np*(16*144) + kc2 + ltermB);
                #pragma unroll
                for (int np = 0; np < 4; np++) {
                    mma16816h(o[2*np],   pf, &vf[np][0]);
                    mma16816h(o[2*np+1], pf, &vf[np][2]);
                }
            }
        }
    }
    #undef LOADKV

    {
        const float inv0 = 1.0f / l0, inv1 = 1.0f / l1;
        const size_t rb = (size_t)(b*SEQ + wrow + l4) * INNER_ + h*DHD;
        #pragma unroll
        for (int nt = 0; nt < 8; nt++) {
            const int col = nt*8 + c2;
            *(uint32_t*)(AOF + rb + col) =
                pack_f16x2(o[nt][0]*inv0, o[nt][1]*inv0);
            *(uint32_t*)(AOF + rb + 8*INNER_ + col) =
                pack_f16x2(o[nt][2]*inv1, o[nt][3]*inv1);
        }
    }
}

// ---------------------------------------------------------------------------
extern "C" void kernel_launch(void* const* d_in, const int* in_sizes, int n_in,
                              void* d_out, int out_size)
{
    const float* x       = (const float*)d_in[0];
    const float* Wq      = (const float*)d_in[1];
    const float* Wkv     = (const float*)d_in[2];
    const float* Wout    = (const float*)d_in[3];
    const float* bout    = (const float*)d_in[4];
    const float* rel_emb = (const float*)d_in[5];
    float* out = (float*)d_out;

    void* p;
    cudaGetSymbolAddress(&p, g_qf);   __half* qf  = (__half*)p;
    cudaGetSymbolAddress(&p, g_kf);   __half* kf  = (__half*)p;
    cudaGetSymbolAddress(&p, g_vtf);  __half* vtf = (__half*)p;
    cudaGetSymbolAddress(&p, g_aof);  __half* aof = (__half*)p;
    cudaGetSymbolAddress(&p, g_xf);   __half* xf  = (__half*)p;
    cudaGetSymbolAddress(&p, g_wcf);  __half* wcf = (__half*)p;
    cudaGetSymbolAddress(&p, g_wof);  __half* wof = (__half*)p;

    cudaFuncSetAttribute(gemm_mma<0>, cudaFuncAttributeMaxDynamicSharedMemorySize, GEMM_SMEM);
    cudaFuncSetAttribute(gemm_mma<1>, cudaFuncAttributeMaxDynamicSharedMemorySize, GEMM_SMEM);
    cudaFuncSetAttribute(flash2, cudaFuncAttributeMaxDynamicSharedMemorySize, FLASH_SMEM);

    dim3 tb(32, 8);
    transpose_wc_kernel<<<dim3((INNER_+2*DHD)/32, DIMM/32), tb>>>(Wq, Wkv, wcf);
    transpose_f16_kernel<<<dim3(DIMM/32, INNER_/32), tb>>>(Wout, wof, INNER_, DIMM, 1.0f);
    convert_f16_kernel<<<(ROWS*DIMM/4 + 255)/256, 256>>>(x, xf, ROWS*DIMM/4);

    gemm_mma<1><<<dim3(9, ROWS/128), 256, GEMM_SMEM>>>(xf, wcf,
                                                       nullptr, nullptr, 0,
                                                       qf, kf, vtf);
    flash2<<<dim3(SEQ/128, HEADS, BATCH), 256, FLASH_SMEM>>>(qf, kf, vtf,
                                                             rel_emb, aof);
    gemm_mma<0><<<dim3(DIMM/128, ROWS/128), 256, GEMM_SMEM>>>(aof, wof,
                                                              out, bout, DIMM,
                                                              nullptr, nullptr, nullptr);
}